// round 5
// baseline (speedup 1.0000x reference)
#include <cuda_runtime.h>
#include <math.h>

// ---------------- problem constants ----------------
#define BB    16
#define NTOK  3136
#define DIM   512
#define HH    56
#define WWID  56
#define HEADS 8
#define HD    64
#define AGENT 49
#define WIN   14
#define WW2   196   // 14*14
#define S1SPLIT 5

// ---------------- scratch (device globals; no allocation allowed) ----------------
__device__ float g_qkv[(size_t)BB * NTOK * 3 * DIM];          // 308 MB
__device__ float g_attnout[(size_t)BB * NTOK * DIM];          // 103 MB
__device__ float g_agent[BB * AGENT * DIM];
__device__ float g_agentv[BB * HEADS * AGENT * HD];
__device__ float g_pacc[(size_t)BB * HEADS * S1SPLIT * AGENT * HD];  // 8 MB
__device__ float g_pm[BB * HEADS * S1SPLIT * AGENT];
__device__ float g_ps[BB * HEADS * S1SPLIT * AGENT];
__device__ float g_pb[HEADS * AGENT * WW2];
__device__ float g_ab[HEADS * 197 * AGENT];
__device__ float g_bias1[HEADS * AGENT * NTOK];
__device__ float g_bias2[HEADS * NTOK * AGENT];

// ---------------- bilinear helpers (jax half-pixel + clamp semantics) ----------------
__device__ __forceinline__ float bil7(const float* __restrict__ A, int wy, int wx) {
    float sy = (wy + 0.5f) * 0.5f - 0.5f;
    float sx = (wx + 0.5f) * 0.5f - 0.5f;
    sy = fminf(fmaxf(sy, 0.f), 6.f);
    sx = fminf(fmaxf(sx, 0.f), 6.f);
    int y0 = (int)sy; float fy = sy - y0; int y1 = min(y0 + 1, 6);
    int x0 = (int)sx; float fx = sx - x0; int x1 = min(x0 + 1, 6);
    float v00 = A[y0 * 7 + x0], v01 = A[y0 * 7 + x1];
    float v10 = A[y1 * 7 + x0], v11 = A[y1 * 7 + x1];
    return (1.f - fy) * ((1.f - fx) * v00 + fx * v01) +
           fy * ((1.f - fx) * v10 + fx * v11);
}

// pb[h][a][t] = resize(an_bias 7x7 -> 14x14) + ah_bias[h][a][wy] + aw_bias[h][a][wx]
__global__ void k_pb(const float* __restrict__ an, const float* __restrict__ ahb,
                     const float* __restrict__ awb) {
    int ha = blockIdx.x;            // h*49 + a
    int t = threadIdx.x;
    if (t >= WW2) return;
    int wy = t / WIN, wx = t % WIN;
    float v = bil7(an + ha * 49, wy, wx);
    g_pb[ha * WW2 + t] = v + ahb[ha * WIN + wy] + awb[ha * WIN + wx];
}

// ab[h][r][a]: r=0 -> ca_bias; r=1+t -> resize(na)[h][a][t] + ha[h][wy][a] + wa[h][wx][a]
__global__ void k_ab(const float* __restrict__ na, const float* __restrict__ hab,
                     const float* __restrict__ wab, const float* __restrict__ cab) {
    int tid = blockIdx.x * blockDim.x + threadIdx.x;
    int total = HEADS * 197 * AGENT;
    if (tid >= total) return;
    int h = tid / (197 * AGENT);
    int r = (tid / AGENT) % 197;
    int a = tid % AGENT;
    float v;
    if (r == 0) {
        v = cab[h * AGENT + a];
    } else {
        int t = r - 1;
        int wy = t / WIN, wx = t % WIN;
        v = bil7(na + (h * AGENT + a) * 49, wy, wx)
          + hab[(h * WIN + wy) * AGENT + a]
          + wab[(h * WIN + wx) * AGENT + a];
    }
    g_ab[(h * 197 + r) * AGENT + a] = v;
}

// bias1[h][a][n]: 1D resize 196 -> 3136 of pb along last dim
__global__ void k_bias1() {
    int tid = blockIdx.x * blockDim.x + threadIdx.x;
    int total = HEADS * AGENT * NTOK;
    if (tid >= total) return;
    int ha = tid / NTOK;
    int n = tid % NTOK;
    float s = (n + 0.5f) * 0.0625f - 0.5f;     // *196/3136
    s = fminf(fmaxf(s, 0.f), 195.f);
    int t0 = (int)s; float f = s - t0; int t1 = min(t0 + 1, 195);
    g_bias1[tid] = g_pb[ha * WW2 + t0] * (1.f - f) + g_pb[ha * WW2 + t1] * f;
}

// bias2[h][n][a]: 1D resize 197 -> 3136 of ab along dim -2
__global__ void k_bias2() {
    int tid = blockIdx.x * blockDim.x + threadIdx.x;
    int total = HEADS * NTOK * AGENT;
    if (tid >= total) return;
    int h = tid / (NTOK * AGENT);
    int rem = tid % (NTOK * AGENT);
    int n = rem / AGENT;
    int a = rem % AGENT;
    float s = (n + 0.5f) * (197.0f / 3136.0f) - 0.5f;
    s = fminf(fmaxf(s, 0.f), 196.f);
    int r0 = (int)s; float f = s - r0; int r1 = min(r0 + 1, 196);
    g_bias2[tid] = g_ab[(h * 197 + r0) * AGENT + a] * (1.f - f)
                 + g_ab[(h * 197 + r1) * AGENT + a] * f;
}

// ---------------- SGEMM (NT): C[M,N] = A[M,K] * B[N,K]^T (+bias) ----------------
__global__ __launch_bounds__(256, 2) void sgemm_nt(
    const float* __restrict__ A, const float* __restrict__ B,
    const float* __restrict__ bias, float* __restrict__ C,
    int M, int N, int K, int useBias)
{
    constexpr int BK = 16;
    __shared__ float As[BK][128];
    __shared__ float Bs[BK][128];
    const int t = threadIdx.x;
    const size_t m0 = (size_t)blockIdx.y * 128;
    const size_t n0 = (size_t)blockIdx.x * 128;
    const float* Ab = A + m0 * K;
    const float* Bb = B + n0 * K;

    const int lr = t >> 2;          // 0..63
    const int lc = (t & 3) * 4;     // 0,4,8,12

    float4 pa0 = *(const float4*)(Ab + (size_t)lr * K + lc);
    float4 pa1 = *(const float4*)(Ab + (size_t)(lr + 64) * K + lc);
    float4 pb0 = *(const float4*)(Bb + (size_t)lr * K + lc);
    float4 pb1 = *(const float4*)(Bb + (size_t)(lr + 64) * K + lc);

    const int tx = t & 15, ty = t >> 4;
    float acc[8][8];
#pragma unroll
    for (int i = 0; i < 8; i++)
#pragma unroll
        for (int j = 0; j < 8; j++) acc[i][j] = 0.f;

    for (int k0 = 0;; k0 += BK) {
        As[lc + 0][lr] = pa0.x; As[lc + 1][lr] = pa0.y; As[lc + 2][lr] = pa0.z; As[lc + 3][lr] = pa0.w;
        As[lc + 0][lr + 64] = pa1.x; As[lc + 1][lr + 64] = pa1.y; As[lc + 2][lr + 64] = pa1.z; As[lc + 3][lr + 64] = pa1.w;
        Bs[lc + 0][lr] = pb0.x; Bs[lc + 1][lr] = pb0.y; Bs[lc + 2][lr] = pb0.z; Bs[lc + 3][lr] = pb0.w;
        Bs[lc + 0][lr + 64] = pb1.x; Bs[lc + 1][lr + 64] = pb1.y; Bs[lc + 2][lr + 64] = pb1.z; Bs[lc + 3][lr + 64] = pb1.w;
        __syncthreads();

        bool more = (k0 + BK) < K;
        if (more) {
            int kn = k0 + BK;
            pa0 = *(const float4*)(Ab + (size_t)lr * K + kn + lc);
            pa1 = *(const float4*)(Ab + (size_t)(lr + 64) * K + kn + lc);
            pb0 = *(const float4*)(Bb + (size_t)lr * K + kn + lc);
            pb1 = *(const float4*)(Bb + (size_t)(lr + 64) * K + kn + lc);
        }

#pragma unroll
        for (int kk = 0; kk < BK; kk++) {
            float4 a0 = *(const float4*)&As[kk][ty * 8];
            float4 a1 = *(const float4*)&As[kk][ty * 8 + 4];
            float4 b0 = *(const float4*)&Bs[kk][tx * 8];
            float4 b1 = *(const float4*)&Bs[kk][tx * 8 + 4];
            float ar[8] = {a0.x, a0.y, a0.z, a0.w, a1.x, a1.y, a1.z, a1.w};
            float br[8] = {b0.x, b0.y, b0.z, b0.w, b1.x, b1.y, b1.z, b1.w};
#pragma unroll
            for (int i = 0; i < 8; i++)
#pragma unroll
                for (int j = 0; j < 8; j++) acc[i][j] += ar[i] * br[j];
        }
        __syncthreads();
        if (!more) break;
    }

#pragma unroll
    for (int i = 0; i < 8; i++) {
        size_t m = m0 + ty * 8 + i;
        float* Crow = C + m * N + n0 + tx * 8;
#pragma unroll
        for (int j = 0; j < 8; j += 4) {
            float4 v = make_float4(acc[i][j], acc[i][j + 1], acc[i][j + 2], acc[i][j + 3]);
            if (useBias) {
                const float* bp = bias + n0 + tx * 8 + j;
                v.x += bp[0]; v.y += bp[1]; v.z += bp[2]; v.w += bp[3];
            }
            *(float4*)(Crow + j) = v;
        }
    }
}

// ---------------- agent pooling: exact 8x8 block mean of q ----------------
__global__ void k_agent() {
    int b = blockIdx.x / AGENT;
    int a = blockIdx.x % AGENT;
    int py = a / 7, px = a % 7;
    int c = threadIdx.x;
    float s = 0.f;
#pragma unroll 4
    for (int dy = 0; dy < 8; dy++)
        for (int dx = 0; dx < 8; dx++) {
            int n = (py * 8 + dy) * WWID + px * 8 + dx;
            s += g_qkv[((size_t)b * NTOK + n) * 1536 + c];
        }
    g_agent[((size_t)b * AGENT + a) * DIM + c] = s * (1.f / 64.f);
}

// ---------------- stage 1 (fused flash, split-KV): agent->kv attention ----------------
// grid (S1SPLIT, HEADS, BB), 256 threads. Each block handles 5 chunks of 128 tokens.
#define S1_SMEM_FLOATS (3136 + 128 * 65 + 49 * 128 + 192)
__global__ __launch_bounds__(256) void k_s1() {
    extern __shared__ float sm[];
    float* ah_s = sm;                       // 49*64
    float* ks   = sm + 3136;                // 128*65 (padded)
    float* sc   = sm + 3136 + 8320;         // 49*128 scores/probs
    float* mrow = sc + 6272;                // 49 (pad 64)
    float* srow = mrow + 64;                // 49
    float* frow = srow + 64;                // 49
    int split = blockIdx.x, h = blockIdx.y, b = blockIdx.z;
    int t = threadIdx.x, warp = t >> 5, lane = t & 31;
    int g = t >> 6, d = t & 63;
    const int base = (g == 0) ? 0 : (13 + 12 * (g - 1));   // 0,13,25,37
    const int cnt = (g == 0) ? 13 : 12;

    for (int idx = t; idx < AGENT * HD; idx += 256) {
        int a = idx >> 6, dd = idx & 63;
        ah_s[idx] = g_agent[((size_t)b * AGENT + a) * DIM + h * HD + dd] * 0.125f;
    }
    if (t < AGENT) { mrow[t] = -1e30f; srow[t] = 0.f; }
    float acc[13];
#pragma unroll
    for (int i = 0; i < 13; i++) acc[i] = 0.f;
    __syncthreads();

    for (int c = 0; c < 5; c++) {
        int n0 = (split * 5 + c) * 128;
        int nc = min(128, NTOK - n0);       // last chunk of last split: 64

        // load k chunk (coalesced)
        for (int idx = t; idx < 128 * 64; idx += 256) {
            int r = idx >> 6, dd = idx & 63;
            ks[r * 65 + dd] = (r < nc)
                ? g_qkv[((size_t)b * NTOK + n0 + r) * 1536 + DIM + h * HD + dd] : 0.f;
        }
        __syncthreads();

        // scores + bias
        for (int idx = t; idx < AGENT * 128; idx += 256) {
            int a = idx >> 7, nl = idx & 127;
            float sv;
            if (nl < nc) {
                float s = 0.f;
#pragma unroll
                for (int dd = 0; dd < 64; dd++) s += ks[nl * 65 + dd] * ah_s[a * 64 + dd];
                sv = s + g_bias1[(h * AGENT + a) * NTOK + n0 + nl];
            } else sv = -1e30f;
            sc[idx] = sv;
        }
        __syncthreads();

        // per-row online stats (8 warps cover 49 rows)
        for (int a = warp; a < AGENT; a += 8) {
            float cm = -1e30f;
            for (int i = lane; i < 128; i += 32) cm = fmaxf(cm, sc[a * 128 + i]);
            for (int off = 16; off; off >>= 1)
                cm = fmaxf(cm, __shfl_xor_sync(0xffffffffu, cm, off));
            float mo = mrow[a];
            float nm = fmaxf(mo, cm);
            float f = __expf(mo - nm);
            float rs = 0.f;
            for (int i = lane; i < 128; i += 32) {
                float p = __expf(sc[a * 128 + i] - nm);
                sc[a * 128 + i] = p;
                rs += p;
            }
            for (int off = 16; off; off >>= 1)
                rs += __shfl_xor_sync(0xffffffffu, rs, off);
            if (lane == 0) { mrow[a] = nm; srow[a] = srow[a] * f + rs; frow[a] = f; }
        }
        __syncthreads();

        // rescale + accumulate V
#pragma unroll
        for (int i = 0; i < 13; i++)
            if (i < cnt) acc[i] *= frow[base + i];
        for (int nl = 0; nl < nc; nl++) {
            float vv = g_qkv[((size_t)b * NTOK + n0 + nl) * 1536 + 1024 + h * HD + d];
#pragma unroll
            for (int i = 0; i < 13; i++)
                if (i < cnt) acc[i] += sc[(base + i) * 128 + nl] * vv;
        }
        __syncthreads();
    }

    // write partials
    size_t pb_ = (((size_t)(b * HEADS + h)) * S1SPLIT + split) * AGENT;
#pragma unroll
    for (int i = 0; i < 13; i++)
        if (i < cnt) g_pacc[(pb_ + base + i) * HD + d] = acc[i];
    if (t < AGENT) { g_pm[pb_ + t] = mrow[t]; g_ps[pb_ + t] = srow[t]; }
}

// merge split-KV partials -> g_agentv
__global__ __launch_bounds__(256) void k_s1merge() {
    int bh = blockIdx.x;
    int t = threadIdx.x;
    for (int idx = t; idx < AGENT * HD; idx += 256) {
        int a = idx >> 6, d = idx & 63;
        size_t p0 = ((size_t)bh * S1SPLIT) * AGENT + a;
        float nm = -1e30f;
        for (int s = 0; s < S1SPLIT; s++) nm = fmaxf(nm, g_pm[p0 + s * AGENT]);
        float S = 0.f, A = 0.f;
        for (int s = 0; s < S1SPLIT; s++) {
            float w = __expf(g_pm[p0 + s * AGENT] - nm);
            S += g_ps[p0 + s * AGENT] * w;
            A += g_pacc[(p0 + s * AGENT) * HD + d] * w;
        }
        g_agentv[((size_t)bh * AGENT + a) * HD + d] = A / S;
    }
}

// ---------------- stage 2: q->agent attention, fully fused per n ----------------
#define S2_SMEM_FLOATS (3136 + 3136 + 128 * 65 + 128 * 49)
__global__ __launch_bounds__(128) void k_s2() {
    extern __shared__ float sm[];
    float* ah_s = sm;                  // 49*64
    float* av_s = sm + 3136;           // 49*64
    float* qs   = sm + 6272;           // 128*65
    float* bsm  = sm + 6272 + 8320;    // 128*49
    int chunk = blockIdx.x, h = blockIdx.y, b = blockIdx.z;
    int t = threadIdx.x;
    int n0 = chunk * 128;

    for (int idx = t; idx < AGENT * HD; idx += 128) {
        int a = idx >> 6, d = idx & 63;
        ah_s[idx] = g_agent[((size_t)b * AGENT + a) * DIM + h * HD + d] * 0.125f;
        av_s[idx] = g_agentv[((size_t)(b * HEADS + h)) * AGENT * HD + idx];
    }
    for (int idx = t; idx < 128 * 64; idx += 128) {
        int r = idx >> 6, d = idx & 63;
        int n = n0 + r;
        qs[r * 65 + d] = (n < NTOK)
            ? g_qkv[((size_t)b * NTOK + n) * 1536 + h * HD + d] : 0.f;
    }
    for (int idx = t; idx < 128 * AGENT; idx += 128) {
        if (n0 * AGENT + idx < NTOK * AGENT)
            bsm[idx] = g_bias2[(size_t)h * NTOK * AGENT + (size_t)n0 * AGENT + idx];
    }
    __syncthreads();

    int n = n0 + t;
    if (n < NTOK) {
        float qr[64];
#pragma unroll
        for (int d = 0; d < 64; d++) qr[d] = qs[t * 65 + d];
        float m = -1e30f;
        for (int a = 0; a < AGENT; a++) {
            float s = 0.f;
#pragma unroll
            for (int d = 0; d < 64; d++) s += qr[d] * ah_s[a * 64 + d];
            s += bsm[t * AGENT + a];
            bsm[t * AGENT + a] = s;
            m = fmaxf(m, s);
        }
        float sum = 0.f;
        for (int a = 0; a < AGENT; a++) {
            float p = __expf(bsm[t * AGENT + a] - m);
            bsm[t * AGENT + a] = p;
            sum += p;
        }
        float inv = 1.f / sum;
        for (int d = 0; d < 64; d++) {
            float o = 0.f;
            for (int a = 0; a < AGENT; a++) o += bsm[t * AGENT + a] * av_s[a * 64 + d];
            qs[t * 65 + d] = o * inv;      // own row only: no sync needed
        }
    }
    __syncthreads();
    for (int idx = t; idx < 128 * 64; idx += 128) {
        int r = idx >> 6, dd = idx & 63;
        int nn = n0 + r;
        if (nn < NTOK)
            g_attnout[((size_t)b * NTOK + nn) * DIM + h * HD + dd] = qs[r * 65 + dd];
    }
}

// ---------------- depthwise 3x3 conv on v (SAME, zero pad), += into attn_out ----------------
__global__ __launch_bounds__(256) void k_dwc(const float* __restrict__ w_dwc,
                                             const float* __restrict__ b_dwc) {
    int y = blockIdx.x, b = blockIdx.y, t = threadIdx.x;
    int c = (t & 127) * 4;
    int xh = t >> 7;
    float wreg[4][9], bd[4];
#pragma unroll
    for (int j = 0; j < 4; j++) {
        bd[j] = b_dwc[c + j];
#pragma unroll
        for (int kk = 0; kk < 9; kk++) wreg[j][kk] = w_dwc[(c + j) * 9 + kk];
    }
    for (int x = xh; x < WWID; x += 2) {
        float a0 = bd[0], a1 = bd[1], a2 = bd[2], a3 = bd[3];
#pragma unroll
        for (int ky = 0; ky < 3; ky++) {
            int yy = y + ky - 1;
            if ((unsigned)yy >= HH) continue;
#pragma unroll
            for (int kx = 0; kx < 3; kx++) {
                int xx = x + kx - 1;
                if ((unsigned)xx >= WWID) continue;
                const float4 v = *(const float4*)&g_qkv[
                    (((size_t)b * NTOK) + yy * WWID + xx) * 1536 + 1024 + c];
                int kk = ky * 3 + kx;
                a0 += v.x * wreg[0][kk];
                a1 += v.y * wreg[1][kk];
                a2 += v.z * wreg[2][kk];
                a3 += v.w * wreg[3][kk];
            }
        }
        size_t o = (((size_t)b * NTOK) + y * WWID + x) * DIM + c;
        float4 cur = *(float4*)&g_attnout[o];
        cur.x += a0; cur.y += a1; cur.z += a2; cur.w += a3;
        *(float4*)&g_attnout[o] = cur;
    }
}

// ---------------- launcher ----------------
extern "C" void kernel_launch(void* const* d_in, const int* in_sizes, int n_in,
                              void* d_out, int out_size) {
    const float* x      = (const float*)d_in[0];
    const float* w_qkv  = (const float*)d_in[1];
    const float* w_proj = (const float*)d_in[2];
    const float* b_proj = (const float*)d_in[3];
    const float* w_dwc  = (const float*)d_in[4];
    const float* b_dwc  = (const float*)d_in[5];
    const float* an     = (const float*)d_in[6];
    const float* na     = (const float*)d_in[7];
    const float* ahb    = (const float*)d_in[8];
    const float* awb    = (const float*)d_in[9];
    const float* hab    = (const float*)d_in[10];
    const float* wab    = (const float*)d_in[11];
    const float* cab    = (const float*)d_in[12];
    float* out = (float*)d_out;

    void *p_qkv = nullptr, *p_ao = nullptr;
    cudaGetSymbolAddress(&p_qkv, g_qkv);
    cudaGetSymbolAddress(&p_ao, g_attnout);
    float* qkv = (float*)p_qkv;
    float* ao = (float*)p_ao;

    cudaFuncSetAttribute(k_s1, cudaFuncAttributeMaxDynamicSharedMemorySize,
                         S1_SMEM_FLOATS * (int)sizeof(float));
    cudaFuncSetAttribute(k_s2, cudaFuncAttributeMaxDynamicSharedMemorySize,
                         S2_SMEM_FLOATS * (int)sizeof(float));

    // QKV GEMM: (50176,512) x (1536,512)^T -> (50176,1536)
    sgemm_nt<<<dim3(1536 / 128, (BB * NTOK) / 128), 256>>>(
        x, w_qkv, nullptr, qkv, BB * NTOK, 1536, DIM, 0);

    // bias tables (b-independent)
    k_pb<<<HEADS * AGENT, WW2>>>(an, ahb, awb);
    k_ab<<<(HEADS * 197 * AGENT + 255) / 256, 256>>>(na, hab, wab, cab);
    k_bias1<<<(HEADS * AGENT * NTOK + 255) / 256, 256>>>();
    k_bias2<<<(HEADS * NTOK * AGENT + 255) / 256, 256>>>();

    // agent pooling
    k_agent<<<BB * AGENT, DIM>>>();

    // stage 1: fused flash attention, split-KV + merge
    k_s1<<<dim3(S1SPLIT, HEADS, BB), 256, S1_SMEM_FLOATS * (int)sizeof(float)>>>();
    k_s1merge<<<BB * HEADS, 256>>>();

    // stage 2 (writes attn_out)
    k_s2<<<dim3(25, HEADS, BB), 128, S2_SMEM_FLOATS * (int)sizeof(float)>>>();

    // depthwise conv residual (+= attn_out)
    k_dwc<<<dim3(HH, BB), 256>>>(w_dwc, b_dwc);

    // projection GEMM with bias -> final output
    sgemm_nt<<<dim3(DIM / 128, (BB * NTOK) / 128), 256>>>(
        ao, w_proj, b_proj, out, BB * NTOK, DIM, DIM, 1);
}

// round 10
// speedup vs baseline: 1.4834x; 1.4834x over previous
#include <cuda_runtime.h>
#include <math.h>

typedef unsigned int u32;
typedef unsigned long long u64;

// ---------------- problem constants ----------------
#define BB    16
#define NTOK  3136
#define DIM   512
#define HH    56
#define WWID  56
#define HEADS 8
#define HD    64
#define AGENT 49
#define WIN   14
#define WW2   196   // 14*14
#define S1SPLIT 5

// ---------------- scratch (device globals; no allocation allowed) ----------------
__device__ float g_qkv[(size_t)BB * NTOK * 3 * DIM];            // fp32 qkv
__device__ float g_attnout[(size_t)BB * NTOK * DIM];            // attention only
__device__ unsigned short g_xhl[(size_t)BB * NTOK * 2 * DIM];   // x hi/lo bf16 bits
__device__ unsigned short g_aohl[(size_t)BB * NTOK * 2 * DIM];  // attn+dwc hi/lo bf16 bits
__device__ unsigned short g_wqkvhl[3 * DIM * 2 * DIM];
__device__ unsigned short g_wprojhl[DIM * 2 * DIM];
__device__ float g_agent[BB * AGENT * DIM];
__device__ float g_agentv[BB * HEADS * AGENT * HD];
__device__ float g_pacc[(size_t)BB * HEADS * S1SPLIT * AGENT * HD];
__device__ float g_pm[BB * HEADS * S1SPLIT * AGENT];
__device__ float g_ps[BB * HEADS * S1SPLIT * AGENT];
__device__ float g_pb[HEADS * AGENT * WW2];
__device__ float g_ab[HEADS * 197 * AGENT];
__device__ float g_bias1[HEADS * AGENT * NTOK];
__device__ float g_bias2[HEADS * NTOK * AGENT];

// ---------------- manual bf16 helpers (no cuda_bf16 types) ----------------
__device__ __forceinline__ u32 f2bf(float f) {           // round-to-nearest-even
    u32 u = __float_as_uint(f);
    return (u + 0x7fffu + ((u >> 16) & 1u)) >> 16;
}
__device__ __forceinline__ float bf2f(u32 b) { return __uint_as_float(b << 16); }
__device__ __forceinline__ u32 pack2(float lo, float hi) {
    return f2bf(lo) | (f2bf(hi) << 16);
}

// ---------------- bilinear helpers (jax half-pixel + clamp semantics) ----------------
__device__ __forceinline__ float bil7(const float* __restrict__ A, int wy, int wx) {
    float sy = (wy + 0.5f) * 0.5f - 0.5f;
    float sx = (wx + 0.5f) * 0.5f - 0.5f;
    sy = fminf(fmaxf(sy, 0.f), 6.f);
    sx = fminf(fmaxf(sx, 0.f), 6.f);
    int y0 = (int)sy; float fy = sy - y0; int y1 = min(y0 + 1, 6);
    int x0 = (int)sx; float fx = sx - x0; int x1 = min(x0 + 1, 6);
    float v00 = A[y0 * 7 + x0], v01 = A[y0 * 7 + x1];
    float v10 = A[y1 * 7 + x0], v11 = A[y1 * 7 + x1];
    return (1.f - fy) * ((1.f - fx) * v00 + fx * v01) +
           fy * ((1.f - fx) * v10 + fx * v11);
}

__global__ void k_pb(const float* __restrict__ an, const float* __restrict__ ahb,
                     const float* __restrict__ awb) {
    int ha = blockIdx.x;
    int t = threadIdx.x;
    if (t >= WW2) return;
    int wy = t / WIN, wx = t % WIN;
    float v = bil7(an + ha * 49, wy, wx);
    g_pb[ha * WW2 + t] = v + ahb[ha * WIN + wy] + awb[ha * WIN + wx];
}

__global__ void k_ab(const float* __restrict__ na, const float* __restrict__ hab,
                     const float* __restrict__ wab, const float* __restrict__ cab) {
    int tid = blockIdx.x * blockDim.x + threadIdx.x;
    int total = HEADS * 197 * AGENT;
    if (tid >= total) return;
    int h = tid / (197 * AGENT);
    int r = (tid / AGENT) % 197;
    int a = tid % AGENT;
    float v;
    if (r == 0) {
        v = cab[h * AGENT + a];
    } else {
        int t = r - 1;
        int wy = t / WIN, wx = t % WIN;
        v = bil7(na + (h * AGENT + a) * 49, wy, wx)
          + hab[(h * WIN + wy) * AGENT + a]
          + wab[(h * WIN + wx) * AGENT + a];
    }
    g_ab[(h * 197 + r) * AGENT + a] = v;
}

__global__ void k_bias1() {
    int tid = blockIdx.x * blockDim.x + threadIdx.x;
    int total = HEADS * AGENT * NTOK;
    if (tid >= total) return;
    int ha = tid / NTOK;
    int n = tid % NTOK;
    float s = (n + 0.5f) * 0.0625f - 0.5f;
    s = fminf(fmaxf(s, 0.f), 195.f);
    int t0 = (int)s; float f = s - t0; int t1 = min(t0 + 1, 195);
    g_bias1[tid] = g_pb[ha * WW2 + t0] * (1.f - f) + g_pb[ha * WW2 + t1] * f;
}

__global__ void k_bias2() {
    int tid = blockIdx.x * blockDim.x + threadIdx.x;
    int total = HEADS * NTOK * AGENT;
    if (tid >= total) return;
    int h = tid / (NTOK * AGENT);
    int rem = tid % (NTOK * AGENT);
    int n = rem / AGENT;
    int a = rem % AGENT;
    float s = (n + 0.5f) * (197.0f / 3136.0f) - 0.5f;
    s = fminf(fmaxf(s, 0.f), 196.f);
    int r0 = (int)s; float f = s - r0; int r1 = min(r0 + 1, 196);
    g_bias2[tid] = g_ab[(h * 197 + r0) * AGENT + a] * (1.f - f)
                 + g_ab[(h * 197 + r1) * AGENT + a] * f;
}

// ---------------- fp32 -> bf16 hi/lo split conversion ----------------
// src: [M, 512] fp32 row-major. dst: [M, 1024] bf16-bits, row = [hi(512) | lo(512)]
__global__ void k_cvt(const float* __restrict__ src, unsigned short* __restrict__ dst,
                      int total4) {
    int idx = blockIdx.x * 256 + threadIdx.x;
    if (idx >= total4) return;
    int m = idx >> 7;            // /128  (512/4 groups per row)
    int k4 = (idx & 127) << 2;
    float4 v = *(const float4*)(src + (size_t)m * 512 + k4);
    u32 h0 = f2bf(v.x), h1 = f2bf(v.y), h2 = f2bf(v.z), h3 = f2bf(v.w);
    float r0 = v.x - bf2f(h0), r1 = v.y - bf2f(h1);
    float r2 = v.z - bf2f(h2), r3 = v.w - bf2f(h3);
    u32* dh = (u32*)(dst + (size_t)m * 1024 + k4);
    dh[0] = h0 | (h1 << 16);
    dh[1] = h2 | (h3 << 16);
    u32* dl = (u32*)(dst + (size_t)m * 1024 + 512 + k4);
    dl[0] = pack2(r0, r1);
    dl[1] = pack2(r2, r3);
}

// ================= bf16x3 GEMM via mma.sync (HMMA, base sm_103-safe) =================
// C[M,N] = A[M,512]*B[N,512]^T (+bias). A/B rows: 1024 bf16 = [hi(512)|lo(512)].
// CTA tile 128x128, 256 thr (8 warps 4x2, warp tile 32x64), BK=32, 4-stage cp.async.
// smem stage: Ah/Al/Bh/Bl planes, each 128 rows x 80B (32 halves + 8 pad).

#define G_PLANE 10240                       // 128 * 80 bytes
#define G_STAGE (4 * G_PLANE)               // 40960
#define G_NSTG  4
#define GSMEM_TOTAL (G_NSTG * G_STAGE)      // 163840

static __device__ __forceinline__ u32 smem_u32(const void* p) {
    u32 a;
    asm("{ .reg .u64 t; cvta.to.shared.u64 t, %1; cvt.u32.u64 %0, t; }" : "=r"(a) : "l"(p));
    return a;
}
static __device__ __forceinline__ void cpa16(u32 s, const void* g) {
    asm volatile("cp.async.cg.shared.global [%0], [%1], 16;" :: "r"(s), "l"(g) : "memory");
}
static __device__ __forceinline__ void ldsm4(u32* r, u32 addr) {
    asm volatile("ldmatrix.sync.aligned.m8n8.x4.shared.b16 {%0,%1,%2,%3}, [%4];"
        : "=r"(r[0]), "=r"(r[1]), "=r"(r[2]), "=r"(r[3]) : "r"(addr));
}
static __device__ __forceinline__ void mma16816(float* c, const u32* a, const u32* b) {
    asm volatile("mma.sync.aligned.m16n8k16.row.col.f32.bf16.bf16.f32 "
        "{%0,%1,%2,%3}, {%4,%5,%6,%7}, {%8,%9}, {%0,%1,%2,%3};"
        : "+f"(c[0]), "+f"(c[1]), "+f"(c[2]), "+f"(c[3])
        : "r"(a[0]), "r"(a[1]), "r"(a[2]), "r"(a[3]), "r"(b[0]), "r"(b[1]));
}

// load K-chunk c (32 halves per plane) for A rows m0..+128 and B rows n0..+128
static __device__ __forceinline__ void load_chunk(
    u32 buf, const unsigned short* __restrict__ A, const unsigned short* __restrict__ B,
    int m0, int n0, int c, int tid)
{
    for (int idx = tid; idx < 512; idx += 256) {
        int r = idx >> 2, seg = idx & 3;
        const unsigned short* g = A + (size_t)(m0 + r) * 1024 + c * 32 + seg * 8;
        u32 d = buf + r * 80 + seg * 16;
        cpa16(d, g);                 // A hi
        cpa16(d + G_PLANE, g + 512); // A lo
    }
    for (int idx = tid; idx < 512; idx += 256) {
        int r = idx >> 2, seg = idx & 3;
        const unsigned short* g = B + (size_t)(n0 + r) * 1024 + c * 32 + seg * 8;
        u32 d = buf + 2 * G_PLANE + r * 80 + seg * 16;
        cpa16(d, g);                 // B hi
        cpa16(d + G_PLANE, g + 512); // B lo
    }
    asm volatile("cp.async.commit_group;" ::: "memory");
}

__global__ __launch_bounds__(256)
void k_gemm(const unsigned short* __restrict__ Ahl, const unsigned short* __restrict__ Bhl,
            const float* __restrict__ bias, float* __restrict__ C, int ldc)
{
    extern __shared__ char smem[];
    const u32 sb = smem_u32(smem);
    const int tid = threadIdx.x;
    const int wid = tid >> 5, lane = tid & 31;
    const int wm = wid >> 1, wn = wid & 1;       // 4 x 2 warp grid
    const int m0 = blockIdx.y * 128;
    const int n0 = blockIdx.x * 128;
    const int row_a = lane & 15;                 // ldmatrix row within 16
    const int kseg = lane >> 4;                  // 0/1 -> k halves 0-7 / 8-15

    float acc[2][8][4];
#pragma unroll
    for (int mt = 0; mt < 2; mt++)
#pragma unroll
        for (int j = 0; j < 8; j++)
#pragma unroll
            for (int q = 0; q < 4; q++) acc[mt][j][q] = 0.f;

    // prologue: 3 chunks in flight
    load_chunk(sb + 0 * G_STAGE, Ahl, Bhl, m0, n0, 0, tid);
    load_chunk(sb + 1 * G_STAGE, Ahl, Bhl, m0, n0, 1, tid);
    load_chunk(sb + 2 * G_STAGE, Ahl, Bhl, m0, n0, 2, tid);

    for (int c = 0; c < 16; c++) {
        if (c + 3 < 16)
            load_chunk(sb + ((c + 3) & 3) * G_STAGE, Ahl, Bhl, m0, n0, c + 3, tid);
        int rem = 15 - c;
        if (rem >= 3)      asm volatile("cp.async.wait_group 3;" ::: "memory");
        else if (rem == 2) asm volatile("cp.async.wait_group 2;" ::: "memory");
        else if (rem == 1) asm volatile("cp.async.wait_group 1;" ::: "memory");
        else               asm volatile("cp.async.wait_group 0;" ::: "memory");
        __syncthreads();

        const u32 buf = sb + (c & 3) * G_STAGE;
#pragma unroll
        for (int ks = 0; ks < 2; ks++) {
            const int kb = ks * 32 + kseg * 16;  // byte offset of k within 64B row
            u32 ah[2][4], al[2][4], bh[8][2], bl[8][2];
#pragma unroll
            for (int mt = 0; mt < 2; mt++) {
                u32 ad = buf + (u32)((wm * 32 + mt * 16 + row_a) * 80) + kb;
                ldsm4(ah[mt], ad);
                ldsm4(al[mt], ad + G_PLANE);
            }
#pragma unroll
            for (int nt = 0; nt < 4; nt++) {
                u32 bd = buf + 2 * G_PLANE + (u32)((wn * 64 + nt * 16 + row_a) * 80) + kb;
                u32 r[4];
                ldsm4(r, bd);
                bh[2 * nt][0] = r[0]; bh[2 * nt + 1][0] = r[1];
                bh[2 * nt][1] = r[2]; bh[2 * nt + 1][1] = r[3];
                ldsm4(r, bd + G_PLANE);
                bl[2 * nt][0] = r[0]; bl[2 * nt + 1][0] = r[1];
                bl[2 * nt][1] = r[2]; bl[2 * nt + 1][1] = r[3];
            }
#pragma unroll
            for (int mt = 0; mt < 2; mt++)
#pragma unroll
                for (int j = 0; j < 8; j++) {
                    mma16816(acc[mt][j], ah[mt], bh[j]);
                    mma16816(acc[mt][j], ah[mt], bl[j]);
                    mma16816(acc[mt][j], al[mt], bh[j]);
                }
        }
        __syncthreads();
    }

    // epilogue: direct float2 stores (+bias)
    const int gq = lane >> 2, tg = lane & 3;
#pragma unroll
    for (int mt = 0; mt < 2; mt++) {
        int row = m0 + wm * 32 + mt * 16 + gq;
#pragma unroll
        for (int j = 0; j < 8; j++) {
            int col = n0 + wn * 64 + j * 8 + tg * 2;
            float b0 = 0.f, b1 = 0.f;
            if (bias) { b0 = bias[col]; b1 = bias[col + 1]; }
            float2 v0 = make_float2(acc[mt][j][0] + b0, acc[mt][j][1] + b1);
            float2 v1 = make_float2(acc[mt][j][2] + b0, acc[mt][j][3] + b1);
            *(float2*)&C[(size_t)row * ldc + col] = v0;
            *(float2*)&C[(size_t)(row + 8) * ldc + col] = v1;
        }
    }
}

// ---------------- agent pooling: exact 8x8 block mean of q ----------------
__global__ void k_agent() {
    int b = blockIdx.x / AGENT;
    int a = blockIdx.x % AGENT;
    int py = a / 7, px = a % 7;
    int c = threadIdx.x;
    float s = 0.f;
#pragma unroll 4
    for (int dy = 0; dy < 8; dy++)
        for (int dx = 0; dx < 8; dx++) {
            int n = (py * 8 + dy) * WWID + px * 8 + dx;
            s += g_qkv[((size_t)b * NTOK + n) * 1536 + c];
        }
    g_agent[((size_t)b * AGENT + a) * DIM + c] = s * (1.f / 64.f);
}

// ---------------- stage 1 (fused flash, split-KV) ----------------
#define S1_SMEM_FLOATS (3136 + 128 * 65 + 49 * 128 + 192)
__global__ __launch_bounds__(256) void k_s1() {
    extern __shared__ float sm[];
    float* ah_s = sm;
    float* ks   = sm + 3136;
    float* sc   = sm + 3136 + 8320;
    float* mrow = sc + 6272;
    float* srow = mrow + 64;
    float* frow = srow + 64;
    int split = blockIdx.x, h = blockIdx.y, b = blockIdx.z;
    int t = threadIdx.x, warp = t >> 5, lane = t & 31;
    int g = t >> 6, d = t & 63;
    const int base = (g == 0) ? 0 : (13 + 12 * (g - 1));
    const int cnt = (g == 0) ? 13 : 12;

    for (int idx = t; idx < AGENT * HD; idx += 256) {
        int a = idx >> 6, dd = idx & 63;
        ah_s[idx] = g_agent[((size_t)b * AGENT + a) * DIM + h * HD + dd] * 0.125f;
    }
    if (t < AGENT) { mrow[t] = -1e30f; srow[t] = 0.f; }
    float acc[13];
#pragma unroll
    for (int i = 0; i < 13; i++) acc[i] = 0.f;
    __syncthreads();

    for (int c = 0; c < 5; c++) {
        int n0 = (split * 5 + c) * 128;
        int nc = min(128, NTOK - n0);

        for (int idx = t; idx < 128 * 64; idx += 256) {
            int r = idx >> 6, dd = idx & 63;
            ks[r * 65 + dd] = (r < nc)
                ? g_qkv[((size_t)b * NTOK + n0 + r) * 1536 + DIM + h * HD + dd] : 0.f;
        }
        __syncthreads();

        for (int idx = t; idx < AGENT * 128; idx += 256) {
            int a = idx >> 7, nl = idx & 127;
            float sv;
            if (nl < nc) {
                float s = 0.f;
#pragma unroll
                for (int dd = 0; dd < 64; dd++) s += ks[nl * 65 + dd] * ah_s[a * 64 + dd];
                sv = s + g_bias1[(h * AGENT + a) * NTOK + n0 + nl];
            } else sv = -1e30f;
            sc[idx] = sv;
        }
        __syncthreads();

        for (int a = warp; a < AGENT; a += 8) {
            float cm = -1e30f;
            for (int i = lane; i < 128; i += 32) cm = fmaxf(cm, sc[a * 128 + i]);
            for (int off = 16; off; off >>= 1)
                cm = fmaxf(cm, __shfl_xor_sync(0xffffffffu, cm, off));
            float mo = mrow[a];
            float nm = fmaxf(mo, cm);
            float f = __expf(mo - nm);
            float rs = 0.f;
            for (int i = lane; i < 128; i += 32) {
                float p = __expf(sc[a * 128 + i] - nm);
                sc[a * 128 + i] = p;
                rs += p;
            }
            for (int off = 16; off; off >>= 1)
                rs += __shfl_xor_sync(0xffffffffu, rs, off);
            if (lane == 0) { mrow[a] = nm; srow[a] = srow[a] * f + rs; frow[a] = f; }
        }
        __syncthreads();

#pragma unroll
        for (int i = 0; i < 13; i++)
            if (i < cnt) acc[i] *= frow[base + i];
        for (int nl = 0; nl < nc; nl++) {
            float vv = g_qkv[((size_t)b * NTOK + n0 + nl) * 1536 + 1024 + h * HD + d];
#pragma unroll
            for (int i = 0; i < 13; i++)
                if (i < cnt) acc[i] += sc[(base + i) * 128 + nl] * vv;
        }
        __syncthreads();
    }

    size_t pb_ = (((size_t)(b * HEADS + h)) * S1SPLIT + split) * AGENT;
#pragma unroll
    for (int i = 0; i < 13; i++)
        if (i < cnt) g_pacc[(pb_ + base + i) * HD + d] = acc[i];
    if (t < AGENT) { g_pm[pb_ + t] = mrow[t]; g_ps[pb_ + t] = srow[t]; }
}

__global__ __launch_bounds__(256) void k_s1merge() {
    int bh = blockIdx.x;
    int t = threadIdx.x;
    for (int idx = t; idx < AGENT * HD; idx += 256) {
        int a = idx >> 6, d = idx & 63;
        size_t p0 = ((size_t)bh * S1SPLIT) * AGENT + a;
        float nm = -1e30f;
        for (int s = 0; s < S1SPLIT; s++) nm = fmaxf(nm, g_pm[p0 + s * AGENT]);
        float S = 0.f, A = 0.f;
        for (int s = 0; s < S1SPLIT; s++) {
            float w = __expf(g_pm[p0 + s * AGENT] - nm);
            S += g_ps[p0 + s * AGENT] * w;
            A += g_pacc[(p0 + s * AGENT) * HD + d] * w;
        }
        g_agentv[((size_t)bh * AGENT + a) * HD + d] = A / S;
    }
}

// ---------------- stage 2: q->agent attention ----------------
#define S2_SMEM_FLOATS (3136 + 3136 + 128 * 65 + 128 * 49)
__global__ __launch_bounds__(128) void k_s2() {
    extern __shared__ float sm[];
    float* ah_s = sm;
    float* av_s = sm + 3136;
    float* qs   = sm + 6272;
    float* bsm  = sm + 6272 + 8320;
    int chunk = blockIdx.x, h = blockIdx.y, b = blockIdx.z;
    int t = threadIdx.x;
    int n0 = chunk * 128;

    for (int idx = t; idx < AGENT * HD; idx += 128) {
        int a = idx >> 6, d = idx & 63;
        ah_s[idx] = g_agent[((size_t)b * AGENT + a) * DIM + h * HD + d] * 0.125f;
        av_s[idx] = g_agentv[((size_t)(b * HEADS + h)) * AGENT * HD + idx];
    }
    for (int idx = t; idx < 128 * 64; idx += 128) {
        int r = idx >> 6, d = idx & 63;
        int n = n0 + r;
        qs[r * 65 + d] = (n < NTOK)
            ? g_qkv[((size_t)b * NTOK + n) * 1536 + h * HD + d] : 0.f;
    }
    for (int idx = t; idx < 128 * AGENT; idx += 128) {
        if (n0 * AGENT + idx < NTOK * AGENT)
            bsm[idx] = g_bias2[(size_t)h * NTOK * AGENT + (size_t)n0 * AGENT + idx];
    }
    __syncthreads();

    int n = n0 + t;
    if (n < NTOK) {
        float qr[64];
#pragma unroll
        for (int d = 0; d < 64; d++) qr[d] = qs[t * 65 + d];
        float m = -1e30f;
        for (int a = 0; a < AGENT; a++) {
            float s = 0.f;
#pragma unroll
            for (int d = 0; d < 64; d++) s += qr[d] * ah_s[a * 64 + d];
            s += bsm[t * AGENT + a];
            bsm[t * AGENT + a] = s;
            m = fmaxf(m, s);
        }
        float sum = 0.f;
        for (int a = 0; a < AGENT; a++) {
            float p = __expf(bsm[t * AGENT + a] - m);
            bsm[t * AGENT + a] = p;
            sum += p;
        }
        float inv = 1.f / sum;
        for (int d = 0; d < 64; d++) {
            float o = 0.f;
            for (int a = 0; a < AGENT; a++) o += bsm[t * AGENT + a] * av_s[a * 64 + d];
            qs[t * 65 + d] = o * inv;
        }
    }
    __syncthreads();
    for (int idx = t; idx < 128 * 64; idx += 128) {
        int r = idx >> 6, dd = idx & 63;
        int nn = n0 + r;
        if (nn < NTOK)
            g_attnout[((size_t)b * NTOK + nn) * DIM + h * HD + dd] = qs[r * 65 + dd];
    }
}

// ---------------- depthwise 3x3 conv on v + attn residual -> bf16 hi/lo ----------------
__global__ __launch_bounds__(256) void k_dwc(const float* __restrict__ w_dwc,
                                             const float* __restrict__ b_dwc) {
    int y = blockIdx.x, b = blockIdx.y, t = threadIdx.x;
    int c = (t & 127) * 4;
    int xh = t >> 7;
    float wreg[4][9], bd[4];
#pragma unroll
    for (int j = 0; j < 4; j++) {
        bd[j] = b_dwc[c + j];
#pragma unroll
        for (int kk = 0; kk < 9; kk++) wreg[j][kk] = w_dwc[(c + j) * 9 + kk];
    }
    for (int x = xh; x < WWID; x += 2) {
        float a0 = bd[0], a1 = bd[1], a2 = bd[2], a3 = bd[3];
#pragma unroll
        for (int ky = 0; ky < 3; ky++) {
            int yy = y + ky - 1;
            if ((unsigned)yy >= HH) continue;
#pragma unroll
            for (int kx = 0; kx < 3; kx++) {
                int xx = x + kx - 1;
                if ((unsigned)xx >= WWID) continue;
                const float4 v = *(const float4*)&g_qkv[
                    (((size_t)b * NTOK) + yy * WWID + xx) * 1536 + 1024 + c];
                int kk = ky * 3 + kx;
                a0 += v.x * wreg[0][kk];
                a1 += v.y * wreg[1][kk];
                a2 += v.z * wreg[2][kk];
                a3 += v.w * wreg[3][kk];
            }
        }
        size_t m = ((size_t)b * NTOK) + y * WWID + x;
        const float4 cur = *(const float4*)&g_attnout[m * DIM + c];
        a0 += cur.x; a1 += cur.y; a2 += cur.z; a3 += cur.w;
        u32 h0 = f2bf(a0), h1 = f2bf(a1), h2 = f2bf(a2), h3 = f2bf(a3);
        u32* dh = (u32*)&g_aohl[m * 1024 + c];
        dh[0] = h0 | (h1 << 16);
        dh[1] = h2 | (h3 << 16);
        u32* dl = (u32*)&g_aohl[m * 1024 + 512 + c];
        dl[0] = pack2(a0 - bf2f(h0), a1 - bf2f(h1));
        dl[1] = pack2(a2 - bf2f(h2), a3 - bf2f(h3));
    }
}

// ---------------- launcher ----------------
extern "C" void kernel_launch(void* const* d_in, const int* in_sizes, int n_in,
                              void* d_out, int out_size) {
    const float* x      = (const float*)d_in[0];
    const float* w_qkv  = (const float*)d_in[1];
    const float* w_proj = (const float*)d_in[2];
    const float* b_proj = (const float*)d_in[3];
    const float* w_dwc  = (const float*)d_in[4];
    const float* b_dwc  = (const float*)d_in[5];
    const float* an     = (const float*)d_in[6];
    const float* na     = (const float*)d_in[7];
    const float* ahb    = (const float*)d_in[8];
    const float* awb    = (const float*)d_in[9];
    const float* hab    = (const float*)d_in[10];
    const float* wab    = (const float*)d_in[11];
    const float* cab    = (const float*)d_in[12];
    float* out = (float*)d_out;

    void *p_qkv = 0, *p_xhl = 0, *p_aohl = 0, *p_wq = 0, *p_wp = 0;
    cudaGetSymbolAddress(&p_qkv, g_qkv);
    cudaGetSymbolAddress(&p_xhl, g_xhl);
    cudaGetSymbolAddress(&p_aohl, g_aohl);
    cudaGetSymbolAddress(&p_wq, g_wqkvhl);
    cudaGetSymbolAddress(&p_wp, g_wprojhl);
    float* qkv = (float*)p_qkv;
    unsigned short* xhl = (unsigned short*)p_xhl;
    unsigned short* aohl = (unsigned short*)p_aohl;
    unsigned short* wqhl = (unsigned short*)p_wq;
    unsigned short* wphl = (unsigned short*)p_wp;

    cudaFuncSetAttribute(k_gemm, cudaFuncAttributeMaxDynamicSharedMemorySize, GSMEM_TOTAL);
    cudaFuncSetAttribute(k_s1, cudaFuncAttributeMaxDynamicSharedMemorySize,
                         S1_SMEM_FLOATS * (int)sizeof(float));
    cudaFuncSetAttribute(k_s2, cudaFuncAttributeMaxDynamicSharedMemorySize,
                         S2_SMEM_FLOATS * (int)sizeof(float));

    const int M = BB * NTOK;   // 50176

    // bf16 hi/lo conversions
    k_cvt<<<(M * 128 + 255) / 256, 256>>>(x, xhl, M * 128);
    k_cvt<<<(1536 * 128 + 255) / 256, 256>>>(w_qkv, wqhl, 1536 * 128);
    k_cvt<<<(512 * 128 + 255) / 256, 256>>>(w_proj, wphl, 512 * 128);

    // QKV GEMM: (50176,512)x(1536,512)^T -> (50176,1536) via HMMA bf16x3
    k_gemm<<<dim3(1536 / 128, M / 128), 256, GSMEM_TOTAL>>>(xhl, wqhl, 0, qkv, 1536);

    // bias tables (b-independent)
    k_pb<<<HEADS * AGENT, WW2>>>(an, ahb, awb);
    k_ab<<<(HEADS * 197 * AGENT + 255) / 256, 256>>>(na, hab, wab, cab);
    k_bias1<<<(HEADS * AGENT * NTOK + 255) / 256, 256>>>();
    k_bias2<<<(HEADS * NTOK * AGENT + 255) / 256, 256>>>();

    // agent pooling
    k_agent<<<BB * AGENT, DIM>>>();

    // stage 1: fused flash attention, split-KV + merge
    k_s1<<<dim3(S1SPLIT, HEADS, BB), 256, S1_SMEM_FLOATS * (int)sizeof(float)>>>();
    k_s1merge<<<BB * HEADS, 256>>>();

    // stage 2 (writes g_attnout)
    k_s2<<<dim3(25, HEADS, BB), 128, S2_SMEM_FLOATS * (int)sizeof(float)>>>();

    // depthwise conv residual, fused fp32->bf16 split (writes g_aohl)
    k_dwc<<<dim3(HH, BB), 256>>>(w_dwc, b_dwc);

    // projection GEMM with bias -> final fp32 output
    k_gemm<<<dim3(512 / 128, M / 128), 256, GSMEM_TOTAL>>>(aohl, wphl, b_proj, out, 512);
}

// round 11
// speedup vs baseline: 1.6532x; 1.1145x over previous
#include <cuda_runtime.h>
#include <math.h>

typedef unsigned int u32;
typedef unsigned long long u64;

// ---------------- problem constants ----------------
#define BB    16
#define NTOK  3136
#define DIM   512
#define HH    56
#define WWID  56
#define HEADS 8
#define HD    64
#define AGENT 49
#define WIN   14
#define WW2   196   // 14*14
#define S1SPLIT 5

// ---------------- scratch (device globals; no allocation allowed) ----------------
__device__ float g_qkv[(size_t)BB * NTOK * 3 * DIM];            // fp32 qkv
__device__ float g_attnout[(size_t)BB * NTOK * DIM];            // attention only
__device__ unsigned short g_xhl[(size_t)BB * NTOK * 2 * DIM];   // x hi/lo bf16 bits
__device__ unsigned short g_aohl[(size_t)BB * NTOK * 2 * DIM];  // attn+dwc hi/lo bf16 bits
__device__ unsigned short g_wqkvhl[3 * DIM * 2 * DIM];
__device__ unsigned short g_wprojhl[DIM * 2 * DIM];
__device__ float g_agent[BB * AGENT * DIM];
__device__ float g_agentv[BB * HEADS * AGENT * HD];
__device__ float g_pacc[(size_t)BB * HEADS * S1SPLIT * AGENT * HD];
__device__ float g_pm[BB * HEADS * S1SPLIT * AGENT];
__device__ float g_ps[BB * HEADS * S1SPLIT * AGENT];
__device__ float g_pb[HEADS * AGENT * WW2];
__device__ float g_ab[HEADS * 197 * AGENT];
__device__ float g_bias1[HEADS * AGENT * NTOK];
__device__ float g_bias2[HEADS * NTOK * AGENT];

// ---------------- manual bf16 helpers (no cuda_bf16 types) ----------------
__device__ __forceinline__ u32 f2bf(float f) {           // round-to-nearest-even
    u32 u = __float_as_uint(f);
    return (u + 0x7fffu + ((u >> 16) & 1u)) >> 16;
}
__device__ __forceinline__ float bf2f(u32 b) { return __uint_as_float(b << 16); }
__device__ __forceinline__ u32 pack2(float lo, float hi) {
    return f2bf(lo) | (f2bf(hi) << 16);
}

// ---------------- bilinear helpers (jax half-pixel + clamp semantics) ----------------
__device__ __forceinline__ float bil7(const float* __restrict__ A, int wy, int wx) {
    float sy = (wy + 0.5f) * 0.5f - 0.5f;
    float sx = (wx + 0.5f) * 0.5f - 0.5f;
    sy = fminf(fmaxf(sy, 0.f), 6.f);
    sx = fminf(fmaxf(sx, 0.f), 6.f);
    int y0 = (int)sy; float fy = sy - y0; int y1 = min(y0 + 1, 6);
    int x0 = (int)sx; float fx = sx - x0; int x1 = min(x0 + 1, 6);
    float v00 = A[y0 * 7 + x0], v01 = A[y0 * 7 + x1];
    float v10 = A[y1 * 7 + x0], v11 = A[y1 * 7 + x1];
    return (1.f - fy) * ((1.f - fx) * v00 + fx * v01) +
           fy * ((1.f - fx) * v10 + fx * v11);
}

__global__ void k_pb(const float* __restrict__ an, const float* __restrict__ ahb,
                     const float* __restrict__ awb) {
    int ha = blockIdx.x;
    int t = threadIdx.x;
    if (t >= WW2) return;
    int wy = t / WIN, wx = t % WIN;
    float v = bil7(an + ha * 49, wy, wx);
    g_pb[ha * WW2 + t] = v + ahb[ha * WIN + wy] + awb[ha * WIN + wx];
}

__global__ void k_ab(const float* __restrict__ na, const float* __restrict__ hab,
                     const float* __restrict__ wab, const float* __restrict__ cab) {
    int tid = blockIdx.x * blockDim.x + threadIdx.x;
    int total = HEADS * 197 * AGENT;
    if (tid >= total) return;
    int h = tid / (197 * AGENT);
    int r = (tid / AGENT) % 197;
    int a = tid % AGENT;
    float v;
    if (r == 0) {
        v = cab[h * AGENT + a];
    } else {
        int t = r - 1;
        int wy = t / WIN, wx = t % WIN;
        v = bil7(na + (h * AGENT + a) * 49, wy, wx)
          + hab[(h * WIN + wy) * AGENT + a]
          + wab[(h * WIN + wx) * AGENT + a];
    }
    g_ab[(h * 197 + r) * AGENT + a] = v;
}

__global__ void k_bias1() {
    int tid = blockIdx.x * blockDim.x + threadIdx.x;
    int total = HEADS * AGENT * NTOK;
    if (tid >= total) return;
    int ha = tid / NTOK;
    int n = tid % NTOK;
    float s = (n + 0.5f) * 0.0625f - 0.5f;
    s = fminf(fmaxf(s, 0.f), 195.f);
    int t0 = (int)s; float f = s - t0; int t1 = min(t0 + 1, 195);
    g_bias1[tid] = g_pb[ha * WW2 + t0] * (1.f - f) + g_pb[ha * WW2 + t1] * f;
}

__global__ void k_bias2() {
    int tid = blockIdx.x * blockDim.x + threadIdx.x;
    int total = HEADS * NTOK * AGENT;
    if (tid >= total) return;
    int h = tid / (NTOK * AGENT);
    int rem = tid % (NTOK * AGENT);
    int n = rem / AGENT;
    int a = rem % AGENT;
    float s = (n + 0.5f) * (197.0f / 3136.0f) - 0.5f;
    s = fminf(fmaxf(s, 0.f), 196.f);
    int r0 = (int)s; float f = s - r0; int r1 = min(r0 + 1, 196);
    g_bias2[tid] = g_ab[(h * 197 + r0) * AGENT + a] * (1.f - f)
                 + g_ab[(h * 197 + r1) * AGENT + a] * f;
}

// ---------------- fp32 -> bf16 hi/lo split conversion ----------------
// src: [M, 512] fp32 row-major. dst: [M, 1024] bf16-bits, row = [hi(512) | lo(512)]
__global__ void k_cvt(const float* __restrict__ src, unsigned short* __restrict__ dst,
                      int total4) {
    int idx = blockIdx.x * 256 + threadIdx.x;
    if (idx >= total4) return;
    int m = idx >> 7;            // /128  (512/4 groups per row)
    int k4 = (idx & 127) << 2;
    float4 v = *(const float4*)(src + (size_t)m * 512 + k4);
    u32 h0 = f2bf(v.x), h1 = f2bf(v.y), h2 = f2bf(v.z), h3 = f2bf(v.w);
    float r0 = v.x - bf2f(h0), r1 = v.y - bf2f(h1);
    float r2 = v.z - bf2f(h2), r3 = v.w - bf2f(h3);
    u32* dh = (u32*)(dst + (size_t)m * 1024 + k4);
    dh[0] = h0 | (h1 << 16);
    dh[1] = h2 | (h3 << 16);
    u32* dl = (u32*)(dst + (size_t)m * 1024 + 512 + k4);
    dl[0] = pack2(r0, r1);
    dl[1] = pack2(r2, r3);
}

// ================= bf16x3 GEMM via mma.sync (HMMA, base sm_103-safe) =================
// C[M,N] = A[M,512]*B[N,512]^T (+bias). A/B rows: 1024 bf16 = [hi(512)|lo(512)].
// CTA tile 128x128, 256 thr (8 warps 4x2, warp tile 32x64), BK=32,
// 2-stage cp.async double buffer (80KB) -> 2 CTAs/SM (RF-capped at 2 anyway).
// smem stage: Ah/Al/Bh/Bl planes, each 128 rows x 80B (32 halves + 8 pad).

#define G_PLANE 10240                       // 128 * 80 bytes
#define G_STAGE (4 * G_PLANE)               // 40960
#define G_NSTG  2
#define GSMEM_TOTAL (G_NSTG * G_STAGE)      // 81920

static __device__ __forceinline__ u32 smem_u32(const void* p) {
    u32 a;
    asm("{ .reg .u64 t; cvta.to.shared.u64 t, %1; cvt.u32.u64 %0, t; }" : "=r"(a) : "l"(p));
    return a;
}
static __device__ __forceinline__ void cpa16(u32 s, const void* g) {
    asm volatile("cp.async.cg.shared.global [%0], [%1], 16;" :: "r"(s), "l"(g) : "memory");
}
static __device__ __forceinline__ void ldsm4(u32* r, u32 addr) {
    asm volatile("ldmatrix.sync.aligned.m8n8.x4.shared.b16 {%0,%1,%2,%3}, [%4];"
        : "=r"(r[0]), "=r"(r[1]), "=r"(r[2]), "=r"(r[3]) : "r"(addr));
}
static __device__ __forceinline__ void mma16816(float* c, const u32* a, const u32* b) {
    asm volatile("mma.sync.aligned.m16n8k16.row.col.f32.bf16.bf16.f32 "
        "{%0,%1,%2,%3}, {%4,%5,%6,%7}, {%8,%9}, {%0,%1,%2,%3};"
        : "+f"(c[0]), "+f"(c[1]), "+f"(c[2]), "+f"(c[3])
        : "r"(a[0]), "r"(a[1]), "r"(a[2]), "r"(a[3]), "r"(b[0]), "r"(b[1]));
}

// load K-chunk c (32 halves per plane) for A rows m0..+128 and B rows n0..+128
static __device__ __forceinline__ void load_chunk(
    u32 buf, const unsigned short* __restrict__ A, const unsigned short* __restrict__ B,
    int m0, int n0, int c, int tid)
{
    for (int idx = tid; idx < 512; idx += 256) {
        int r = idx >> 2, seg = idx & 3;
        const unsigned short* g = A + (size_t)(m0 + r) * 1024 + c * 32 + seg * 8;
        u32 d = buf + r * 80 + seg * 16;
        cpa16(d, g);                 // A hi
        cpa16(d + G_PLANE, g + 512); // A lo
    }
    for (int idx = tid; idx < 512; idx += 256) {
        int r = idx >> 2, seg = idx & 3;
        const unsigned short* g = B + (size_t)(n0 + r) * 1024 + c * 32 + seg * 8;
        u32 d = buf + 2 * G_PLANE + r * 80 + seg * 16;
        cpa16(d, g);                 // B hi
        cpa16(d + G_PLANE, g + 512); // B lo
    }
    asm volatile("cp.async.commit_group;" ::: "memory");
}

__global__ __launch_bounds__(256, 2)
void k_gemm(const unsigned short* __restrict__ Ahl, const unsigned short* __restrict__ Bhl,
            const float* __restrict__ bias, float* __restrict__ C, int ldc)
{
    extern __shared__ char smem[];
    const u32 sb = smem_u32(smem);
    const int tid = threadIdx.x;
    const int wid = tid >> 5, lane = tid & 31;
    const int wm = wid >> 1, wn = wid & 1;       // 4 x 2 warp grid
    const int m0 = blockIdx.y * 128;
    const int n0 = blockIdx.x * 128;
    const int row_a = lane & 15;                 // ldmatrix row within 16
    const int kseg = lane >> 4;                  // 0/1 -> k halves 0-7 / 8-15

    float acc[2][8][4];
#pragma unroll
    for (int mt = 0; mt < 2; mt++)
#pragma unroll
        for (int j = 0; j < 8; j++)
#pragma unroll
            for (int q = 0; q < 4; q++) acc[mt][j][q] = 0.f;

    // prologue: fill both buffers
    load_chunk(sb + 0 * G_STAGE, Ahl, Bhl, m0, n0, 0, tid);
    load_chunk(sb + 1 * G_STAGE, Ahl, Bhl, m0, n0, 1, tid);

    // per-warp fragment offsets within a stage (buf-independent)
    const u32 aoff0 = (u32)((wm * 32 + row_a) * 80) + (u32)(kseg * 16);
    const u32 boff0 = 2 * G_PLANE + (u32)((wn * 64 + row_a) * 80) + (u32)(kseg * 16);

    for (int c = 0; c < 16; c++) {
        if (c < 15) asm volatile("cp.async.wait_group 1;" ::: "memory");
        else        asm volatile("cp.async.wait_group 0;" ::: "memory");
        __syncthreads();

        const u32 buf = sb + (c & 1) * G_STAGE;
#pragma unroll
        for (int ks = 0; ks < 2; ks++) {
            const u32 kb = ks * 32;
            u32 ah[2][4], al[2][4], bh[8][2], bl[8][2];
#pragma unroll
            for (int mt = 0; mt < 2; mt++) {
                u32 ad = buf + aoff0 + mt * (16 * 80) + kb;
                ldsm4(ah[mt], ad);
                ldsm4(al[mt], ad + G_PLANE);
            }
#pragma unroll
            for (int nt = 0; nt < 4; nt++) {
                u32 bd = buf + boff0 + nt * (16 * 80) + kb;
                u32 r[4];
                ldsm4(r, bd);
                bh[2 * nt][0] = r[0]; bh[2 * nt + 1][0] = r[1];
                bh[2 * nt][1] = r[2]; bh[2 * nt + 1][1] = r[3];
                ldsm4(r, bd + G_PLANE);
                bl[2 * nt][0] = r[0]; bl[2 * nt + 1][0] = r[1];
                bl[2 * nt][1] = r[2]; bl[2 * nt + 1][1] = r[3];
            }
#pragma unroll
            for (int mt = 0; mt < 2; mt++)
#pragma unroll
                for (int j = 0; j < 8; j++) {
                    mma16816(acc[mt][j], ah[mt], bh[j]);
                    mma16816(acc[mt][j], ah[mt], bl[j]);
                    mma16816(acc[mt][j], al[mt], bh[j]);
                }
        }
        __syncthreads();
        if (c + 2 < 16)
            load_chunk(buf, Ahl, Bhl, m0, n0, c + 2, tid);
    }

    // epilogue: direct float2 stores (+bias)
    const int gq = lane >> 2, tg = lane & 3;
#pragma unroll
    for (int mt = 0; mt < 2; mt++) {
        int row = m0 + wm * 32 + mt * 16 + gq;
#pragma unroll
        for (int j = 0; j < 8; j++) {
            int col = n0 + wn * 64 + j * 8 + tg * 2;
            float b0 = 0.f, b1 = 0.f;
            if (bias) { b0 = bias[col]; b1 = bias[col + 1]; }
            float2 v0 = make_float2(acc[mt][j][0] + b0, acc[mt][j][1] + b1);
            float2 v1 = make_float2(acc[mt][j][2] + b0, acc[mt][j][3] + b1);
            *(float2*)&C[(size_t)row * ldc + col] = v0;
            *(float2*)&C[(size_t)(row + 8) * ldc + col] = v1;
        }
    }
}

// ---------------- agent pooling: exact 8x8 block mean of q ----------------
__global__ void k_agent() {
    int b = blockIdx.x / AGENT;
    int a = blockIdx.x % AGENT;
    int py = a / 7, px = a % 7;
    int c = threadIdx.x;
    float s = 0.f;
#pragma unroll 4
    for (int dy = 0; dy < 8; dy++)
        for (int dx = 0; dx < 8; dx++) {
            int n = (py * 8 + dy) * WWID + px * 8 + dx;
            s += g_qkv[((size_t)b * NTOK + n) * 1536 + c];
        }
    g_agent[((size_t)b * AGENT + a) * DIM + c] = s * (1.f / 64.f);
}

// ---------------- stage 1 (fused flash, split-KV) ----------------
#define S1_SMEM_FLOATS (3136 + 128 * 65 + 49 * 128 + 192)
__global__ __launch_bounds__(256) void k_s1() {
    extern __shared__ float sm[];
    float* ah_s = sm;
    float* ks   = sm + 3136;
    float* sc   = sm + 3136 + 8320;
    float* mrow = sc + 6272;
    float* srow = mrow + 64;
    float* frow = srow + 64;
    int split = blockIdx.x, h = blockIdx.y, b = blockIdx.z;
    int t = threadIdx.x, warp = t >> 5, lane = t & 31;
    int g = t >> 6, d = t & 63;
    const int base = (g == 0) ? 0 : (13 + 12 * (g - 1));
    const int cnt = (g == 0) ? 13 : 12;

    for (int idx = t; idx < AGENT * HD; idx += 256) {
        int a = idx >> 6, dd = idx & 63;
        ah_s[idx] = g_agent[((size_t)b * AGENT + a) * DIM + h * HD + dd] * 0.125f;
    }
    if (t < AGENT) { mrow[t] = -1e30f; srow[t] = 0.f; }
    float acc[13];
#pragma unroll
    for (int i = 0; i < 13; i++) acc[i] = 0.f;
    __syncthreads();

    for (int c = 0; c < 5; c++) {
        int n0 = (split * 5 + c) * 128;
        int nc = min(128, NTOK - n0);

        for (int idx = t; idx < 128 * 64; idx += 256) {
            int r = idx >> 6, dd = idx & 63;
            ks[r * 65 + dd] = (r < nc)
                ? g_qkv[((size_t)b * NTOK + n0 + r) * 1536 + DIM + h * HD + dd] : 0.f;
        }
        __syncthreads();

        for (int idx = t; idx < AGENT * 128; idx += 256) {
            int a = idx >> 7, nl = idx & 127;
            float sv;
            if (nl < nc) {
                float s = 0.f;
#pragma unroll
                for (int dd = 0; dd < 64; dd++) s += ks[nl * 65 + dd] * ah_s[a * 64 + dd];
                sv = s + g_bias1[(h * AGENT + a) * NTOK + n0 + nl];
            } else sv = -1e30f;
            sc[idx] = sv;
        }
        __syncthreads();

        for (int a = warp; a < AGENT; a += 8) {
            float cm = -1e30f;
            for (int i = lane; i < 128; i += 32) cm = fmaxf(cm, sc[a * 128 + i]);
            for (int off = 16; off; off >>= 1)
                cm = fmaxf(cm, __shfl_xor_sync(0xffffffffu, cm, off));
            float mo = mrow[a];
            float nm = fmaxf(mo, cm);
            float f = __expf(mo - nm);
            float rs = 0.f;
            for (int i = lane; i < 128; i += 32) {
                float p = __expf(sc[a * 128 + i] - nm);
                sc[a * 128 + i] = p;
                rs += p;
            }
            for (int off = 16; off; off >>= 1)
                rs += __shfl_xor_sync(0xffffffffu, rs, off);
            if (lane == 0) { mrow[a] = nm; srow[a] = srow[a] * f + rs; frow[a] = f; }
        }
        __syncthreads();

#pragma unroll
        for (int i = 0; i < 13; i++)
            if (i < cnt) acc[i] *= frow[base + i];
        for (int nl = 0; nl < nc; nl++) {
            float vv = g_qkv[((size_t)b * NTOK + n0 + nl) * 1536 + 1024 + h * HD + d];
#pragma unroll
            for (int i = 0; i < 13; i++)
                if (i < cnt) acc[i] += sc[(base + i) * 128 + nl] * vv;
        }
        __syncthreads();
    }

    size_t pb_ = (((size_t)(b * HEADS + h)) * S1SPLIT + split) * AGENT;
#pragma unroll
    for (int i = 0; i < 13; i++)
        if (i < cnt) g_pacc[(pb_ + base + i) * HD + d] = acc[i];
    if (t < AGENT) { g_pm[pb_ + t] = mrow[t]; g_ps[pb_ + t] = srow[t]; }
}

__global__ __launch_bounds__(256) void k_s1merge() {
    int bh = blockIdx.x;
    int t = threadIdx.x;
    for (int idx = t; idx < AGENT * HD; idx += 256) {
        int a = idx >> 6, d = idx & 63;
        size_t p0 = ((size_t)bh * S1SPLIT) * AGENT + a;
        float nm = -1e30f;
        for (int s = 0; s < S1SPLIT; s++) nm = fmaxf(nm, g_pm[p0 + s * AGENT]);
        float S = 0.f, A = 0.f;
        for (int s = 0; s < S1SPLIT; s++) {
            float w = __expf(g_pm[p0 + s * AGENT] - nm);
            S += g_ps[p0 + s * AGENT] * w;
            A += g_pacc[(p0 + s * AGENT) * HD + d] * w;
        }
        g_agentv[((size_t)bh * AGENT + a) * HD + d] = A / S;
    }
}

// ---------------- stage 2: q->agent attention ----------------
#define S2_SMEM_FLOATS (3136 + 3136 + 128 * 65 + 128 * 49)
__global__ __launch_bounds__(128) void k_s2() {
    extern __shared__ float sm[];
    float* ah_s = sm;
    float* av_s = sm + 3136;
    float* qs   = sm + 6272;
    float* bsm  = sm + 6272 + 8320;
    int chunk = blockIdx.x, h = blockIdx.y, b = blockIdx.z;
    int t = threadIdx.x;
    int n0 = chunk * 128;

    for (int idx = t; idx < AGENT * HD; idx += 128) {
        int a = idx >> 6, d = idx & 63;
        ah_s[idx] = g_agent[((size_t)b * AGENT + a) * DIM + h * HD + d] * 0.125f;
        av_s[idx] = g_agentv[((size_t)(b * HEADS + h)) * AGENT * HD + idx];
    }
    for (int idx = t; idx < 128 * 64; idx += 128) {
        int r = idx >> 6, d = idx & 63;
        int n = n0 + r;
        qs[r * 65 + d] = (n < NTOK)
            ? g_qkv[((size_t)b * NTOK + n) * 1536 + h * HD + d] : 0.f;
    }
    for (int idx = t; idx < 128 * AGENT; idx += 128) {
        if (n0 * AGENT + idx < NTOK * AGENT)
            bsm[idx] = g_bias2[(size_t)h * NTOK * AGENT + (size_t)n0 * AGENT + idx];
    }
    __syncthreads();

    int n = n0 + t;
    if (n < NTOK) {
        float qr[64];
#pragma unroll
        for (int d = 0; d < 64; d++) qr[d] = qs[t * 65 + d];
        float m = -1e30f;
        for (int a = 0; a < AGENT; a++) {
            float s = 0.f;
#pragma unroll
            for (int d = 0; d < 64; d++) s += qr[d] * ah_s[a * 64 + d];
            s += bsm[t * AGENT + a];
            bsm[t * AGENT + a] = s;
            m = fmaxf(m, s);
        }
        float sum = 0.f;
        for (int a = 0; a < AGENT; a++) {
            float p = __expf(bsm[t * AGENT + a] - m);
            bsm[t * AGENT + a] = p;
            sum += p;
        }
        float inv = 1.f / sum;
        for (int d = 0; d < 64; d++) {
            float o = 0.f;
            for (int a = 0; a < AGENT; a++) o += bsm[t * AGENT + a] * av_s[a * 64 + d];
            qs[t * 65 + d] = o * inv;
        }
    }
    __syncthreads();
    for (int idx = t; idx < 128 * 64; idx += 128) {
        int r = idx >> 6, dd = idx & 63;
        int nn = n0 + r;
        if (nn < NTOK)
            g_attnout[((size_t)b * NTOK + nn) * DIM + h * HD + dd] = qs[r * 65 + dd];
    }
}

// ---------------- depthwise 3x3 conv on v + attn residual -> bf16 hi/lo ----------------
__global__ __launch_bounds__(256) void k_dwc(const float* __restrict__ w_dwc,
                                             const float* __restrict__ b_dwc) {
    int y = blockIdx.x, b = blockIdx.y, t = threadIdx.x;
    int c = (t & 127) * 4;
    int xh = t >> 7;
    float wreg[4][9], bd[4];
#pragma unroll
    for (int j = 0; j < 4; j++) {
        bd[j] = b_dwc[c + j];
#pragma unroll
        for (int kk = 0; kk < 9; kk++) wreg[j][kk] = w_dwc[(c + j) * 9 + kk];
    }
    for (int x = xh; x < WWID; x += 2) {
        float a0 = bd[0], a1 = bd[1], a2 = bd[2], a3 = bd[3];
#pragma unroll
        for (int ky = 0; ky < 3; ky++) {
            int yy = y + ky - 1;
            if ((unsigned)yy >= HH) continue;
#pragma unroll
            for (int kx = 0; kx < 3; kx++) {
                int xx = x + kx - 1;
                if ((unsigned)xx >= WWID) continue;
                const float4 v = *(const float4*)&g_qkv[
                    (((size_t)b * NTOK) + yy * WWID + xx) * 1536 + 1024 + c];
                int kk = ky * 3 + kx;
                a0 += v.x * wreg[0][kk];
                a1 += v.y * wreg[1][kk];
                a2 += v.z * wreg[2][kk];
                a3 += v.w * wreg[3][kk];
            }
        }
        size_t m = ((size_t)b * NTOK) + y * WWID + x;
        const float4 cur = *(const float4*)&g_attnout[m * DIM + c];
        a0 += cur.x; a1 += cur.y; a2 += cur.z; a3 += cur.w;
        u32 h0 = f2bf(a0), h1 = f2bf(a1), h2 = f2bf(a2), h3 = f2bf(a3);
        u32* dh = (u32*)&g_aohl[m * 1024 + c];
        dh[0] = h0 | (h1 << 16);
        dh[1] = h2 | (h3 << 16);
        u32* dl = (u32*)&g_aohl[m * 1024 + 512 + c];
        dl[0] = pack2(a0 - bf2f(h0), a1 - bf2f(h1));
        dl[1] = pack2(a2 - bf2f(h2), a3 - bf2f(h3));
    }
}

// ---------------- launcher ----------------
extern "C" void kernel_launch(void* const* d_in, const int* in_sizes, int n_in,
                              void* d_out, int out_size) {
    const float* x      = (const float*)d_in[0];
    const float* w_qkv  = (const float*)d_in[1];
    const float* w_proj = (const float*)d_in[2];
    const float* b_proj = (const float*)d_in[3];
    const float* w_dwc  = (const float*)d_in[4];
    const float* b_dwc  = (const float*)d_in[5];
    const float* an     = (const float*)d_in[6];
    const float* na     = (const float*)d_in[7];
    const float* ahb    = (const float*)d_in[8];
    const float* awb    = (const float*)d_in[9];
    const float* hab    = (const float*)d_in[10];
    const float* wab    = (const float*)d_in[11];
    const float* cab    = (const float*)d_in[12];
    float* out = (float*)d_out;

    void *p_qkv = 0, *p_xhl = 0, *p_aohl = 0, *p_wq = 0, *p_wp = 0;
    cudaGetSymbolAddress(&p_qkv, g_qkv);
    cudaGetSymbolAddress(&p_xhl, g_xhl);
    cudaGetSymbolAddress(&p_aohl, g_aohl);
    cudaGetSymbolAddress(&p_wq, g_wqkvhl);
    cudaGetSymbolAddress(&p_wp, g_wprojhl);
    float* qkv = (float*)p_qkv;
    unsigned short* xhl = (unsigned short*)p_xhl;
    unsigned short* aohl = (unsigned short*)p_aohl;
    unsigned short* wqhl = (unsigned short*)p_wq;
    unsigned short* wphl = (unsigned short*)p_wp;

    cudaFuncSetAttribute(k_gemm, cudaFuncAttributeMaxDynamicSharedMemorySize, GSMEM_TOTAL);
    cudaFuncSetAttribute(k_s1, cudaFuncAttributeMaxDynamicSharedMemorySize,
                         S1_SMEM_FLOATS * (int)sizeof(float));
    cudaFuncSetAttribute(k_s2, cudaFuncAttributeMaxDynamicSharedMemorySize,
                         S2_SMEM_FLOATS * (int)sizeof(float));

    const int M = BB * NTOK;   // 50176

    // bf16 hi/lo conversions
    k_cvt<<<(M * 128 + 255) / 256, 256>>>(x, xhl, M * 128);
    k_cvt<<<(1536 * 128 + 255) / 256, 256>>>(w_qkv, wqhl, 1536 * 128);
    k_cvt<<<(512 * 128 + 255) / 256, 256>>>(w_proj, wphl, 512 * 128);

    // QKV GEMM: (50176,512)x(1536,512)^T -> (50176,1536) via HMMA bf16x3
    k_gemm<<<dim3(1536 / 128, M / 128), 256, GSMEM_TOTAL>>>(xhl, wqhl, 0, qkv, 1536);

    // bias tables (b-independent)
    k_pb<<<HEADS * AGENT, WW2>>>(an, ahb, awb);
    k_ab<<<(HEADS * 197 * AGENT + 255) / 256, 256>>>(na, hab, wab, cab);
    k_bias1<<<(HEADS * AGENT * NTOK + 255) / 256, 256>>>();
    k_bias2<<<(HEADS * NTOK * AGENT + 255) / 256, 256>>>();

    // agent pooling
    k_agent<<<BB * AGENT, DIM>>>();

    // stage 1: fused flash attention, split-KV + merge
    k_s1<<<dim3(S1SPLIT, HEADS, BB), 256, S1_SMEM_FLOATS * (int)sizeof(float)>>>();
    k_s1merge<<<BB * HEADS, 256>>>();

    // stage 2 (writes g_attnout)
    k_s2<<<dim3(25, HEADS, BB), 128, S2_SMEM_FLOATS * (int)sizeof(float)>>>();

    // depthwise conv residual, fused fp32->bf16 split (writes g_aohl)
    k_dwc<<<dim3(HH, BB), 256>>>(w_dwc, b_dwc);

    // projection GEMM with bias -> final fp32 output
    k_gemm<<<dim3(512 / 128, M / 128), 256, GSMEM_TOTAL>>>(aohl, wphl, b_proj, out, 512);
}

// round 12
// speedup vs baseline: 1.7720x; 1.0719x over previous
#include <cuda_runtime.h>
#include <math.h>

typedef unsigned int u32;
typedef unsigned long long u64;

// ---------------- problem constants ----------------
#define BB    16
#define NTOK  3136
#define DIM   512
#define HH    56
#define WWID  56
#define HEADS 8
#define HD    64
#define AGENT 49
#define WIN   14
#define WW2   196   // 14*14
#define S1SPLIT 5

// ---------------- packed f32x2 helpers (B300 FFMA2) ----------------
#define FMA2(c, a, b) asm("fma.rn.f32x2 %0, %1, %2, %0;" : "+l"(c) : "l"(a), "l"(b))
#define PACK2F(out, lo, hi) asm("mov.b64 %0, {%1, %2};" : "=l"(out) : "f"(lo), "f"(hi))
#define UNPACK2F(lo, hi, in) asm("mov.b64 {%0, %1}, %2;" : "=f"(lo), "=f"(hi) : "l"(in))

// ---------------- scratch (device globals; no allocation allowed) ----------------
__device__ float g_qkv[(size_t)BB * NTOK * 3 * DIM];            // fp32 qkv
__device__ float g_attnout[(size_t)BB * NTOK * DIM];            // attention only
__device__ unsigned short g_xhl[(size_t)BB * NTOK * 2 * DIM];   // x hi/lo bf16 bits
__device__ unsigned short g_aohl[(size_t)BB * NTOK * 2 * DIM];  // attn+dwc hi/lo bf16 bits
__device__ unsigned short g_wqkvhl[3 * DIM * 2 * DIM];
__device__ unsigned short g_wprojhl[DIM * 2 * DIM];
__device__ float g_agent[BB * AGENT * DIM];
__device__ float g_agentv[BB * HEADS * AGENT * HD];
__device__ float g_pacc[(size_t)BB * HEADS * S1SPLIT * AGENT * HD];
__device__ float g_pm[BB * HEADS * S1SPLIT * AGENT];
__device__ float g_ps[BB * HEADS * S1SPLIT * AGENT];
__device__ float g_pb[HEADS * AGENT * WW2];
__device__ float g_ab[HEADS * 197 * AGENT];
__device__ float g_bias1[HEADS * AGENT * NTOK];
__device__ float g_bias2[HEADS * NTOK * AGENT];

// ---------------- manual bf16 helpers (no cuda_bf16 types) ----------------
__device__ __forceinline__ u32 f2bf(float f) {           // round-to-nearest-even
    u32 u = __float_as_uint(f);
    return (u + 0x7fffu + ((u >> 16) & 1u)) >> 16;
}
__device__ __forceinline__ float bf2f(u32 b) { return __uint_as_float(b << 16); }
__device__ __forceinline__ u32 pack2(float lo, float hi) {
    return f2bf(lo) | (f2bf(hi) << 16);
}

// ---------------- bilinear helpers (jax half-pixel + clamp semantics) ----------------
__device__ __forceinline__ float bil7(const float* __restrict__ A, int wy, int wx) {
    float sy = (wy + 0.5f) * 0.5f - 0.5f;
    float sx = (wx + 0.5f) * 0.5f - 0.5f;
    sy = fminf(fmaxf(sy, 0.f), 6.f);
    sx = fminf(fmaxf(sx, 0.f), 6.f);
    int y0 = (int)sy; float fy = sy - y0; int y1 = min(y0 + 1, 6);
    int x0 = (int)sx; float fx = sx - x0; int x1 = min(x0 + 1, 6);
    float v00 = A[y0 * 7 + x0], v01 = A[y0 * 7 + x1];
    float v10 = A[y1 * 7 + x0], v11 = A[y1 * 7 + x1];
    return (1.f - fy) * ((1.f - fx) * v00 + fx * v01) +
           fy * ((1.f - fx) * v10 + fx * v11);
}

__global__ void k_pb(const float* __restrict__ an, const float* __restrict__ ahb,
                     const float* __restrict__ awb) {
    int ha = blockIdx.x;
    int t = threadIdx.x;
    if (t >= WW2) return;
    int wy = t / WIN, wx = t % WIN;
    float v = bil7(an + ha * 49, wy, wx);
    g_pb[ha * WW2 + t] = v + ahb[ha * WIN + wy] + awb[ha * WIN + wx];
}

__global__ void k_ab(const float* __restrict__ na, const float* __restrict__ hab,
                     const float* __restrict__ wab, const float* __restrict__ cab) {
    int tid = blockIdx.x * blockDim.x + threadIdx.x;
    int total = HEADS * 197 * AGENT;
    if (tid >= total) return;
    int h = tid / (197 * AGENT);
    int r = (tid / AGENT) % 197;
    int a = tid % AGENT;
    float v;
    if (r == 0) {
        v = cab[h * AGENT + a];
    } else {
        int t = r - 1;
        int wy = t / WIN, wx = t % WIN;
        v = bil7(na + (h * AGENT + a) * 49, wy, wx)
          + hab[(h * WIN + wy) * AGENT + a]
          + wab[(h * WIN + wx) * AGENT + a];
    }
    g_ab[(h * 197 + r) * AGENT + a] = v;
}

__global__ void k_bias1() {
    int tid = blockIdx.x * blockDim.x + threadIdx.x;
    int total = HEADS * AGENT * NTOK;
    if (tid >= total) return;
    int ha = tid / NTOK;
    int n = tid % NTOK;
    float s = (n + 0.5f) * 0.0625f - 0.5f;
    s = fminf(fmaxf(s, 0.f), 195.f);
    int t0 = (int)s; float f = s - t0; int t1 = min(t0 + 1, 195);
    g_bias1[tid] = g_pb[ha * WW2 + t0] * (1.f - f) + g_pb[ha * WW2 + t1] * f;
}

__global__ void k_bias2() {
    int tid = blockIdx.x * blockDim.x + threadIdx.x;
    int total = HEADS * NTOK * AGENT;
    if (tid >= total) return;
    int h = tid / (NTOK * AGENT);
    int rem = tid % (NTOK * AGENT);
    int n = rem / AGENT;
    int a = rem % AGENT;
    float s = (n + 0.5f) * (197.0f / 3136.0f) - 0.5f;
    s = fminf(fmaxf(s, 0.f), 196.f);
    int r0 = (int)s; float f = s - r0; int r1 = min(r0 + 1, 196);
    g_bias2[tid] = g_ab[(h * 197 + r0) * AGENT + a] * (1.f - f)
                 + g_ab[(h * 197 + r1) * AGENT + a] * f;
}

// ---------------- fp32 -> bf16 hi/lo split conversion ----------------
// src: [M, 512] fp32 row-major. dst: [M, 1024] bf16-bits, row = [hi(512) | lo(512)]
__global__ void k_cvt(const float* __restrict__ src, unsigned short* __restrict__ dst,
                      int total4) {
    int idx = blockIdx.x * 256 + threadIdx.x;
    if (idx >= total4) return;
    int m = idx >> 7;            // /128  (512/4 groups per row)
    int k4 = (idx & 127) << 2;
    float4 v = *(const float4*)(src + (size_t)m * 512 + k4);
    u32 h0 = f2bf(v.x), h1 = f2bf(v.y), h2 = f2bf(v.z), h3 = f2bf(v.w);
    float r0 = v.x - bf2f(h0), r1 = v.y - bf2f(h1);
    float r2 = v.z - bf2f(h2), r3 = v.w - bf2f(h3);
    u32* dh = (u32*)(dst + (size_t)m * 1024 + k4);
    dh[0] = h0 | (h1 << 16);
    dh[1] = h2 | (h3 << 16);
    u32* dl = (u32*)(dst + (size_t)m * 1024 + 512 + k4);
    dl[0] = pack2(r0, r1);
    dl[1] = pack2(r2, r3);
}

// ================= bf16x3 GEMM via mma.sync (HMMA, base sm_103-safe) =================
// C[M,N] = A[M,512]*B[N,512]^T (+bias). A/B rows: 1024 bf16 = [hi(512)|lo(512)].
// CTA tile 128x128, 256 thr (8 warps 4x2, warp tile 32x64), BK=32,
// 2-stage cp.async double buffer (80KB) -> 2 CTAs/SM.

#define G_PLANE 10240                       // 128 * 80 bytes
#define G_STAGE (4 * G_PLANE)               // 40960
#define G_NSTG  2
#define GSMEM_TOTAL (G_NSTG * G_STAGE)      // 81920

static __device__ __forceinline__ u32 smem_u32(const void* p) {
    u32 a;
    asm("{ .reg .u64 t; cvta.to.shared.u64 t, %1; cvt.u32.u64 %0, t; }" : "=r"(a) : "l"(p));
    return a;
}
static __device__ __forceinline__ void cpa16(u32 s, const void* g) {
    asm volatile("cp.async.cg.shared.global [%0], [%1], 16;" :: "r"(s), "l"(g) : "memory");
}
static __device__ __forceinline__ void ldsm4(u32* r, u32 addr) {
    asm volatile("ldmatrix.sync.aligned.m8n8.x4.shared.b16 {%0,%1,%2,%3}, [%4];"
        : "=r"(r[0]), "=r"(r[1]), "=r"(r[2]), "=r"(r[3]) : "r"(addr));
}
static __device__ __forceinline__ void mma16816(float* c, const u32* a, const u32* b) {
    asm volatile("mma.sync.aligned.m16n8k16.row.col.f32.bf16.bf16.f32 "
        "{%0,%1,%2,%3}, {%4,%5,%6,%7}, {%8,%9}, {%0,%1,%2,%3};"
        : "+f"(c[0]), "+f"(c[1]), "+f"(c[2]), "+f"(c[3])
        : "r"(a[0]), "r"(a[1]), "r"(a[2]), "r"(a[3]), "r"(b[0]), "r"(b[1]));
}

// load K-chunk c (32 halves per plane) for A rows m0..+128 and B rows n0..+128
static __device__ __forceinline__ void load_chunk(
    u32 buf, const unsigned short* __restrict__ A, const unsigned short* __restrict__ B,
    int m0, int n0, int c, int tid)
{
    for (int idx = tid; idx < 512; idx += 256) {
        int r = idx >> 2, seg = idx & 3;
        const unsigned short* g = A + (size_t)(m0 + r) * 1024 + c * 32 + seg * 8;
        u32 d = buf + r * 80 + seg * 16;
        cpa16(d, g);                 // A hi
        cpa16(d + G_PLANE, g + 512); // A lo
    }
    for (int idx = tid; idx < 512; idx += 256) {
        int r = idx >> 2, seg = idx & 3;
        const unsigned short* g = B + (size_t)(n0 + r) * 1024 + c * 32 + seg * 8;
        u32 d = buf + 2 * G_PLANE + r * 80 + seg * 16;
        cpa16(d, g);                 // B hi
        cpa16(d + G_PLANE, g + 512); // B lo
    }
    asm volatile("cp.async.commit_group;" ::: "memory");
}

__global__ __launch_bounds__(256, 2)
void k_gemm(const unsigned short* __restrict__ Ahl, const unsigned short* __restrict__ Bhl,
            const float* __restrict__ bias, float* __restrict__ C, int ldc)
{
    extern __shared__ char smem[];
    const u32 sb = smem_u32(smem);
    const int tid = threadIdx.x;
    const int wid = tid >> 5, lane = tid & 31;
    const int wm = wid >> 1, wn = wid & 1;       // 4 x 2 warp grid
    const int m0 = blockIdx.y * 128;
    const int n0 = blockIdx.x * 128;
    const int row_a = lane & 15;                 // ldmatrix row within 16
    const int kseg = lane >> 4;                  // 0/1 -> k halves 0-7 / 8-15

    float acc[2][8][4];
#pragma unroll
    for (int mt = 0; mt < 2; mt++)
#pragma unroll
        for (int j = 0; j < 8; j++)
#pragma unroll
            for (int q = 0; q < 4; q++) acc[mt][j][q] = 0.f;

    // prologue: fill both buffers
    load_chunk(sb + 0 * G_STAGE, Ahl, Bhl, m0, n0, 0, tid);
    load_chunk(sb + 1 * G_STAGE, Ahl, Bhl, m0, n0, 1, tid);

    // per-warp fragment offsets within a stage (buf-independent)
    const u32 aoff0 = (u32)((wm * 32 + row_a) * 80) + (u32)(kseg * 16);
    const u32 boff0 = 2 * G_PLANE + (u32)((wn * 64 + row_a) * 80) + (u32)(kseg * 16);

    for (int c = 0; c < 16; c++) {
        if (c < 15) asm volatile("cp.async.wait_group 1;" ::: "memory");
        else        asm volatile("cp.async.wait_group 0;" ::: "memory");
        __syncthreads();

        const u32 buf = sb + (c & 1) * G_STAGE;
#pragma unroll
        for (int ks = 0; ks < 2; ks++) {
            const u32 kb = ks * 32;
            u32 ah[2][4], al[2][4], bh[8][2], bl[8][2];
#pragma unroll
            for (int mt = 0; mt < 2; mt++) {
                u32 ad = buf + aoff0 + mt * (16 * 80) + kb;
                ldsm4(ah[mt], ad);
                ldsm4(al[mt], ad + G_PLANE);
            }
#pragma unroll
            for (int nt = 0; nt < 4; nt++) {
                u32 bd = buf + boff0 + nt * (16 * 80) + kb;
                u32 r[4];
                ldsm4(r, bd);
                bh[2 * nt][0] = r[0]; bh[2 * nt + 1][0] = r[1];
                bh[2 * nt][1] = r[2]; bh[2 * nt + 1][1] = r[3];
                ldsm4(r, bd + G_PLANE);
                bl[2 * nt][0] = r[0]; bl[2 * nt + 1][0] = r[1];
                bl[2 * nt][1] = r[2]; bl[2 * nt + 1][1] = r[3];
            }
#pragma unroll
            for (int mt = 0; mt < 2; mt++)
#pragma unroll
                for (int j = 0; j < 8; j++) {
                    mma16816(acc[mt][j], ah[mt], bh[j]);
                    mma16816(acc[mt][j], ah[mt], bl[j]);
                    mma16816(acc[mt][j], al[mt], bh[j]);
                }
        }
        __syncthreads();
        if (c + 2 < 16)
            load_chunk(buf, Ahl, Bhl, m0, n0, c + 2, tid);
    }

    // epilogue: direct float2 stores (+bias)
    const int gq = lane >> 2, tg = lane & 3;
#pragma unroll
    for (int mt = 0; mt < 2; mt++) {
        int row = m0 + wm * 32 + mt * 16 + gq;
#pragma unroll
        for (int j = 0; j < 8; j++) {
            int col = n0 + wn * 64 + j * 8 + tg * 2;
            float b0 = 0.f, b1 = 0.f;
            if (bias) { b0 = bias[col]; b1 = bias[col + 1]; }
            float2 v0 = make_float2(acc[mt][j][0] + b0, acc[mt][j][1] + b1);
            float2 v1 = make_float2(acc[mt][j][2] + b0, acc[mt][j][3] + b1);
            *(float2*)&C[(size_t)row * ldc + col] = v0;
            *(float2*)&C[(size_t)(row + 8) * ldc + col] = v1;
        }
    }
}

// ---------------- agent pooling: exact 8x8 block mean of q ----------------
__global__ void k_agent() {
    int b = blockIdx.x / AGENT;
    int a = blockIdx.x % AGENT;
    int py = a / 7, px = a % 7;
    int c = threadIdx.x;
    float s = 0.f;
#pragma unroll 4
    for (int dy = 0; dy < 8; dy++)
        for (int dx = 0; dx < 8; dx++) {
            int n = (py * 8 + dy) * WWID + px * 8 + dx;
            s += g_qkv[((size_t)b * NTOK + n) * 1536 + c];
        }
    g_agent[((size_t)b * AGENT + a) * DIM + c] = s * (1.f / 64.f);
}

// ---------------- stage 1 (fused flash, split-KV) ----------------
#define S1_SMEM_FLOATS (3136 + 128 * 65 + 49 * 128 + 192)
__global__ __launch_bounds__(256) void k_s1() {
    extern __shared__ float sm[];
    float* ah_s = sm;
    float* ks   = sm + 3136;
    float* sc   = sm + 3136 + 8320;
    float* mrow = sc + 6272;
    float* srow = mrow + 64;
    float* frow = srow + 64;
    int split = blockIdx.x, h = blockIdx.y, b = blockIdx.z;
    int t = threadIdx.x, warp = t >> 5, lane = t & 31;
    int g = t >> 6, d = t & 63;
    const int base = (g == 0) ? 0 : (13 + 12 * (g - 1));
    const int cnt = (g == 0) ? 13 : 12;
    // f32x2 scores ownership: thread owns k-row nl_own, half the agent range
    const int nl_own = t & 127;
    const int a_beg = (t >> 7) ? 25 : 0;
    const int a_end = (t >> 7) ? 49 : 25;

    for (int idx = t; idx < AGENT * HD; idx += 256) {
        int a = idx >> 6, dd = idx & 63;
        ah_s[idx] = g_agent[((size_t)b * AGENT + a) * DIM + h * HD + dd] * 0.125f;
    }
    if (t < AGENT) { mrow[t] = -1e30f; srow[t] = 0.f; }
    float acc[13];
#pragma unroll
    for (int i = 0; i < 13; i++) acc[i] = 0.f;
    __syncthreads();

    for (int c = 0; c < 5; c++) {
        int n0 = (split * 5 + c) * 128;
        int nc = min(128, NTOK - n0);

        for (int idx = t; idx < 128 * 64; idx += 256) {
            int r = idx >> 6, dd = idx & 63;
            ks[r * 65 + dd] = (r < nc)
                ? g_qkv[((size_t)b * NTOK + n0 + r) * 1536 + DIM + h * HD + dd] : 0.f;
        }
        __syncthreads();

        // scores + bias via packed f32x2: own k-row in 32 u64 regs
        {
            u64 k2[32];
#pragma unroll
            for (int d2 = 0; d2 < 32; d2++)
                PACK2F(k2[d2], ks[nl_own * 65 + 2 * d2], ks[nl_own * 65 + 2 * d2 + 1]);
            bool valid = nl_own < nc;
#pragma unroll 1
            for (int a = a_beg; a < a_end; a++) {
                u64 acc2 = 0;
                const u64* ah2 = (const u64*)(ah_s + a * 64);
#pragma unroll
                for (int d2 = 0; d2 < 32; d2++) FMA2(acc2, k2[d2], ah2[d2]);
                float lo, hi; UNPACK2F(lo, hi, acc2);
                sc[a * 128 + nl_own] = valid
                    ? (lo + hi + g_bias1[(h * AGENT + a) * NTOK + n0 + nl_own]) : -1e30f;
            }
        }
        __syncthreads();

        for (int a = warp; a < AGENT; a += 8) {
            float cm = -1e30f;
            for (int i = lane; i < 128; i += 32) cm = fmaxf(cm, sc[a * 128 + i]);
            for (int off = 16; off; off >>= 1)
                cm = fmaxf(cm, __shfl_xor_sync(0xffffffffu, cm, off));
            float mo = mrow[a];
            float nm = fmaxf(mo, cm);
            float f = __expf(mo - nm);
            float rs = 0.f;
            for (int i = lane; i < 128; i += 32) {
                float p = __expf(sc[a * 128 + i] - nm);
                sc[a * 128 + i] = p;
                rs += p;
            }
            for (int off = 16; off; off >>= 1)
                rs += __shfl_xor_sync(0xffffffffu, rs, off);
            if (lane == 0) { mrow[a] = nm; srow[a] = srow[a] * f + rs; frow[a] = f; }
        }
        __syncthreads();

#pragma unroll
        for (int i = 0; i < 13; i++)
            if (i < cnt) acc[i] *= frow[base + i];
        for (int nl = 0; nl < nc; nl++) {
            float vv = g_qkv[((size_t)b * NTOK + n0 + nl) * 1536 + 1024 + h * HD + d];
#pragma unroll
            for (int i = 0; i < 13; i++)
                if (i < cnt) acc[i] += sc[(base + i) * 128 + nl] * vv;
        }
        __syncthreads();
    }

    size_t pb_ = (((size_t)(b * HEADS + h)) * S1SPLIT + split) * AGENT;
#pragma unroll
    for (int i = 0; i < 13; i++)
        if (i < cnt) g_pacc[(pb_ + base + i) * HD + d] = acc[i];
    if (t < AGENT) { g_pm[pb_ + t] = mrow[t]; g_ps[pb_ + t] = srow[t]; }
}

__global__ __launch_bounds__(256) void k_s1merge() {
    int bh = blockIdx.x;
    int t = threadIdx.x;
    for (int idx = t; idx < AGENT * HD; idx += 256) {
        int a = idx >> 6, d = idx & 63;
        size_t p0 = ((size_t)bh * S1SPLIT) * AGENT + a;
        float nm = -1e30f;
        for (int s = 0; s < S1SPLIT; s++) nm = fmaxf(nm, g_pm[p0 + s * AGENT]);
        float S = 0.f, A = 0.f;
        for (int s = 0; s < S1SPLIT; s++) {
            float w = __expf(g_pm[p0 + s * AGENT] - nm);
            S += g_ps[p0 + s * AGENT] * w;
            A += g_pacc[(p0 + s * AGENT) * HD + d] * w;
        }
        g_agentv[((size_t)bh * AGENT + a) * HD + d] = A / S;
    }
}

// ---------------- stage 2: q->agent attention (f32x2 packed math) ----------------
#define S2_SMEM_FLOATS (3136 + 3136 + 128 * 65 + 128 * 49)
__global__ __launch_bounds__(128) void k_s2() {
    extern __shared__ float sm[];
    float* ah_s = sm;
    float* av_s = sm + 3136;
    float* qs   = sm + 6272;
    float* bsm  = sm + 6272 + 8320;
    int chunk = blockIdx.x, h = blockIdx.y, b = blockIdx.z;
    int t = threadIdx.x;
    int n0 = chunk * 128;

    for (int idx = t; idx < AGENT * HD; idx += 128) {
        int a = idx >> 6, d = idx & 63;
        ah_s[idx] = g_agent[((size_t)b * AGENT + a) * DIM + h * HD + d] * 0.125f;
        av_s[idx] = g_agentv[((size_t)(b * HEADS + h)) * AGENT * HD + idx];
    }
    for (int idx = t; idx < 128 * 64; idx += 128) {
        int r = idx >> 6, d = idx & 63;
        int n = n0 + r;
        qs[r * 65 + d] = (n < NTOK)
            ? g_qkv[((size_t)b * NTOK + n) * 1536 + h * HD + d] : 0.f;
    }
    for (int idx = t; idx < 128 * AGENT; idx += 128) {
        if (n0 * AGENT + idx < NTOK * AGENT)
            bsm[idx] = g_bias2[(size_t)h * NTOK * AGENT + (size_t)n0 * AGENT + idx];
    }
    __syncthreads();

    int n = n0 + t;
    if (n < NTOK) {
        // pack own q row into 32 u64
        u64 q2[32];
#pragma unroll
        for (int d2 = 0; d2 < 32; d2++)
            PACK2F(q2[d2], qs[t * 65 + 2 * d2], qs[t * 65 + 2 * d2 + 1]);

        float m = -1e30f;
#pragma unroll 1
        for (int a = 0; a < AGENT; a++) {
            u64 acc2 = 0;
            const u64* ah2 = (const u64*)(ah_s + a * 64);
#pragma unroll
            for (int d2 = 0; d2 < 32; d2++) FMA2(acc2, q2[d2], ah2[d2]);
            float lo, hi; UNPACK2F(lo, hi, acc2);
            float s = lo + hi + bsm[t * AGENT + a];
            bsm[t * AGENT + a] = s;
            m = fmaxf(m, s);
        }
        float sum = 0.f;
        for (int a = 0; a < AGENT; a++) {
            float p = __expf(bsm[t * AGENT + a] - m);
            bsm[t * AGENT + a] = p;
            sum += p;
        }
        float inv = 1.f / sum;
        // output: agent-outer with packed broadcast prob
        u64 o2[32];
#pragma unroll
        for (int d2 = 0; d2 < 32; d2++) o2[d2] = 0;
#pragma unroll 1
        for (int a = 0; a < AGENT; a++) {
            float p = bsm[t * AGENT + a];
            u64 p2; PACK2F(p2, p, p);
            const u64* av2 = (const u64*)(av_s + a * 64);
#pragma unroll
            for (int d2 = 0; d2 < 32; d2++) FMA2(o2[d2], p2, av2[d2]);
        }
#pragma unroll
        for (int d2 = 0; d2 < 32; d2++) {
            float lo, hi; UNPACK2F(lo, hi, o2[d2]);
            qs[t * 65 + 2 * d2] = lo * inv;
            qs[t * 65 + 2 * d2 + 1] = hi * inv;
        }
    }
    __syncthreads();
    for (int idx = t; idx < 128 * 64; idx += 128) {
        int r = idx >> 6, dd = idx & 63;
        int nn = n0 + r;
        if (nn < NTOK)
            g_attnout[((size_t)b * NTOK + nn) * DIM + h * HD + dd] = qs[r * 65 + dd];
    }
}

// ---------------- depthwise 3x3 conv on v + attn residual -> bf16 hi/lo ----------------
__global__ __launch_bounds__(256) void k_dwc(const float* __restrict__ w_dwc,
                                             const float* __restrict__ b_dwc) {
    int y = blockIdx.x, b = blockIdx.y, t = threadIdx.x;
    int c = (t & 127) * 4;
    int xh = t >> 7;
    float wreg[4][9], bd[4];
#pragma unroll
    for (int j = 0; j < 4; j++) {
        bd[j] = b_dwc[c + j];
#pragma unroll
        for (int kk = 0; kk < 9; kk++) wreg[j][kk] = w_dwc[(c + j) * 9 + kk];
    }
    for (int x = xh; x < WWID; x += 2) {
        float a0 = bd[0], a1 = bd[1], a2 = bd[2], a3 = bd[3];
#pragma unroll
        for (int ky = 0; ky < 3; ky++) {
            int yy = y + ky - 1;
            if ((unsigned)yy >= HH) continue;
#pragma unroll
            for (int kx = 0; kx < 3; kx++) {
                int xx = x + kx - 1;
                if ((unsigned)xx >= WWID) continue;
                const float4 v = *(const float4*)&g_qkv[
                    (((size_t)b * NTOK) + yy * WWID + xx) * 1536 + 1024 + c];
                int kk = ky * 3 + kx;
                a0 += v.x * wreg[0][kk];
                a1 += v.y * wreg[1][kk];
                a2 += v.z * wreg[2][kk];
                a3 += v.w * wreg[3][kk];
            }
        }
        size_t m = ((size_t)b * NTOK) + y * WWID + x;
        const float4 cur = *(const float4*)&g_attnout[m * DIM + c];
        a0 += cur.x; a1 += cur.y; a2 += cur.z; a3 += cur.w;
        u32 h0 = f2bf(a0), h1 = f2bf(a1), h2 = f2bf(a2), h3 = f2bf(a3);
        u32* dh = (u32*)&g_aohl[m * 1024 + c];
        dh[0] = h0 | (h1 << 16);
        dh[1] = h2 | (h3 << 16);
        u32* dl = (u32*)&g_aohl[m * 1024 + 512 + c];
        dl[0] = pack2(a0 - bf2f(h0), a1 - bf2f(h1));
        dl[1] = pack2(a2 - bf2f(h2), a3 - bf2f(h3));
    }
}

// ---------------- launcher ----------------
extern "C" void kernel_launch(void* const* d_in, const int* in_sizes, int n_in,
                              void* d_out, int out_size) {
    const float* x      = (const float*)d_in[0];
    const float* w_qkv  = (const float*)d_in[1];
    const float* w_proj = (const float*)d_in[2];
    const float* b_proj = (const float*)d_in[3];
    const float* w_dwc  = (const float*)d_in[4];
    const float* b_dwc  = (const float*)d_in[5];
    const float* an     = (const float*)d_in[6];
    const float* na     = (const float*)d_in[7];
    const float* ahb    = (const float*)d_in[8];
    const float* awb    = (const float*)d_in[9];
    const float* hab    = (const float*)d_in[10];
    const float* wab    = (const float*)d_in[11];
    const float* cab    = (const float*)d_in[12];
    float* out = (float*)d_out;

    void *p_qkv = 0, *p_xhl = 0, *p_aohl = 0, *p_wq = 0, *p_wp = 0;
    cudaGetSymbolAddress(&p_qkv, g_qkv);
    cudaGetSymbolAddress(&p_xhl, g_xhl);
    cudaGetSymbolAddress(&p_aohl, g_aohl);
    cudaGetSymbolAddress(&p_wq, g_wqkvhl);
    cudaGetSymbolAddress(&p_wp, g_wprojhl);
    float* qkv = (float*)p_qkv;
    unsigned short* xhl = (unsigned short*)p_xhl;
    unsigned short* aohl = (unsigned short*)p_aohl;
    unsigned short* wqhl = (unsigned short*)p_wq;
    unsigned short* wphl = (unsigned short*)p_wp;

    cudaFuncSetAttribute(k_gemm, cudaFuncAttributeMaxDynamicSharedMemorySize, GSMEM_TOTAL);
    cudaFuncSetAttribute(k_s1, cudaFuncAttributeMaxDynamicSharedMemorySize,
                         S1_SMEM_FLOATS * (int)sizeof(float));
    cudaFuncSetAttribute(k_s2, cudaFuncAttributeMaxDynamicSharedMemorySize,
                         S2_SMEM_FLOATS * (int)sizeof(float));

    const int M = BB * NTOK;   // 50176

    // bf16 hi/lo conversions
    k_cvt<<<(M * 128 + 255) / 256, 256>>>(x, xhl, M * 128);
    k_cvt<<<(1536 * 128 + 255) / 256, 256>>>(w_qkv, wqhl, 1536 * 128);
    k_cvt<<<(512 * 128 + 255) / 256, 256>>>(w_proj, wphl, 512 * 128);

    // QKV GEMM: (50176,512)x(1536,512)^T -> (50176,1536) via HMMA bf16x3
    k_gemm<<<dim3(1536 / 128, M / 128), 256, GSMEM_TOTAL>>>(xhl, wqhl, 0, qkv, 1536);

    // bias tables (b-independent)
    k_pb<<<HEADS * AGENT, WW2>>>(an, ahb, awb);
    k_ab<<<(HEADS * 197 * AGENT + 255) / 256, 256>>>(na, hab, wab, cab);
    k_bias1<<<(HEADS * AGENT * NTOK + 255) / 256, 256>>>();
    k_bias2<<<(HEADS * NTOK * AGENT + 255) / 256, 256>>>();

    // agent pooling
    k_agent<<<BB * AGENT, DIM>>>();

    // stage 1: fused flash attention, split-KV + merge
    k_s1<<<dim3(S1SPLIT, HEADS, BB), 256, S1_SMEM_FLOATS * (int)sizeof(float)>>>();
    k_s1merge<<<BB * HEADS, 256>>>();

    // stage 2 (writes g_attnout)
    k_s2<<<dim3(25, HEADS, BB), 128, S2_SMEM_FLOATS * (int)sizeof(float)>>>();

    // depthwise conv residual, fused fp32->bf16 split (writes g_aohl)
    k_dwc<<<dim3(HH, BB), 256>>>(w_dwc, b_dwc);

    // projection GEMM with bias -> final fp32 output
    k_gemm<<<dim3(512 / 128, M / 128), 256, GSMEM_TOTAL>>>(aohl, wphl, b_proj, out, 512);
}

// round 14
// speedup vs baseline: 1.8989x; 1.0716x over previous
#include <cuda_runtime.h>
#include <math.h>

typedef unsigned int u32;
typedef unsigned long long u64;

// ---------------- problem constants ----------------
#define BB    16
#define NTOK  3136
#define DIM   512
#define HH    56
#define WWID  56
#define HEADS 8
#define HD    64
#define AGENT 49
#define WIN   14
#define WW2   196   // 14*14
#define S1SPLIT 5

// ---------------- packed f32x2 helpers (B300 FFMA2) ----------------
#define FMA2(c, a, b) asm("fma.rn.f32x2 %0, %1, %2, %0;" : "+l"(c) : "l"(a), "l"(b))
#define PACK2F(out, lo, hi) asm("mov.b64 %0, {%1, %2};" : "=l"(out) : "f"(lo), "f"(hi))
#define UNPACK2F(lo, hi, in) asm("mov.b64 {%0, %1}, %2;" : "=f"(lo), "=f"(hi) : "l"(in))

// ---------------- scratch (device globals; no allocation allowed) ----------------
__device__ float g_qkv[(size_t)BB * NTOK * 3 * DIM];            // fp32 qkv
__device__ float g_attnout[(size_t)BB * NTOK * DIM];            // attention only
__device__ unsigned short g_xhl[(size_t)BB * NTOK * 2 * DIM];   // x hi/lo bf16 bits
__device__ unsigned short g_aohl[(size_t)BB * NTOK * 2 * DIM];  // attn+dwc hi/lo bf16 bits
__device__ unsigned short g_wqkvhl[3 * DIM * 2 * DIM];
__device__ unsigned short g_wprojhl[DIM * 2 * DIM];
__device__ float g_agent[BB * AGENT * DIM];
__device__ float g_agentv[BB * HEADS * AGENT * HD];
__device__ float g_pacc[(size_t)BB * HEADS * S1SPLIT * AGENT * HD];
__device__ float g_pm[BB * HEADS * S1SPLIT * AGENT];
__device__ float g_ps[BB * HEADS * S1SPLIT * AGENT];
__device__ float g_pb[HEADS * AGENT * WW2];
__device__ float g_ab[HEADS * 197 * AGENT];
__device__ float g_bias1[HEADS * AGENT * NTOK];
__device__ float g_bias2[HEADS * NTOK * AGENT];

// ---------------- manual bf16 helpers (no cuda_bf16 types) ----------------
__device__ __forceinline__ u32 f2bf(float f) {           // round-to-nearest-even
    u32 u = __float_as_uint(f);
    return (u + 0x7fffu + ((u >> 16) & 1u)) >> 16;
}
__device__ __forceinline__ float bf2f(u32 b) { return __uint_as_float(b << 16); }
__device__ __forceinline__ u32 pack2(float lo, float hi) {
    return f2bf(lo) | (f2bf(hi) << 16);
}

// ---------------- bilinear helpers (jax half-pixel + clamp semantics) ----------------
__device__ __forceinline__ float bil7(const float* __restrict__ A, int wy, int wx) {
    float sy = (wy + 0.5f) * 0.5f - 0.5f;
    float sx = (wx + 0.5f) * 0.5f - 0.5f;
    sy = fminf(fmaxf(sy, 0.f), 6.f);
    sx = fminf(fmaxf(sx, 0.f), 6.f);
    int y0 = (int)sy; float fy = sy - y0; int y1 = min(y0 + 1, 6);
    int x0 = (int)sx; float fx = sx - x0; int x1 = min(x0 + 1, 6);
    float v00 = A[y0 * 7 + x0], v01 = A[y0 * 7 + x1];
    float v10 = A[y1 * 7 + x0], v11 = A[y1 * 7 + x1];
    return (1.f - fy) * ((1.f - fx) * v00 + fx * v01) +
           fy * ((1.f - fx) * v10 + fx * v11);
}

__global__ void k_pb(const float* __restrict__ an, const float* __restrict__ ahb,
                     const float* __restrict__ awb) {
    int ha = blockIdx.x;
    int t = threadIdx.x;
    if (t >= WW2) return;
    int wy = t / WIN, wx = t % WIN;
    float v = bil7(an + ha * 49, wy, wx);
    g_pb[ha * WW2 + t] = v + ahb[ha * WIN + wy] + awb[ha * WIN + wx];
}

__global__ void k_ab(const float* __restrict__ na, const float* __restrict__ hab,
                     const float* __restrict__ wab, const float* __restrict__ cab) {
    int tid = blockIdx.x * blockDim.x + threadIdx.x;
    int total = HEADS * 197 * AGENT;
    if (tid >= total) return;
    int h = tid / (197 * AGENT);
    int r = (tid / AGENT) % 197;
    int a = tid % AGENT;
    float v;
    if (r == 0) {
        v = cab[h * AGENT + a];
    } else {
        int t = r - 1;
        int wy = t / WIN, wx = t % WIN;
        v = bil7(na + (h * AGENT + a) * 49, wy, wx)
          + hab[(h * WIN + wy) * AGENT + a]
          + wab[(h * WIN + wx) * AGENT + a];
    }
    g_ab[(h * 197 + r) * AGENT + a] = v;
}

__global__ void k_bias1() {
    int tid = blockIdx.x * blockDim.x + threadIdx.x;
    int total = HEADS * AGENT * NTOK;
    if (tid >= total) return;
    int ha = tid / NTOK;
    int n = tid % NTOK;
    float s = (n + 0.5f) * 0.0625f - 0.5f;
    s = fminf(fmaxf(s, 0.f), 195.f);
    int t0 = (int)s; float f = s - t0; int t1 = min(t0 + 1, 195);
    g_bias1[tid] = g_pb[ha * WW2 + t0] * (1.f - f) + g_pb[ha * WW2 + t1] * f;
}

__global__ void k_bias2() {
    int tid = blockIdx.x * blockDim.x + threadIdx.x;
    int total = HEADS * NTOK * AGENT;
    if (tid >= total) return;
    int h = tid / (NTOK * AGENT);
    int rem = tid % (NTOK * AGENT);
    int n = rem / AGENT;
    int a = rem % AGENT;
    float s = (n + 0.5f) * (197.0f / 3136.0f) - 0.5f;
    s = fminf(fmaxf(s, 0.f), 196.f);
    int r0 = (int)s; float f = s - r0; int r1 = min(r0 + 1, 196);
    g_bias2[tid] = g_ab[(h * 197 + r0) * AGENT + a] * (1.f - f)
                 + g_ab[(h * 197 + r1) * AGENT + a] * f;
}

// ---------------- fp32 -> bf16 hi/lo split conversion ----------------
// src: [M, 512] fp32 row-major. dst: [M, 1024] bf16-bits, row = [hi(512) | lo(512)]
__global__ void k_cvt(const float* __restrict__ src, unsigned short* __restrict__ dst,
                      int total4) {
    int idx = blockIdx.x * 256 + threadIdx.x;
    if (idx >= total4) return;
    int m = idx >> 7;            // /128  (512/4 groups per row)
    int k4 = (idx & 127) << 2;
    float4 v = *(const float4*)(src + (size_t)m * 512 + k4);
    u32 h0 = f2bf(v.x), h1 = f2bf(v.y), h2 = f2bf(v.z), h3 = f2bf(v.w);
    float r0 = v.x - bf2f(h0), r1 = v.y - bf2f(h1);
    float r2 = v.z - bf2f(h2), r3 = v.w - bf2f(h3);
    u32* dh = (u32*)(dst + (size_t)m * 1024 + k4);
    dh[0] = h0 | (h1 << 16);
    dh[1] = h2 | (h3 << 16);
    u32* dl = (u32*)(dst + (size_t)m * 1024 + 512 + k4);
    dl[0] = pack2(r0, r1);
    dl[1] = pack2(r2, r3);
}

// ================= bf16x3 GEMM via mma.sync (HMMA, base sm_103-safe) =================
// C[M,N] = A[M,512]*B[N,512]^T (+bias). A/B rows: 1024 bf16 = [hi(512)|lo(512)].
// CTA tile 128x128, 256 thr (8 warps 4x2, warp tile 32x64), BK=32,
// 2-stage cp.async double buffer (80KB) -> 2 CTAs/SM.
// Inner loop: per-nt interleaved ldsm/mma for tensor-pipe overlap.

#define G_PLANE 10240                       // 128 * 80 bytes
#define G_STAGE (4 * G_PLANE)               // 40960
#define G_NSTG  2
#define GSMEM_TOTAL (G_NSTG * G_STAGE)      // 81920

static __device__ __forceinline__ u32 smem_u32(const void* p) {
    u32 a;
    asm("{ .reg .u64 t; cvta.to.shared.u64 t, %1; cvt.u32.u64 %0, t; }" : "=r"(a) : "l"(p));
    return a;
}
static __device__ __forceinline__ void cpa16(u32 s, const void* g) {
    asm volatile("cp.async.cg.shared.global [%0], [%1], 16;" :: "r"(s), "l"(g) : "memory");
}
static __device__ __forceinline__ void ldsm4(u32* r, u32 addr) {
    asm volatile("ldmatrix.sync.aligned.m8n8.x4.shared.b16 {%0,%1,%2,%3}, [%4];"
        : "=r"(r[0]), "=r"(r[1]), "=r"(r[2]), "=r"(r[3]) : "r"(addr));
}
static __device__ __forceinline__ void mma16816(float* c, const u32* a, const u32* b) {
    asm volatile("mma.sync.aligned.m16n8k16.row.col.f32.bf16.bf16.f32 "
        "{%0,%1,%2,%3}, {%4,%5,%6,%7}, {%8,%9}, {%0,%1,%2,%3};"
        : "+f"(c[0]), "+f"(c[1]), "+f"(c[2]), "+f"(c[3])
        : "r"(a[0]), "r"(a[1]), "r"(a[2]), "r"(a[3]), "r"(b[0]), "r"(b[1]));
}

// load K-chunk c (32 halves per plane) for A rows m0..+128 and B rows n0..+128
static __device__ __forceinline__ void load_chunk(
    u32 buf, const unsigned short* __restrict__ A, const unsigned short* __restrict__ B,
    int m0, int n0, int c, int tid)
{
    for (int idx = tid; idx < 512; idx += 256) {
        int r = idx >> 2, seg = idx & 3;
        const unsigned short* g = A + (size_t)(m0 + r) * 1024 + c * 32 + seg * 8;
        u32 d = buf + r * 80 + seg * 16;
        cpa16(d, g);                 // A hi
        cpa16(d + G_PLANE, g + 512); // A lo
    }
    for (int idx = tid; idx < 512; idx += 256) {
        int r = idx >> 2, seg = idx & 3;
        const unsigned short* g = B + (size_t)(n0 + r) * 1024 + c * 32 + seg * 8;
        u32 d = buf + 2 * G_PLANE + r * 80 + seg * 16;
        cpa16(d, g);                 // B hi
        cpa16(d + G_PLANE, g + 512); // B lo
    }
    asm volatile("cp.async.commit_group;" ::: "memory");
}

__global__ __launch_bounds__(256, 2)
void k_gemm(const unsigned short* __restrict__ Ahl, const unsigned short* __restrict__ Bhl,
            const float* __restrict__ bias, float* __restrict__ C, int ldc)
{
    extern __shared__ char smem[];
    const u32 sb = smem_u32(smem);
    const int tid = threadIdx.x;
    const int wid = tid >> 5, lane = tid & 31;
    const int wm = wid >> 1, wn = wid & 1;       // 4 x 2 warp grid
    const int m0 = blockIdx.y * 128;
    const int n0 = blockIdx.x * 128;
    const int row_a = lane & 15;                 // ldmatrix row within 16
    const int kseg = lane >> 4;                  // 0/1 -> k halves 0-7 / 8-15

    float acc[2][8][4];
#pragma unroll
    for (int mt = 0; mt < 2; mt++)
#pragma unroll
        for (int j = 0; j < 8; j++)
#pragma unroll
            for (int q = 0; q < 4; q++) acc[mt][j][q] = 0.f;

    // prologue: fill both buffers
    load_chunk(sb + 0 * G_STAGE, Ahl, Bhl, m0, n0, 0, tid);
    load_chunk(sb + 1 * G_STAGE, Ahl, Bhl, m0, n0, 1, tid);

    // per-warp fragment offsets within a stage (buf-independent)
    const u32 aoff0 = (u32)((wm * 32 + row_a) * 80) + (u32)(kseg * 16);
    const u32 boff0 = 2 * G_PLANE + (u32)((wn * 64 + row_a) * 80) + (u32)(kseg * 16);

    for (int c = 0; c < 16; c++) {
        if (c < 15) asm volatile("cp.async.wait_group 1;" ::: "memory");
        else        asm volatile("cp.async.wait_group 0;" ::: "memory");
        __syncthreads();

        const u32 buf = sb + (c & 1) * G_STAGE;
#pragma unroll
        for (int ks = 0; ks < 2; ks++) {
            const u32 kb = ks * 32;
            u32 ah[2][4], al[2][4];
#pragma unroll
            for (int mt = 0; mt < 2; mt++) {
                u32 ad = buf + aoff0 + mt * (16 * 80) + kb;
                ldsm4(ah[mt], ad);
                ldsm4(al[mt], ad + G_PLANE);
            }
            // per-nt interleaved: 2 ldsm then 12 mma -> ldsm(nt+1) overlaps mma(nt)
#pragma unroll
            for (int nt = 0; nt < 4; nt++) {
                u32 bd = buf + boff0 + nt * (16 * 80) + kb;
                u32 rh[4], rl[4];
                ldsm4(rh, bd);
                ldsm4(rl, bd + G_PLANE);
                u32 b0h[2] = {rh[0], rh[2]}, b1h[2] = {rh[1], rh[3]};
                u32 b0l[2] = {rl[0], rl[2]}, b1l[2] = {rl[1], rl[3]};
#pragma unroll
                for (int mt = 0; mt < 2; mt++) {
                    mma16816(acc[mt][2 * nt], ah[mt], b0h);
                    mma16816(acc[mt][2 * nt], ah[mt], b0l);
                    mma16816(acc[mt][2 * nt], al[mt], b0h);
                    mma16816(acc[mt][2 * nt + 1], ah[mt], b1h);
                    mma16816(acc[mt][2 * nt + 1], ah[mt], b1l);
                    mma16816(acc[mt][2 * nt + 1], al[mt], b1h);
                }
            }
        }
        __syncthreads();
        if (c + 2 < 16)
            load_chunk(buf, Ahl, Bhl, m0, n0, c + 2, tid);
    }

    // epilogue: direct float2 stores (+bias)
    const int gq = lane >> 2, tg = lane & 3;
#pragma unroll
    for (int mt = 0; mt < 2; mt++) {
        int row = m0 + wm * 32 + mt * 16 + gq;
#pragma unroll
        for (int j = 0; j < 8; j++) {
            int col = n0 + wn * 64 + j * 8 + tg * 2;
            float b0 = 0.f, b1 = 0.f;
            if (bias) { b0 = bias[col]; b1 = bias[col + 1]; }
            float2 v0 = make_float2(acc[mt][j][0] + b0, acc[mt][j][1] + b1);
            float2 v1 = make_float2(acc[mt][j][2] + b0, acc[mt][j][3] + b1);
            *(float2*)&C[(size_t)row * ldc + col] = v0;
            *(float2*)&C[(size_t)(row + 8) * ldc + col] = v1;
        }
    }
}

// ---------------- agent pooling: exact 8x8 block mean of q ----------------
__global__ void k_agent() {
    int b = blockIdx.x / AGENT;
    int a = blockIdx.x % AGENT;
    int py = a / 7, px = a % 7;
    int c = threadIdx.x;
    float s = 0.f;
#pragma unroll 4
    for (int dy = 0; dy < 8; dy++)
        for (int dx = 0; dx < 8; dx++) {
            int n = (py * 8 + dy) * WWID + px * 8 + dx;
            s += g_qkv[((size_t)b * NTOK + n) * 1536 + c];
        }
    g_agent[((size_t)b * AGENT + a) * DIM + c] = s * (1.f / 64.f);
}

// ---------------- stage 1 (fused flash, split-KV) ----------------
#define S1_SMEM_FLOATS (3136 + 128 * 65 + 49 * 128 + 192)
__global__ __launch_bounds__(256) void k_s1() {
    extern __shared__ float sm[];
    float* ah_s = sm;
    float* ks   = sm + 3136;          // k tile during scores; reused as v tile after
    float* sc   = sm + 3136 + 8320;
    float* mrow = sc + 6272;
    float* srow = mrow + 64;
    float* frow = srow + 64;
    int split = blockIdx.x, h = blockIdx.y, b = blockIdx.z;
    int t = threadIdx.x, warp = t >> 5, lane = t & 31;
    int g = t >> 6, d = t & 63;
    const int base = (g == 0) ? 0 : (13 + 12 * (g - 1));
    const int cnt = (g == 0) ? 13 : 12;
    // f32x2 scores ownership: thread owns k-row nl_own, half the agent range
    const int nl_own = t & 127;
    const int a_beg = (t >> 7) ? 25 : 0;
    const int a_end = (t >> 7) ? 49 : 25;

    for (int idx = t; idx < AGENT * HD; idx += 256) {
        int a = idx >> 6, dd = idx & 63;
        ah_s[idx] = g_agent[((size_t)b * AGENT + a) * DIM + h * HD + dd] * 0.125f;
    }
    if (t < AGENT) { mrow[t] = -1e30f; srow[t] = 0.f; }
    float acc[13];
#pragma unroll
    for (int i = 0; i < 13; i++) acc[i] = 0.f;
    __syncthreads();

    for (int c = 0; c < 5; c++) {
        int n0 = (split * 5 + c) * 128;
        int nc = min(128, NTOK - n0);

        for (int idx = t; idx < 128 * 64; idx += 256) {
            int r = idx >> 6, dd = idx & 63;
            ks[r * 65 + dd] = (r < nc)
                ? g_qkv[((size_t)b * NTOK + n0 + r) * 1536 + DIM + h * HD + dd] : 0.f;
        }
        __syncthreads();

        // scores + bias via packed f32x2: own k-row in 32 u64 regs
        {
            u64 k2[32];
#pragma unroll
            for (int d2 = 0; d2 < 32; d2++)
                PACK2F(k2[d2], ks[nl_own * 65 + 2 * d2], ks[nl_own * 65 + 2 * d2 + 1]);
            bool valid = nl_own < nc;
#pragma unroll 1
            for (int a = a_beg; a < a_end; a++) {
                u64 acc2 = 0;
                const u64* ah2 = (const u64*)(ah_s + a * 64);
#pragma unroll
                for (int d2 = 0; d2 < 32; d2++) FMA2(acc2, k2[d2], ah2[d2]);
                float lo, hi; UNPACK2F(lo, hi, acc2);
                sc[a * 128 + nl_own] = valid
                    ? (lo + hi + g_bias1[(h * AGENT + a) * NTOK + n0 + nl_own]) : -1e30f;
            }
        }
        __syncthreads();

        // stage v chunk into ks (k tile is dead now; stride 64, 16B-aligned)
        for (int idx = t; idx < 2048; idx += 256) {
            int r = idx >> 4, f4 = (idx & 15) << 2;
            if (r < nc) {
                const float4 vv4 = *(const float4*)&g_qkv[
                    ((size_t)b * NTOK + n0 + r) * 1536 + 1024 + h * HD + f4];
                *(float4*)&ks[r * 64 + f4] = vv4;
            }
        }
        // per-row online stats (8 warps cover 49 rows) — concurrent with v staging
        for (int a = warp; a < AGENT; a += 8) {
            float cm = -1e30f;
            for (int i = lane; i < 128; i += 32) cm = fmaxf(cm, sc[a * 128 + i]);
            for (int off = 16; off; off >>= 1)
                cm = fmaxf(cm, __shfl_xor_sync(0xffffffffu, cm, off));
            float mo = mrow[a];
            float nm = fmaxf(mo, cm);
            float f = __expf(mo - nm);
            float rs = 0.f;
            for (int i = lane; i < 128; i += 32) {
                float p = __expf(sc[a * 128 + i] - nm);
                sc[a * 128 + i] = p;
                rs += p;
            }
            for (int off = 16; off; off >>= 1)
                rs += __shfl_xor_sync(0xffffffffu, rs, off);
            if (lane == 0) { mrow[a] = nm; srow[a] = srow[a] * f + rs; frow[a] = f; }
        }
        __syncthreads();

#pragma unroll
        for (int i = 0; i < 13; i++)
            if (i < cnt) acc[i] *= frow[base + i];
        for (int nl = 0; nl < nc; nl++) {
            float vv = ks[nl * 64 + d];
#pragma unroll
            for (int i = 0; i < 13; i++)
                if (i < cnt) acc[i] += sc[(base + i) * 128 + nl] * vv;
        }
        __syncthreads();
    }

    size_t pb_ = (((size_t)(b * HEADS + h)) * S1SPLIT + split) * AGENT;
#pragma unroll
    for (int i = 0; i < 13; i++)
        if (i < cnt) g_pacc[(pb_ + base + i) * HD + d] = acc[i];
    if (t < AGENT) { g_pm[pb_ + t] = mrow[t]; g_ps[pb_ + t] = srow[t]; }
}

__global__ __launch_bounds__(256) void k_s1merge() {
    int bh = blockIdx.x;
    int t = threadIdx.x;
    for (int idx = t; idx < AGENT * HD; idx += 256) {
        int a = idx >> 6, d = idx & 63;
        size_t p0 = ((size_t)bh * S1SPLIT) * AGENT + a;
        float nm = -1e30f;
        for (int s = 0; s < S1SPLIT; s++) nm = fmaxf(nm, g_pm[p0 + s * AGENT]);
        float S = 0.f, A = 0.f;
        for (int s = 0; s < S1SPLIT; s++) {
            float w = __expf(g_pm[p0 + s * AGENT] - nm);
            S += g_ps[p0 + s * AGENT] * w;
            A += g_pacc[(p0 + s * AGENT) * HD + d] * w;
        }
        g_agentv[((size_t)bh * AGENT + a) * HD + d] = A / S;
    }
}

// ---------------- stage 2: q->agent attention (f32x2 packed math) ----------------
#define S2_SMEM_FLOATS (3136 + 3136 + 128 * 65 + 128 * 49)
__global__ __launch_bounds__(128) void k_s2() {
    extern __shared__ float sm[];
    float* ah_s = sm;
    float* av_s = sm + 3136;
    float* qs   = sm + 6272;
    float* bsm  = sm + 6272 + 8320;
    int chunk = blockIdx.x, h = blockIdx.y, b = blockIdx.z;
    int t = threadIdx.x;
    int n0 = chunk * 128;

    for (int idx = t; idx < AGENT * HD; idx += 128) {
        int a = idx >> 6, d = idx & 63;
        ah_s[idx] = g_agent[((size_t)b * AGENT + a) * DIM + h * HD + d] * 0.125f;
        av_s[idx] = g_agentv[((size_t)(b * HEADS + h)) * AGENT * HD + idx];
    }
    for (int idx = t; idx < 128 * 64; idx += 128) {
        int r = idx >> 6, d = idx & 63;
        int n = n0 + r;
        qs[r * 65 + d] = (n < NTOK)
            ? g_qkv[((size_t)b * NTOK + n) * 1536 + h * HD + d] : 0.f;
    }
    for (int idx = t; idx < 128 * AGENT; idx += 128) {
        if (n0 * AGENT + idx < NTOK * AGENT)
            bsm[idx] = g_bias2[(size_t)h * NTOK * AGENT + (size_t)n0 * AGENT + idx];
    }
    __syncthreads();

    int n = n0 + t;
    if (n < NTOK) {
        // pack own q row into 32 u64
        u64 q2[32];
#pragma unroll
        for (int d2 = 0; d2 < 32; d2++)
            PACK2F(q2[d2], qs[t * 65 + 2 * d2], qs[t * 65 + 2 * d2 + 1]);

        float m = -1e30f;
#pragma unroll 1
        for (int a = 0; a < AGENT; a++) {
            u64 acc2 = 0;
            const u64* ah2 = (const u64*)(ah_s + a * 64);
#pragma unroll
            for (int d2 = 0; d2 < 32; d2++) FMA2(acc2, q2[d2], ah2[d2]);
            float lo, hi; UNPACK2F(lo, hi, acc2);
            float s = lo + hi + bsm[t * AGENT + a];
            bsm[t * AGENT + a] = s;
            m = fmaxf(m, s);
        }
        float sum = 0.f;
        for (int a = 0; a < AGENT; a++) {
            float p = __expf(bsm[t * AGENT + a] - m);
            bsm[t * AGENT + a] = p;
            sum += p;
        }
        float inv = 1.f / sum;
        // output: agent-outer with packed broadcast prob
        u64 o2[32];
#pragma unroll
        for (int d2 = 0; d2 < 32; d2++) o2[d2] = 0;
#pragma unroll 1
        for (int a = 0; a < AGENT; a++) {
            float p = bsm[t * AGENT + a];
            u64 p2; PACK2F(p2, p, p);
            const u64* av2 = (const u64*)(av_s + a * 64);
#pragma unroll
            for (int d2 = 0; d2 < 32; d2++) FMA2(o2[d2], p2, av2[d2]);
        }
#pragma unroll
        for (int d2 = 0; d2 < 32; d2++) {
            float lo, hi; UNPACK2F(lo, hi, o2[d2]);
            qs[t * 65 + 2 * d2] = lo * inv;
            qs[t * 65 + 2 * d2 + 1] = hi * inv;
        }
    }
    __syncthreads();
    for (int idx = t; idx < 128 * 64; idx += 128) {
        int r = idx >> 6, dd = idx & 63;
        int nn = n0 + r;
        if (nn < NTOK)
            g_attnout[((size_t)b * NTOK + nn) * DIM + h * HD + dd] = qs[r * 65 + dd];
    }
}

// ---------------- depthwise 3x3 conv on v + attn residual -> bf16 hi/lo ----------------
__global__ __launch_bounds__(256) void k_dwc(const float* __restrict__ w_dwc,
                                             const float* __restrict__ b_dwc) {
    int y = blockIdx.x, b = blockIdx.y, t = threadIdx.x;
    int c = (t & 127) * 4;
    int xh = t >> 7;
    float wreg[4][9], bd[4];
#pragma unroll
    for (int j = 0; j < 4; j++) {
        bd[j] = b_dwc[c + j];
#pragma unroll
        for (int kk = 0; kk < 9; kk++) wreg[j][kk] = w_dwc[(c + j) * 9 + kk];
    }
    for (int x = xh; x < WWID; x += 2) {
        float a0 = bd[0], a1 = bd[1], a2 = bd[2], a3 = bd[3];
#pragma unroll
        for (int ky = 0; ky < 3; ky++) {
            int yy = y + ky - 1;
            if ((unsigned)yy >= HH) continue;
#pragma unroll
            for (int kx = 0; kx < 3; kx++) {
                int xx = x + kx - 1;
                if ((unsigned)xx >= WWID) continue;
                const float4 v = *(const float4*)&g_qkv[
                    (((size_t)b * NTOK) + yy * WWID + xx) * 1536 + 1024 + c];
                int kk = ky * 3 + kx;
                a0 += v.x * wreg[0][kk];
                a1 += v.y * wreg[1][kk];
                a2 += v.z * wreg[2][kk];
                a3 += v.w * wreg[3][kk];
            }
        }
        size_t m = ((size_t)b * NTOK) + y * WWID + x;
        const float4 cur = *(const float4*)&g_attnout[m * DIM + c];
        a0 += cur.x; a1 += cur.y; a2 += cur.z; a3 += cur.w;
        u32 h0 = f2bf(a0), h1 = f2bf(a1), h2 = f2bf(a2), h3 = f2bf(a3);
        u32* dh = (u32*)&g_aohl[m * 1024 + c];
        dh[0] = h0 | (h1 << 16);
        dh[1] = h2 | (h3 << 16);
        u32* dl = (u32*)&g_aohl[m * 1024 + 512 + c];
        dl[0] = pack2(a0 - bf2f(h0), a1 - bf2f(h1));
        dl[1] = pack2(a2 - bf2f(h2), a3 - bf2f(h3));
    }
}

// ---------------- launcher ----------------
extern "C" void kernel_launch(void* const* d_in, const int* in_sizes, int n_in,
                              void* d_out, int out_size) {
    const float* x      = (const float*)d_in[0];
    const float* w_qkv  = (const float*)d_in[1];
    const float* w_proj = (const float*)d_in[2];
    const float* b_proj = (const float*)d_in[3];
    const float* w_dwc  = (const float*)d_in[4];
    const float* b_dwc  = (const float*)d_in[5];
    const float* an     = (const float*)d_in[6];
    const float* na     = (const float*)d_in[7];
    const float* ahb    = (const float*)d_in[8];
    const float* awb    = (const float*)d_in[9];
    const float* hab    = (const float*)d_in[10];
    const float* wab    = (const float*)d_in[11];
    const float* cab    = (const float*)d_in[12];
    float* out = (float*)d_out;

    void *p_qkv = 0, *p_xhl = 0, *p_aohl = 0, *p_wq = 0, *p_wp = 0;
    cudaGetSymbolAddress(&p_qkv, g_qkv);
    cudaGetSymbolAddress(&p_xhl, g_xhl);
    cudaGetSymbolAddress(&p_aohl, g_aohl);
    cudaGetSymbolAddress(&p_wq, g_wqkvhl);
    cudaGetSymbolAddress(&p_wp, g_wprojhl);
    float* qkv = (float*)p_qkv;
    unsigned short* xhl = (unsigned short*)p_xhl;
    unsigned short* aohl = (unsigned short*)p_aohl;
    unsigned short* wqhl = (unsigned short*)p_wq;
    unsigned short* wphl = (unsigned short*)p_wp;

    cudaFuncSetAttribute(k_gemm, cudaFuncAttributeMaxDynamicSharedMemorySize, GSMEM_TOTAL);
    cudaFuncSetAttribute(k_s1, cudaFuncAttributeMaxDynamicSharedMemorySize,
                         S1_SMEM_FLOATS * (int)sizeof(float));
    cudaFuncSetAttribute(k_s2, cudaFuncAttributeMaxDynamicSharedMemorySize,
                         S2_SMEM_FLOATS * (int)sizeof(float));

    const int M = BB * NTOK;   // 50176

    // bf16 hi/lo conversions
    k_cvt<<<(M * 128 + 255) / 256, 256>>>(x, xhl, M * 128);
    k_cvt<<<(1536 * 128 + 255) / 256, 256>>>(w_qkv, wqhl, 1536 * 128);
    k_cvt<<<(512 * 128 + 255) / 256, 256>>>(w_proj, wphl, 512 * 128);

    // QKV GEMM: (50176,512)x(1536,512)^T -> (50176,1536) via HMMA bf16x3
    k_gemm<<<dim3(1536 / 128, M / 128), 256, GSMEM_TOTAL>>>(xhl, wqhl, 0, qkv, 1536);

    // bias tables (b-independent)
    k_pb<<<HEADS * AGENT, WW2>>>(an, ahb, awb);
    k_ab<<<(HEADS * 197 * AGENT + 255) / 256, 256>>>(na, hab, wab, cab);
    k_bias1<<<(HEADS * AGENT * NTOK + 255) / 256, 256>>>();
    k_bias2<<<(HEADS * NTOK * AGENT + 255) / 256, 256>>>();

    // agent pooling
    k_agent<<<BB * AGENT, DIM>>>();

    // stage 1: fused flash attention, split-KV + merge
    k_s1<<<dim3(S1SPLIT, HEADS, BB), 256, S1_SMEM_FLOATS * (int)sizeof(float)>>>();
    k_s1merge<<<BB * HEADS, 256>>>();

    // stage 2 (writes g_attnout)
    k_s2<<<dim3(25, HEADS, BB), 128, S2_SMEM_FLOATS * (int)sizeof(float)>>>();

    // depthwise conv residual, fused fp32->bf16 split (writes g_aohl)
    k_dwc<<<dim3(HH, BB), 256>>>(w_dwc, b_dwc);

    // projection GEMM with bias -> final fp32 output
    k_gemm<<<dim3(512 / 128, M / 128), 256, GSMEM_TOTAL>>>(aohl, wphl, b_proj, out, 512);
}

// round 15
// speedup vs baseline: 1.9227x; 1.0125x over previous
#include <cuda_runtime.h>
#include <math.h>

typedef unsigned int u32;
typedef unsigned long long u64;

// ---------------- problem constants ----------------
#define BB    16
#define NTOK  3136
#define DIM   512
#define HH    56
#define WWID  56
#define HEADS 8
#define HD    64
#define AGENT 49
#define WIN   14
#define WW2   196   // 14*14
#define S1SPLIT 5

// ---------------- packed f32x2 helpers (B300 FFMA2) ----------------
#define FMA2(c, a, b) asm("fma.rn.f32x2 %0, %1, %2, %0;" : "+l"(c) : "l"(a), "l"(b))
#define PACK2F(out, lo, hi) asm("mov.b64 %0, {%1, %2};" : "=l"(out) : "f"(lo), "f"(hi))
#define UNPACK2F(lo, hi, in) asm("mov.b64 {%0, %1}, %2;" : "=f"(lo), "=f"(hi) : "l"(in))

// ---------------- scratch (device globals; no allocation allowed) ----------------
__device__ float g_qkv[(size_t)BB * NTOK * 3 * DIM];            // fp32 qkv
__device__ float g_attnout[(size_t)BB * NTOK * DIM];            // attention only
__device__ unsigned short g_xhl[(size_t)BB * NTOK * 2 * DIM];   // x hi/lo bf16 bits
__device__ unsigned short g_aohl[(size_t)BB * NTOK * 2 * DIM];  // attn+dwc hi/lo bf16 bits
__device__ unsigned short g_wqkvhl[3 * DIM * 2 * DIM];
__device__ unsigned short g_wprojhl[DIM * 2 * DIM];
__device__ float g_agent[BB * AGENT * DIM];
__device__ float g_agentv[BB * HEADS * AGENT * HD];
__device__ float g_pacc[(size_t)BB * HEADS * S1SPLIT * AGENT * HD];
__device__ float g_pm[BB * HEADS * S1SPLIT * AGENT];
__device__ float g_ps[BB * HEADS * S1SPLIT * AGENT];
__device__ float g_pb[HEADS * AGENT * WW2];
__device__ float g_ab[HEADS * 197 * AGENT];
__device__ float g_bias1[HEADS * AGENT * NTOK];
__device__ float g_bias2[HEADS * NTOK * AGENT];

// ---------------- manual bf16 helpers (no cuda_bf16 types) ----------------
__device__ __forceinline__ u32 f2bf(float f) {           // round-to-nearest-even
    u32 u = __float_as_uint(f);
    return (u + 0x7fffu + ((u >> 16) & 1u)) >> 16;
}
__device__ __forceinline__ float bf2f(u32 b) { return __uint_as_float(b << 16); }
__device__ __forceinline__ u32 pack2(float lo, float hi) {
    return f2bf(lo) | (f2bf(hi) << 16);
}

// ---------------- bilinear helpers (jax half-pixel + clamp semantics) ----------------
__device__ __forceinline__ float bil7(const float* __restrict__ A, int wy, int wx) {
    float sy = (wy + 0.5f) * 0.5f - 0.5f;
    float sx = (wx + 0.5f) * 0.5f - 0.5f;
    sy = fminf(fmaxf(sy, 0.f), 6.f);
    sx = fminf(fmaxf(sx, 0.f), 6.f);
    int y0 = (int)sy; float fy = sy - y0; int y1 = min(y0 + 1, 6);
    int x0 = (int)sx; float fx = sx - x0; int x1 = min(x0 + 1, 6);
    float v00 = A[y0 * 7 + x0], v01 = A[y0 * 7 + x1];
    float v10 = A[y1 * 7 + x0], v11 = A[y1 * 7 + x1];
    return (1.f - fy) * ((1.f - fx) * v00 + fx * v01) +
           fy * ((1.f - fx) * v10 + fx * v11);
}

__global__ void k_pb(const float* __restrict__ an, const float* __restrict__ ahb,
                     const float* __restrict__ awb) {
    int ha = blockIdx.x;
    int t = threadIdx.x;
    if (t >= WW2) return;
    int wy = t / WIN, wx = t % WIN;
    float v = bil7(an + ha * 49, wy, wx);
    g_pb[ha * WW2 + t] = v + ahb[ha * WIN + wy] + awb[ha * WIN + wx];
}

__global__ void k_ab(const float* __restrict__ na, const float* __restrict__ hab,
                     const float* __restrict__ wab, const float* __restrict__ cab) {
    int tid = blockIdx.x * blockDim.x + threadIdx.x;
    int total = HEADS * 197 * AGENT;
    if (tid >= total) return;
    int h = tid / (197 * AGENT);
    int r = (tid / AGENT) % 197;
    int a = tid % AGENT;
    float v;
    if (r == 0) {
        v = cab[h * AGENT + a];
    } else {
        int t = r - 1;
        int wy = t / WIN, wx = t % WIN;
        v = bil7(na + (h * AGENT + a) * 49, wy, wx)
          + hab[(h * WIN + wy) * AGENT + a]
          + wab[(h * WIN + wx) * AGENT + a];
    }
    g_ab[(h * 197 + r) * AGENT + a] = v;
}

__global__ void k_bias1() {
    int tid = blockIdx.x * blockDim.x + threadIdx.x;
    int total = HEADS * AGENT * NTOK;
    if (tid >= total) return;
    int ha = tid / NTOK;
    int n = tid % NTOK;
    float s = (n + 0.5f) * 0.0625f - 0.5f;
    s = fminf(fmaxf(s, 0.f), 195.f);
    int t0 = (int)s; float f = s - t0; int t1 = min(t0 + 1, 195);
    g_bias1[tid] = g_pb[ha * WW2 + t0] * (1.f - f) + g_pb[ha * WW2 + t1] * f;
}

__global__ void k_bias2() {
    int tid = blockIdx.x * blockDim.x + threadIdx.x;
    int total = HEADS * NTOK * AGENT;
    if (tid >= total) return;
    int h = tid / (NTOK * AGENT);
    int rem = tid % (NTOK * AGENT);
    int n = rem / AGENT;
    int a = rem % AGENT;
    float s = (n + 0.5f) * (197.0f / 3136.0f) - 0.5f;
    s = fminf(fmaxf(s, 0.f), 196.f);
    int r0 = (int)s; float f = s - r0; int r1 = min(r0 + 1, 196);
    g_bias2[tid] = g_ab[(h * 197 + r0) * AGENT + a] * (1.f - f)
                 + g_ab[(h * 197 + r1) * AGENT + a] * f;
}

// ---------------- fp32 -> bf16 hi/lo split conversion ----------------
// src: [M, 512] fp32 row-major. dst: [M, 1024] bf16-bits, row = [hi(512) | lo(512)]
__global__ void k_cvt(const float* __restrict__ src, unsigned short* __restrict__ dst,
                      int total4) {
    int idx = blockIdx.x * 256 + threadIdx.x;
    if (idx >= total4) return;
    int m = idx >> 7;            // /128  (512/4 groups per row)
    int k4 = (idx & 127) << 2;
    float4 v = *(const float4*)(src + (size_t)m * 512 + k4);
    u32 h0 = f2bf(v.x), h1 = f2bf(v.y), h2 = f2bf(v.z), h3 = f2bf(v.w);
    float r0 = v.x - bf2f(h0), r1 = v.y - bf2f(h1);
    float r2 = v.z - bf2f(h2), r3 = v.w - bf2f(h3);
    u32* dh = (u32*)(dst + (size_t)m * 1024 + k4);
    dh[0] = h0 | (h1 << 16);
    dh[1] = h2 | (h3 << 16);
    u32* dl = (u32*)(dst + (size_t)m * 1024 + 512 + k4);
    dl[0] = pack2(r0, r1);
    dl[1] = pack2(r2, r3);
}

// ================= bf16x3 GEMM via mma.sync (HMMA, base sm_103-safe) =================
// C[M,N] = A[M,512]*B[N,512]^T (+bias). A/B rows: 1024 bf16 = [hi(512)|lo(512)].
// CTA tile 128x128, 256 thr (8 warps 4x2, warp tile 32x64), BK=32,
// 2-stage cp.async double buffer (80KB) -> 2 CTAs/SM.  (R12 inner-loop ordering.)

#define G_PLANE 10240                       // 128 * 80 bytes
#define G_STAGE (4 * G_PLANE)               // 40960
#define G_NSTG  2
#define GSMEM_TOTAL (G_NSTG * G_STAGE)      // 81920

static __device__ __forceinline__ u32 smem_u32(const void* p) {
    u32 a;
    asm("{ .reg .u64 t; cvta.to.shared.u64 t, %1; cvt.u32.u64 %0, t; }" : "=r"(a) : "l"(p));
    return a;
}
static __device__ __forceinline__ void cpa16(u32 s, const void* g) {
    asm volatile("cp.async.cg.shared.global [%0], [%1], 16;" :: "r"(s), "l"(g) : "memory");
}
static __device__ __forceinline__ void ldsm4(u32* r, u32 addr) {
    asm volatile("ldmatrix.sync.aligned.m8n8.x4.shared.b16 {%0,%1,%2,%3}, [%4];"
        : "=r"(r[0]), "=r"(r[1]), "=r"(r[2]), "=r"(r[3]) : "r"(addr));
}
static __device__ __forceinline__ void mma16816(float* c, const u32* a, const u32* b) {
    asm volatile("mma.sync.aligned.m16n8k16.row.col.f32.bf16.bf16.f32 "
        "{%0,%1,%2,%3}, {%4,%5,%6,%7}, {%8,%9}, {%0,%1,%2,%3};"
        : "+f"(c[0]), "+f"(c[1]), "+f"(c[2]), "+f"(c[3])
        : "r"(a[0]), "r"(a[1]), "r"(a[2]), "r"(a[3]), "r"(b[0]), "r"(b[1]));
}

// load K-chunk c (32 halves per plane) for A rows m0..+128 and B rows n0..+128
static __device__ __forceinline__ void load_chunk(
    u32 buf, const unsigned short* __restrict__ A, const unsigned short* __restrict__ B,
    int m0, int n0, int c, int tid)
{
    for (int idx = tid; idx < 512; idx += 256) {
        int r = idx >> 2, seg = idx & 3;
        const unsigned short* g = A + (size_t)(m0 + r) * 1024 + c * 32 + seg * 8;
        u32 d = buf + r * 80 + seg * 16;
        cpa16(d, g);                 // A hi
        cpa16(d + G_PLANE, g + 512); // A lo
    }
    for (int idx = tid; idx < 512; idx += 256) {
        int r = idx >> 2, seg = idx & 3;
        const unsigned short* g = B + (size_t)(n0 + r) * 1024 + c * 32 + seg * 8;
        u32 d = buf + 2 * G_PLANE + r * 80 + seg * 16;
        cpa16(d, g);                 // B hi
        cpa16(d + G_PLANE, g + 512); // B lo
    }
    asm volatile("cp.async.commit_group;" ::: "memory");
}

__global__ __launch_bounds__(256, 2)
void k_gemm(const unsigned short* __restrict__ Ahl, const unsigned short* __restrict__ Bhl,
            const float* __restrict__ bias, float* __restrict__ C, int ldc)
{
    extern __shared__ char smem[];
    const u32 sb = smem_u32(smem);
    const int tid = threadIdx.x;
    const int wid = tid >> 5, lane = tid & 31;
    const int wm = wid >> 1, wn = wid & 1;       // 4 x 2 warp grid
    const int m0 = blockIdx.y * 128;
    const int n0 = blockIdx.x * 128;
    const int row_a = lane & 15;                 // ldmatrix row within 16
    const int kseg = lane >> 4;                  // 0/1 -> k halves 0-7 / 8-15

    float acc[2][8][4];
#pragma unroll
    for (int mt = 0; mt < 2; mt++)
#pragma unroll
        for (int j = 0; j < 8; j++)
#pragma unroll
            for (int q = 0; q < 4; q++) acc[mt][j][q] = 0.f;

    // prologue: fill both buffers
    load_chunk(sb + 0 * G_STAGE, Ahl, Bhl, m0, n0, 0, tid);
    load_chunk(sb + 1 * G_STAGE, Ahl, Bhl, m0, n0, 1, tid);

    // per-warp fragment offsets within a stage (buf-independent)
    const u32 aoff0 = (u32)((wm * 32 + row_a) * 80) + (u32)(kseg * 16);
    const u32 boff0 = 2 * G_PLANE + (u32)((wn * 64 + row_a) * 80) + (u32)(kseg * 16);

    for (int c = 0; c < 16; c++) {
        if (c < 15) asm volatile("cp.async.wait_group 1;" ::: "memory");
        else        asm volatile("cp.async.wait_group 0;" ::: "memory");
        __syncthreads();

        const u32 buf = sb + (c & 1) * G_STAGE;
#pragma unroll
        for (int ks = 0; ks < 2; ks++) {
            const u32 kb = ks * 32;
            u32 ah[2][4], al[2][4], bh[8][2], bl[8][2];
#pragma unroll
            for (int mt = 0; mt < 2; mt++) {
                u32 ad = buf + aoff0 + mt * (16 * 80) + kb;
                ldsm4(ah[mt], ad);
                ldsm4(al[mt], ad + G_PLANE);
            }
#pragma unroll
            for (int nt = 0; nt < 4; nt++) {
                u32 bd = buf + boff0 + nt * (16 * 80) + kb;
                u32 r[4];
                ldsm4(r, bd);
                bh[2 * nt][0] = r[0]; bh[2 * nt + 1][0] = r[1];
                bh[2 * nt][1] = r[2]; bh[2 * nt + 1][1] = r[3];
                ldsm4(r, bd + G_PLANE);
                bl[2 * nt][0] = r[0]; bl[2 * nt + 1][0] = r[1];
                bl[2 * nt][1] = r[2]; bl[2 * nt + 1][1] = r[3];
            }
#pragma unroll
            for (int mt = 0; mt < 2; mt++)
#pragma unroll
                for (int j = 0; j < 8; j++) {
                    mma16816(acc[mt][j], ah[mt], bh[j]);
                    mma16816(acc[mt][j], ah[mt], bl[j]);
                    mma16816(acc[mt][j], al[mt], bh[j]);
                }
        }
        __syncthreads();
        if (c + 2 < 16)
            load_chunk(buf, Ahl, Bhl, m0, n0, c + 2, tid);
    }

    // epilogue: direct float2 stores (+bias)
    const int gq = lane >> 2, tg = lane & 3;
#pragma unroll
    for (int mt = 0; mt < 2; mt++) {
        int row = m0 + wm * 32 + mt * 16 + gq;
#pragma unroll
        for (int j = 0; j < 8; j++) {
            int col = n0 + wn * 64 + j * 8 + tg * 2;
            float b0 = 0.f, b1 = 0.f;
            if (bias) { b0 = bias[col]; b1 = bias[col + 1]; }
            float2 v0 = make_float2(acc[mt][j][0] + b0, acc[mt][j][1] + b1);
            float2 v1 = make_float2(acc[mt][j][2] + b0, acc[mt][j][3] + b1);
            *(float2*)&C[(size_t)row * ldc + col] = v0;
            *(float2*)&C[(size_t)(row + 8) * ldc + col] = v1;
        }
    }
}

// ---------------- agent pooling: exact 8x8 block mean of q ----------------
__global__ void k_agent() {
    int b = blockIdx.x / AGENT;
    int a = blockIdx.x % AGENT;
    int py = a / 7, px = a % 7;
    int c = threadIdx.x;
    float s = 0.f;
#pragma unroll 4
    for (int dy = 0; dy < 8; dy++)
        for (int dx = 0; dx < 8; dx++) {
            int n = (py * 8 + dy) * WWID + px * 8 + dx;
            s += g_qkv[((size_t)b * NTOK + n) * 1536 + c];
        }
    g_agent[((size_t)b * AGENT + a) * DIM + c] = s * (1.f / 64.f);
}

// ---------------- stage 1 (fused flash, split-KV) ----------------
#define S1_SMEM_FLOATS (3136 + 128 * 65 + 49 * 128 + 192)
__global__ __launch_bounds__(256) void k_s1() {
    extern __shared__ float sm[];
    float* ah_s = sm;
    float* ks   = sm + 3136;          // k tile during scores; reused as v tile after
    float* sc   = sm + 3136 + 8320;
    float* mrow = sc + 6272;
    float* srow = mrow + 64;
    float* frow = srow + 64;
    int split = blockIdx.x, h = blockIdx.y, b = blockIdx.z;
    int t = threadIdx.x, warp = t >> 5, lane = t & 31;
    int g = t >> 6, d = t & 63;
    const int base = (g == 0) ? 0 : (13 + 12 * (g - 1));
    const int cnt = (g == 0) ? 13 : 12;
    // f32x2 scores ownership: thread owns k-row nl_own, half the agent range
    const int nl_own = t & 127;
    const int a_beg = (t >> 7) ? 25 : 0;
    const int a_end = (t >> 7) ? 49 : 25;

    for (int idx = t; idx < AGENT * HD; idx += 256) {
        int a = idx >> 6, dd = idx & 63;
        ah_s[idx] = g_agent[((size_t)b * AGENT + a) * DIM + h * HD + dd] * 0.125f;
    }
    if (t < AGENT) { mrow[t] = -1e30f; srow[t] = 0.f; }
    float acc[13];
#pragma unroll
    for (int i = 0; i < 13; i++) acc[i] = 0.f;
    __syncthreads();

    for (int c = 0; c < 5; c++) {
        int n0 = (split * 5 + c) * 128;
        int nc = min(128, NTOK - n0);

        for (int idx = t; idx < 128 * 64; idx += 256) {
            int r = idx >> 6, dd = idx & 63;
            ks[r * 65 + dd] = (r < nc)
                ? g_qkv[((size_t)b * NTOK + n0 + r) * 1536 + DIM + h * HD + dd] : 0.f;
        }
        __syncthreads();

        // scores + bias via packed f32x2: own k-row in 32 u64 regs, 2 indep chains
        {
            u64 k2[32];
#pragma unroll
            for (int d2 = 0; d2 < 32; d2++)
                PACK2F(k2[d2], ks[nl_own * 65 + 2 * d2], ks[nl_own * 65 + 2 * d2 + 1]);
            bool valid = nl_own < nc;
#pragma unroll 1
            for (int a = a_beg; a < a_end; a++) {
                u64 accA = 0, accB = 0;
                const u64* ah2 = (const u64*)(ah_s + a * 64);
#pragma unroll
                for (int d2 = 0; d2 < 16; d2++) {
                    FMA2(accA, k2[2 * d2], ah2[2 * d2]);
                    FMA2(accB, k2[2 * d2 + 1], ah2[2 * d2 + 1]);
                }
                float loA, hiA, loB, hiB;
                UNPACK2F(loA, hiA, accA);
                UNPACK2F(loB, hiB, accB);
                sc[a * 128 + nl_own] = valid
                    ? ((loA + hiA) + (loB + hiB)
                       + g_bias1[(h * AGENT + a) * NTOK + n0 + nl_own]) : -1e30f;
            }
        }
        __syncthreads();

        // stage v chunk into ks (k tile is dead now; stride 64, 16B-aligned)
        for (int idx = t; idx < 2048; idx += 256) {
            int r = idx >> 4, f4 = (idx & 15) << 2;
            if (r < nc) {
                const float4 vv4 = *(const float4*)&g_qkv[
                    ((size_t)b * NTOK + n0 + r) * 1536 + 1024 + h * HD + f4];
                *(float4*)&ks[r * 64 + f4] = vv4;
            }
        }
        // per-row online stats (8 warps cover 49 rows) — concurrent with v staging
        for (int a = warp; a < AGENT; a += 8) {
            float cm = -1e30f;
            for (int i = lane; i < 128; i += 32) cm = fmaxf(cm, sc[a * 128 + i]);
            for (int off = 16; off; off >>= 1)
                cm = fmaxf(cm, __shfl_xor_sync(0xffffffffu, cm, off));
            float mo = mrow[a];
            float nm = fmaxf(mo, cm);
            float f = __expf(mo - nm);
            float rs = 0.f;
            for (int i = lane; i < 128; i += 32) {
                float p = __expf(sc[a * 128 + i] - nm);
                sc[a * 128 + i] = p;
                rs += p;
            }
            for (int off = 16; off; off >>= 1)
                rs += __shfl_xor_sync(0xffffffffu, rs, off);
            if (lane == 0) { mrow[a] = nm; srow[a] = srow[a] * f + rs; frow[a] = f; }
        }
        __syncthreads();

#pragma unroll
        for (int i = 0; i < 13; i++)
            if (i < cnt) acc[i] *= frow[base + i];
        for (int nl = 0; nl < nc; nl++) {
            float vv = ks[nl * 64 + d];
#pragma unroll
            for (int i = 0; i < 13; i++)
                if (i < cnt) acc[i] += sc[(base + i) * 128 + nl] * vv;
        }
        __syncthreads();
    }

    size_t pb_ = (((size_t)(b * HEADS + h)) * S1SPLIT + split) * AGENT;
#pragma unroll
    for (int i = 0; i < 13; i++)
        if (i < cnt) g_pacc[(pb_ + base + i) * HD + d] = acc[i];
    if (t < AGENT) { g_pm[pb_ + t] = mrow[t]; g_ps[pb_ + t] = srow[t]; }
}

__global__ __launch_bounds__(256) void k_s1merge() {
    int bh = blockIdx.x;
    int t = threadIdx.x;
    for (int idx = t; idx < AGENT * HD; idx += 256) {
        int a = idx >> 6, d = idx & 63;
        size_t p0 = ((size_t)bh * S1SPLIT) * AGENT + a;
        float nm = -1e30f;
        for (int s = 0; s < S1SPLIT; s++) nm = fmaxf(nm, g_pm[p0 + s * AGENT]);
        float S = 0.f, A = 0.f;
        for (int s = 0; s < S1SPLIT; s++) {
            float w = __expf(g_pm[p0 + s * AGENT] - nm);
            S += g_ps[p0 + s * AGENT] * w;
            A += g_pacc[(p0 + s * AGENT) * HD + d] * w;
        }
        g_agentv[((size_t)bh * AGENT + a) * HD + d] = A / S;
    }
}

// ---------------- stage 2: q->agent attention (f32x2 packed math) ----------------
#define S2_SMEM_FLOATS (3136 + 3136 + 128 * 65 + 128 * 49)
__global__ __launch_bounds__(128) void k_s2() {
    extern __shared__ float sm[];
    float* ah_s = sm;
    float* av_s = sm + 3136;
    float* qs   = sm + 6272;
    float* bsm  = sm + 6272 + 8320;
    int chunk = blockIdx.x, h = blockIdx.y, b = blockIdx.z;
    int t = threadIdx.x;
    int n0 = chunk * 128;

    for (int idx = t; idx < AGENT * HD; idx += 128) {
        int a = idx >> 6, d = idx & 63;
        ah_s[idx] = g_agent[((size_t)b * AGENT + a) * DIM + h * HD + d] * 0.125f;
        av_s[idx] = g_agentv[((size_t)(b * HEADS + h)) * AGENT * HD + idx];
    }
    for (int idx = t; idx < 128 * 64; idx += 128) {
        int r = idx >> 6, d = idx & 63;
        int n = n0 + r;
        qs[r * 65 + d] = (n < NTOK)
            ? g_qkv[((size_t)b * NTOK + n) * 1536 + h * HD + d] : 0.f;
    }
    for (int idx = t; idx < 128 * AGENT; idx += 128) {
        if (n0 * AGENT + idx < NTOK * AGENT)
            bsm[idx] = g_bias2[(size_t)h * NTOK * AGENT + (size_t)n0 * AGENT + idx];
    }
    __syncthreads();

    int n = n0 + t;
    if (n < NTOK) {
        // pack own q row into 32 u64
        u64 q2[32];
#pragma unroll
        for (int d2 = 0; d2 < 32; d2++)
            PACK2F(q2[d2], qs[t * 65 + 2 * d2], qs[t * 65 + 2 * d2 + 1]);

        float m = -1e30f;
#pragma unroll 1
        for (int a = 0; a < AGENT; a++) {
            u64 accA = 0, accB = 0;
            const u64* ah2 = (const u64*)(ah_s + a * 64);
#pragma unroll
            for (int d2 = 0; d2 < 16; d2++) {
                FMA2(accA, q2[2 * d2], ah2[2 * d2]);
                FMA2(accB, q2[2 * d2 + 1], ah2[2 * d2 + 1]);
            }
            float loA, hiA, loB, hiB;
            UNPACK2F(loA, hiA, accA);
            UNPACK2F(loB, hiB, accB);
            float s = (loA + hiA) + (loB + hiB) + bsm[t * AGENT + a];
            bsm[t * AGENT + a] = s;
            m = fmaxf(m, s);
        }
        float sum = 0.f;
        for (int a = 0; a < AGENT; a++) {
            float p = __expf(bsm[t * AGENT + a] - m);
            bsm[t * AGENT + a] = p;
            sum += p;
        }
        float inv = 1.f / sum;
        // output: agent-outer with packed broadcast prob (32 indep accumulators)
        u64 o2[32];
#pragma unroll
        for (int d2 = 0; d2 < 32; d2++) o2[d2] = 0;
#pragma unroll 1
        for (int a = 0; a < AGENT; a++) {
            float p = bsm[t * AGENT + a];
            u64 p2; PACK2F(p2, p, p);
            const u64* av2 = (const u64*)(av_s + a * 64);
#pragma unroll
            for (int d2 = 0; d2 < 32; d2++) FMA2(o2[d2], p2, av2[d2]);
        }
#pragma unroll
        for (int d2 = 0; d2 < 32; d2++) {
            float lo, hi; UNPACK2F(lo, hi, o2[d2]);
            qs[t * 65 + 2 * d2] = lo * inv;
            qs[t * 65 + 2 * d2 + 1] = hi * inv;
        }
    }
    __syncthreads();
    for (int idx = t; idx < 128 * 64; idx += 128) {
        int r = idx >> 6, dd = idx & 63;
        int nn = n0 + r;
        if (nn < NTOK)
            g_attnout[((size_t)b * NTOK + nn) * DIM + h * HD + dd] = qs[r * 65 + dd];
    }
}

// ---------------- depthwise 3x3 conv on v + attn residual -> bf16 hi/lo ----------------
__global__ __launch_bounds__(256) void k_dwc(const float* __restrict__ w_dwc,
                                             const float* __restrict__ b_dwc) {
    int y = blockIdx.x, b = blockIdx.y, t = threadIdx.x;
    int c = (t & 127) * 4;
    int xh = t >> 7;
    float wreg[4][9], bd[4];
#pragma unroll
    for (int j = 0; j < 4; j++) {
        bd[j] = b_dwc[c + j];
#pragma unroll
        for (int kk = 0; kk < 9; kk++) wreg[j][kk] = w_dwc[(c + j) * 9 + kk];
    }
    for (int x = xh; x < WWID; x += 2) {
        float a0 = bd[0], a1 = bd[1], a2 = bd[2], a3 = bd[3];
#pragma unroll
        for (int ky = 0; ky < 3; ky++) {
            int yy = y + ky - 1;
            if ((unsigned)yy >= HH) continue;
#pragma unroll
            for (int kx = 0; kx < 3; kx++) {
                int xx = x + kx - 1;
                if ((unsigned)xx >= WWID) continue;
                const float4 v = *(const float4*)&g_qkv[
                    (((size_t)b * NTOK) + yy * WWID + xx) * 1536 + 1024 + c];
                int kk = ky * 3 + kx;
                a0 += v.x * wreg[0][kk];
                a1 += v.y * wreg[1][kk];
                a2 += v.z * wreg[2][kk];
                a3 += v.w * wreg[3][kk];
            }
        }
        size_t m = ((size_t)b * NTOK) + y * WWID + x;
        const float4 cur = *(const float4*)&g_attnout[m * DIM + c];
        a0 += cur.x; a1 += cur.y; a2 += cur.z; a3 += cur.w;
        u32 h0 = f2bf(a0), h1 = f2bf(a1), h2 = f2bf(a2), h3 = f2bf(a3);
        u32* dh = (u32*)&g_aohl[m * 1024 + c];
        dh[0] = h0 | (h1 << 16);
        dh[1] = h2 | (h3 << 16);
        u32* dl = (u32*)&g_aohl[m * 1024 + 512 + c];
        dl[0] = pack2(a0 - bf2f(h0), a1 - bf2f(h1));
        dl[1] = pack2(a2 - bf2f(h2), a3 - bf2f(h3));
    }
}

// ---------------- launcher ----------------
extern "C" void kernel_launch(void* const* d_in, const int* in_sizes, int n_in,
                              void* d_out, int out_size) {
    const float* x      = (const float*)d_in[0];
    const float* w_qkv  = (const float*)d_in[1];
    const float* w_proj = (const float*)d_in[2];
    const float* b_proj = (const float*)d_in[3];
    const float* w_dwc  = (const float*)d_in[4];
    const float* b_dwc  = (const float*)d_in[5];
    const float* an     = (const float*)d_in[6];
    const float* na     = (const float*)d_in[7];
    const float* ahb    = (const float*)d_in[8];
    const float* awb    = (const float*)d_in[9];
    const float* hab    = (const float*)d_in[10];
    const float* wab    = (const float*)d_in[11];
    const float* cab    = (const float*)d_in[12];
    float* out = (float*)d_out;

    void *p_qkv = 0, *p_xhl = 0, *p_aohl = 0, *p_wq = 0, *p_wp = 0;
    cudaGetSymbolAddress(&p_qkv, g_qkv);
    cudaGetSymbolAddress(&p_xhl, g_xhl);
    cudaGetSymbolAddress(&p_aohl, g_aohl);
    cudaGetSymbolAddress(&p_wq, g_wqkvhl);
    cudaGetSymbolAddress(&p_wp, g_wprojhl);
    float* qkv = (float*)p_qkv;
    unsigned short* xhl = (unsigned short*)p_xhl;
    unsigned short* aohl = (unsigned short*)p_aohl;
    unsigned short* wqhl = (unsigned short*)p_wq;
    unsigned short* wphl = (unsigned short*)p_wp;

    cudaFuncSetAttribute(k_gemm, cudaFuncAttributeMaxDynamicSharedMemorySize, GSMEM_TOTAL);
    cudaFuncSetAttribute(k_s1, cudaFuncAttributeMaxDynamicSharedMemorySize,
                         S1_SMEM_FLOATS * (int)sizeof(float));
    cudaFuncSetAttribute(k_s2, cudaFuncAttributeMaxDynamicSharedMemorySize,
                         S2_SMEM_FLOATS * (int)sizeof(float));

    const int M = BB * NTOK;   // 50176

    // bf16 hi/lo conversions
    k_cvt<<<(M * 128 + 255) / 256, 256>>>(x, xhl, M * 128);
    k_cvt<<<(1536 * 128 + 255) / 256, 256>>>(w_qkv, wqhl, 1536 * 128);
    k_cvt<<<(512 * 128 + 255) / 256, 256>>>(w_proj, wphl, 512 * 128);

    // QKV GEMM: (50176,512)x(1536,512)^T -> (50176,1536) via HMMA bf16x3
    k_gemm<<<dim3(1536 / 128, M / 128), 256, GSMEM_TOTAL>>>(xhl, wqhl, 0, qkv, 1536);

    // bias tables (b-independent)
    k_pb<<<HEADS * AGENT, WW2>>>(an, ahb, awb);
    k_ab<<<(HEADS * 197 * AGENT + 255) / 256, 256>>>(na, hab, wab, cab);
    k_bias1<<<(HEADS * AGENT * NTOK + 255) / 256, 256>>>();
    k_bias2<<<(HEADS * NTOK * AGENT + 255) / 256, 256>>>();

    // agent pooling
    k_agent<<<BB * AGENT, DIM>>>();

    // stage 1: fused flash attention, split-KV + merge
    k_s1<<<dim3(S1SPLIT, HEADS, BB), 256, S1_SMEM_FLOATS * (int)sizeof(float)>>>();
    k_s1merge<<<BB * HEADS, 256>>>();

    // stage 2 (writes g_attnout)
    k_s2<<<dim3(25, HEADS, BB), 128, S2_SMEM_FLOATS * (int)sizeof(float)>>>();

    // depthwise conv residual, fused fp32->bf16 split (writes g_aohl)
    k_dwc<<<dim3(HH, BB), 256>>>(w_dwc, b_dwc);

    // projection GEMM with bias -> final fp32 output
    k_gemm<<<dim3(512 / 128, M / 128), 256, GSMEM_TOTAL>>>(aohl, wphl, b_proj, out, 512);
}

// round 16
// speedup vs baseline: 1.9543x; 1.0164x over previous
#include <cuda_runtime.h>
#include <math.h>

typedef unsigned int u32;
typedef unsigned long long u64;

// ---------------- problem constants ----------------
#define BB    16
#define NTOK  3136
#define DIM   512
#define HH    56
#define WWID  56
#define HEADS 8
#define HD    64
#define AGENT 49
#define WIN   14
#define WW2   196   // 14*14
#define S1SPLIT 5

// ---------------- packed f32x2 helpers (B300 FFMA2) ----------------
#define FMA2(c, a, b) asm("fma.rn.f32x2 %0, %1, %2, %0;" : "+l"(c) : "l"(a), "l"(b))
#define PACK2F(out, lo, hi) asm("mov.b64 %0, {%1, %2};" : "=l"(out) : "f"(lo), "f"(hi))
#define UNPACK2F(lo, hi, in) asm("mov.b64 {%0, %1}, %2;" : "=f"(lo), "=f"(hi) : "l"(in))

// ---------------- scratch (device globals; no allocation allowed) ----------------
__device__ float g_qkv[(size_t)BB * NTOK * 3 * DIM];            // fp32 qkv
__device__ float g_attnout[(size_t)BB * NTOK * DIM];            // attention only
__device__ unsigned short g_xhl[(size_t)BB * NTOK * 2 * DIM];   // x hi/lo bf16 bits
__device__ unsigned short g_aohl[(size_t)BB * NTOK * 2 * DIM];  // attn+dwc hi/lo bf16 bits
__device__ unsigned short g_wqkvhl[3 * DIM * 2 * DIM];
__device__ unsigned short g_wprojhl[DIM * 2 * DIM];
__device__ float g_agent[BB * AGENT * DIM];
__device__ float g_agentv[BB * HEADS * AGENT * HD];
__device__ float g_pacc[(size_t)BB * HEADS * S1SPLIT * AGENT * HD];
__device__ float g_pm[BB * HEADS * S1SPLIT * AGENT];
__device__ float g_ps[BB * HEADS * S1SPLIT * AGENT];
__device__ float g_pb[HEADS * AGENT * WW2];
__device__ float g_ab[HEADS * 197 * AGENT];
__device__ float g_bias1[HEADS * AGENT * NTOK];
__device__ float g_bias2[HEADS * NTOK * AGENT];

// ---------------- manual bf16 helpers (no cuda_bf16 types) ----------------
__device__ __forceinline__ u32 f2bf(float f) {           // round-to-nearest-even
    u32 u = __float_as_uint(f);
    return (u + 0x7fffu + ((u >> 16) & 1u)) >> 16;
}
__device__ __forceinline__ float bf2f(u32 b) { return __uint_as_float(b << 16); }
__device__ __forceinline__ u32 pack2(float lo, float hi) {
    return f2bf(lo) | (f2bf(hi) << 16);
}

// ---------------- bilinear helpers (jax half-pixel + clamp semantics) ----------------
__device__ __forceinline__ float bil7(const float* __restrict__ A, int wy, int wx) {
    float sy = (wy + 0.5f) * 0.5f - 0.5f;
    float sx = (wx + 0.5f) * 0.5f - 0.5f;
    sy = fminf(fmaxf(sy, 0.f), 6.f);
    sx = fminf(fmaxf(sx, 0.f), 6.f);
    int y0 = (int)sy; float fy = sy - y0; int y1 = min(y0 + 1, 6);
    int x0 = (int)sx; float fx = sx - x0; int x1 = min(x0 + 1, 6);
    float v00 = A[y0 * 7 + x0], v01 = A[y0 * 7 + x1];
    float v10 = A[y1 * 7 + x0], v11 = A[y1 * 7 + x1];
    return (1.f - fy) * ((1.f - fx) * v00 + fx * v01) +
           fy * ((1.f - fx) * v10 + fx * v11);
}

__global__ void k_pb(const float* __restrict__ an, const float* __restrict__ ahb,
                     const float* __restrict__ awb) {
    int ha = blockIdx.x;
    int t = threadIdx.x;
    if (t >= WW2) return;
    int wy = t / WIN, wx = t % WIN;
    float v = bil7(an + ha * 49, wy, wx);
    g_pb[ha * WW2 + t] = v + ahb[ha * WIN + wy] + awb[ha * WIN + wx];
}

__global__ void k_ab(const float* __restrict__ na, const float* __restrict__ hab,
                     const float* __restrict__ wab, const float* __restrict__ cab) {
    int tid = blockIdx.x * blockDim.x + threadIdx.x;
    int total = HEADS * 197 * AGENT;
    if (tid >= total) return;
    int h = tid / (197 * AGENT);
    int r = (tid / AGENT) % 197;
    int a = tid % AGENT;
    float v;
    if (r == 0) {
        v = cab[h * AGENT + a];
    } else {
        int t = r - 1;
        int wy = t / WIN, wx = t % WIN;
        v = bil7(na + (h * AGENT + a) * 49, wy, wx)
          + hab[(h * WIN + wy) * AGENT + a]
          + wab[(h * WIN + wx) * AGENT + a];
    }
    g_ab[(h * 197 + r) * AGENT + a] = v;
}

__global__ void k_bias1() {
    int tid = blockIdx.x * blockDim.x + threadIdx.x;
    int total = HEADS * AGENT * NTOK;
    if (tid >= total) return;
    int ha = tid / NTOK;
    int n = tid % NTOK;
    float s = (n + 0.5f) * 0.0625f - 0.5f;
    s = fminf(fmaxf(s, 0.f), 195.f);
    int t0 = (int)s; float f = s - t0; int t1 = min(t0 + 1, 195);
    g_bias1[tid] = g_pb[ha * WW2 + t0] * (1.f - f) + g_pb[ha * WW2 + t1] * f;
}

__global__ void k_bias2() {
    int tid = blockIdx.x * blockDim.x + threadIdx.x;
    int total = HEADS * NTOK * AGENT;
    if (tid >= total) return;
    int h = tid / (NTOK * AGENT);
    int rem = tid % (NTOK * AGENT);
    int n = rem / AGENT;
    int a = rem % AGENT;
    float s = (n + 0.5f) * (197.0f / 3136.0f) - 0.5f;
    s = fminf(fmaxf(s, 0.f), 196.f);
    int r0 = (int)s; float f = s - r0; int r1 = min(r0 + 1, 196);
    g_bias2[tid] = g_ab[(h * 197 + r0) * AGENT + a] * (1.f - f)
                 + g_ab[(h * 197 + r1) * AGENT + a] * f;
}

// ---------------- fp32 -> bf16 hi/lo split conversion ----------------
// src: [M, 512] fp32 row-major. dst: [M, 1024] bf16-bits, row = [hi(512) | lo(512)]
__global__ void k_cvt(const float* __restrict__ src, unsigned short* __restrict__ dst,
                      int total4) {
    int idx = blockIdx.x * 256 + threadIdx.x;
    if (idx >= total4) return;
    int m = idx >> 7;            // /128  (512/4 groups per row)
    int k4 = (idx & 127) << 2;
    float4 v = *(const float4*)(src + (size_t)m * 512 + k4);
    u32 h0 = f2bf(v.x), h1 = f2bf(v.y), h2 = f2bf(v.z), h3 = f2bf(v.w);
    float r0 = v.x - bf2f(h0), r1 = v.y - bf2f(h1);
    float r2 = v.z - bf2f(h2), r3 = v.w - bf2f(h3);
    u32* dh = (u32*)(dst + (size_t)m * 1024 + k4);
    dh[0] = h0 | (h1 << 16);
    dh[1] = h2 | (h3 << 16);
    u32* dl = (u32*)(dst + (size_t)m * 1024 + 512 + k4);
    dl[0] = pack2(r0, r1);
    dl[1] = pack2(r2, r3);
}

// ================= bf16x3 GEMM via mma.sync (HMMA, base sm_103-safe) =================
// C[M,N] = A[M,512]*B[N,512]^T (+bias). A/B rows: 1024 bf16 = [hi(512)|lo(512)].
// CTA tile 128x128, 256 thr (8 warps 4x2, warp tile 32x64), BK=32,
// 2-stage cp.async double buffer (80KB) -> 2 CTAs/SM.  (R12 inner-loop ordering.)

#define G_PLANE 10240                       // 128 * 80 bytes
#define G_STAGE (4 * G_PLANE)               // 40960
#define G_NSTG  2
#define GSMEM_TOTAL (G_NSTG * G_STAGE)      // 81920

static __device__ __forceinline__ u32 smem_u32(const void* p) {
    u32 a;
    asm("{ .reg .u64 t; cvta.to.shared.u64 t, %1; cvt.u32.u64 %0, t; }" : "=r"(a) : "l"(p));
    return a;
}
static __device__ __forceinline__ void cpa16(u32 s, const void* g) {
    asm volatile("cp.async.cg.shared.global [%0], [%1], 16;" :: "r"(s), "l"(g) : "memory");
}
static __device__ __forceinline__ void ldsm4(u32* r, u32 addr) {
    asm volatile("ldmatrix.sync.aligned.m8n8.x4.shared.b16 {%0,%1,%2,%3}, [%4];"
        : "=r"(r[0]), "=r"(r[1]), "=r"(r[2]), "=r"(r[3]) : "r"(addr));
}
static __device__ __forceinline__ void mma16816(float* c, const u32* a, const u32* b) {
    asm volatile("mma.sync.aligned.m16n8k16.row.col.f32.bf16.bf16.f32 "
        "{%0,%1,%2,%3}, {%4,%5,%6,%7}, {%8,%9}, {%0,%1,%2,%3};"
        : "+f"(c[0]), "+f"(c[1]), "+f"(c[2]), "+f"(c[3])
        : "r"(a[0]), "r"(a[1]), "r"(a[2]), "r"(a[3]), "r"(b[0]), "r"(b[1]));
}

// load K-chunk c (32 halves per plane) for A rows m0..+128 and B rows n0..+128
static __device__ __forceinline__ void load_chunk(
    u32 buf, const unsigned short* __restrict__ A, const unsigned short* __restrict__ B,
    int m0, int n0, int c, int tid)
{
    for (int idx = tid; idx < 512; idx += 256) {
        int r = idx >> 2, seg = idx & 3;
        const unsigned short* g = A + (size_t)(m0 + r) * 1024 + c * 32 + seg * 8;
        u32 d = buf + r * 80 + seg * 16;
        cpa16(d, g);                 // A hi
        cpa16(d + G_PLANE, g + 512); // A lo
    }
    for (int idx = tid; idx < 512; idx += 256) {
        int r = idx >> 2, seg = idx & 3;
        const unsigned short* g = B + (size_t)(n0 + r) * 1024 + c * 32 + seg * 8;
        u32 d = buf + 2 * G_PLANE + r * 80 + seg * 16;
        cpa16(d, g);                 // B hi
        cpa16(d + G_PLANE, g + 512); // B lo
    }
    asm volatile("cp.async.commit_group;" ::: "memory");
}

__global__ __launch_bounds__(256, 2)
void k_gemm(const unsigned short* __restrict__ Ahl, const unsigned short* __restrict__ Bhl,
            const float* __restrict__ bias, float* __restrict__ C, int ldc)
{
    extern __shared__ char smem[];
    const u32 sb = smem_u32(smem);
    const int tid = threadIdx.x;
    const int wid = tid >> 5, lane = tid & 31;
    const int wm = wid >> 1, wn = wid & 1;       // 4 x 2 warp grid
    const int m0 = blockIdx.y * 128;
    const int n0 = blockIdx.x * 128;
    const int row_a = lane & 15;                 // ldmatrix row within 16
    const int kseg = lane >> 4;                  // 0/1 -> k halves 0-7 / 8-15

    float acc[2][8][4];
#pragma unroll
    for (int mt = 0; mt < 2; mt++)
#pragma unroll
        for (int j = 0; j < 8; j++)
#pragma unroll
            for (int q = 0; q < 4; q++) acc[mt][j][q] = 0.f;

    // prologue: fill both buffers
    load_chunk(sb + 0 * G_STAGE, Ahl, Bhl, m0, n0, 0, tid);
    load_chunk(sb + 1 * G_STAGE, Ahl, Bhl, m0, n0, 1, tid);

    // per-warp fragment offsets within a stage (buf-independent)
    const u32 aoff0 = (u32)((wm * 32 + row_a) * 80) + (u32)(kseg * 16);
    const u32 boff0 = 2 * G_PLANE + (u32)((wn * 64 + row_a) * 80) + (u32)(kseg * 16);

    for (int c = 0; c < 16; c++) {
        if (c < 15) asm volatile("cp.async.wait_group 1;" ::: "memory");
        else        asm volatile("cp.async.wait_group 0;" ::: "memory");
        __syncthreads();

        const u32 buf = sb + (c & 1) * G_STAGE;
#pragma unroll
        for (int ks = 0; ks < 2; ks++) {
            const u32 kb = ks * 32;
            u32 ah[2][4], al[2][4], bh[8][2], bl[8][2];
#pragma unroll
            for (int mt = 0; mt < 2; mt++) {
                u32 ad = buf + aoff0 + mt * (16 * 80) + kb;
                ldsm4(ah[mt], ad);
                ldsm4(al[mt], ad + G_PLANE);
            }
#pragma unroll
            for (int nt = 0; nt < 4; nt++) {
                u32 bd = buf + boff0 + nt * (16 * 80) + kb;
                u32 r[4];
                ldsm4(r, bd);
                bh[2 * nt][0] = r[0]; bh[2 * nt + 1][0] = r[1];
                bh[2 * nt][1] = r[2]; bh[2 * nt + 1][1] = r[3];
                ldsm4(r, bd + G_PLANE);
                bl[2 * nt][0] = r[0]; bl[2 * nt + 1][0] = r[1];
                bl[2 * nt][1] = r[2]; bl[2 * nt + 1][1] = r[3];
            }
#pragma unroll
            for (int mt = 0; mt < 2; mt++)
#pragma unroll
                for (int j = 0; j < 8; j++) {
                    mma16816(acc[mt][j], ah[mt], bh[j]);
                    mma16816(acc[mt][j], ah[mt], bl[j]);
                    mma16816(acc[mt][j], al[mt], bh[j]);
                }
        }
        __syncthreads();
        if (c + 2 < 16)
            load_chunk(buf, Ahl, Bhl, m0, n0, c + 2, tid);
    }

    // epilogue: direct float2 stores (+bias)
    const int gq = lane >> 2, tg = lane & 3;
#pragma unroll
    for (int mt = 0; mt < 2; mt++) {
        int row = m0 + wm * 32 + mt * 16 + gq;
#pragma unroll
        for (int j = 0; j < 8; j++) {
            int col = n0 + wn * 64 + j * 8 + tg * 2;
            float b0 = 0.f, b1 = 0.f;
            if (bias) { b0 = bias[col]; b1 = bias[col + 1]; }
            float2 v0 = make_float2(acc[mt][j][0] + b0, acc[mt][j][1] + b1);
            float2 v1 = make_float2(acc[mt][j][2] + b0, acc[mt][j][3] + b1);
            *(float2*)&C[(size_t)row * ldc + col] = v0;
            *(float2*)&C[(size_t)(row + 8) * ldc + col] = v1;
        }
    }
}

// ---------------- agent pooling: exact 8x8 block mean of q ----------------
__global__ void k_agent() {
    int b = blockIdx.x / AGENT;
    int a = blockIdx.x % AGENT;
    int py = a / 7, px = a % 7;
    int c = threadIdx.x;
    float s = 0.f;
#pragma unroll 4
    for (int dy = 0; dy < 8; dy++)
        for (int dx = 0; dx < 8; dx++) {
            int n = (py * 8 + dy) * WWID + px * 8 + dx;
            s += g_qkv[((size_t)b * NTOK + n) * 1536 + c];
        }
    g_agent[((size_t)b * AGENT + a) * DIM + c] = s * (1.f / 64.f);
}

// ---------------- stage 1 (fused flash, split-KV) ----------------
#define S1_SMEM_FLOATS (3136 + 128 * 65 + 49 * 128 + 192)
__global__ __launch_bounds__(256) void k_s1() {
    extern __shared__ float sm[];
    float* ah_s = sm;
    float* ks   = sm + 3136;          // k tile during scores; reused as v tile after
    float* sc   = sm + 3136 + 8320;
    float* mrow = sc + 6272;
    float* srow = mrow + 64;
    float* frow = srow + 64;
    int split = blockIdx.x, h = blockIdx.y, b = blockIdx.z;
    int t = threadIdx.x, warp = t >> 5, lane = t & 31;
    int g = t >> 6, d = t & 63;
    const int base = (g == 0) ? 0 : (13 + 12 * (g - 1));
    const int cnt = (g == 0) ? 13 : 12;
    // f32x2 scores ownership: thread owns k-row nl_own, half the agent range
    const int nl_own = t & 127;
    const int a_beg = (t >> 7) ? 25 : 0;
    const int a_end = (t >> 7) ? 49 : 25;

    for (int idx = t; idx < AGENT * HD; idx += 256) {
        int a = idx >> 6, dd = idx & 63;
        ah_s[idx] = g_agent[((size_t)b * AGENT + a) * DIM + h * HD + dd] * 0.125f;
    }
    if (t < AGENT) { mrow[t] = -1e30f; srow[t] = 0.f; }
    float acc[13];
#pragma unroll
    for (int i = 0; i < 13; i++) acc[i] = 0.f;
    __syncthreads();

    for (int c = 0; c < 5; c++) {
        int n0 = (split * 5 + c) * 128;
        int nc = min(128, NTOK - n0);

        for (int idx = t; idx < 128 * 64; idx += 256) {
            int r = idx >> 6, dd = idx & 63;
            ks[r * 65 + dd] = (r < nc)
                ? g_qkv[((size_t)b * NTOK + n0 + r) * 1536 + DIM + h * HD + dd] : 0.f;
        }
        __syncthreads();

        // scores + bias via packed f32x2: own k-row in 32 u64 regs, 2 indep chains
        {
            u64 k2[32];
#pragma unroll
            for (int d2 = 0; d2 < 32; d2++)
                PACK2F(k2[d2], ks[nl_own * 65 + 2 * d2], ks[nl_own * 65 + 2 * d2 + 1]);
            bool valid = nl_own < nc;
#pragma unroll 1
            for (int a = a_beg; a < a_end; a++) {
                u64 accA = 0, accB = 0;
                const u64* ah2 = (const u64*)(ah_s + a * 64);
#pragma unroll
                for (int d2 = 0; d2 < 16; d2++) {
                    FMA2(accA, k2[2 * d2], ah2[2 * d2]);
                    FMA2(accB, k2[2 * d2 + 1], ah2[2 * d2 + 1]);
                }
                float loA, hiA, loB, hiB;
                UNPACK2F(loA, hiA, accA);
                UNPACK2F(loB, hiB, accB);
                sc[a * 128 + nl_own] = valid
                    ? ((loA + hiA) + (loB + hiB)
                       + g_bias1[(h * AGENT + a) * NTOK + n0 + nl_own]) : -1e30f;
            }
        }
        __syncthreads();

        // stage v chunk into ks (k tile is dead now; stride 64, 16B-aligned)
        for (int idx = t; idx < 2048; idx += 256) {
            int r = idx >> 4, f4 = (idx & 15) << 2;
            if (r < nc) {
                const float4 vv4 = *(const float4*)&g_qkv[
                    ((size_t)b * NTOK + n0 + r) * 1536 + 1024 + h * HD + f4];
                *(float4*)&ks[r * 64 + f4] = vv4;
            }
        }
        // per-row online stats (8 warps cover 49 rows) — concurrent with v staging
        for (int a = warp; a < AGENT; a += 8) {
            float cm = -1e30f;
            for (int i = lane; i < 128; i += 32) cm = fmaxf(cm, sc[a * 128 + i]);
            for (int off = 16; off; off >>= 1)
                cm = fmaxf(cm, __shfl_xor_sync(0xffffffffu, cm, off));
            float mo = mrow[a];
            float nm = fmaxf(mo, cm);
            float f = __expf(mo - nm);
            float rs = 0.f;
            for (int i = lane; i < 128; i += 32) {
                float p = __expf(sc[a * 128 + i] - nm);
                sc[a * 128 + i] = p;
                rs += p;
            }
            for (int off = 16; off; off >>= 1)
                rs += __shfl_xor_sync(0xffffffffu, rs, off);
            if (lane == 0) { mrow[a] = nm; srow[a] = srow[a] * f + rs; frow[a] = f; }
        }
        __syncthreads();

#pragma unroll
        for (int i = 0; i < 13; i++)
            if (i < cnt) acc[i] *= frow[base + i];
        for (int nl = 0; nl < nc; nl++) {
            float vv = ks[nl * 64 + d];
#pragma unroll
            for (int i = 0; i < 13; i++)
                if (i < cnt) acc[i] += sc[(base + i) * 128 + nl] * vv;
        }
        __syncthreads();
    }

    size_t pb_ = (((size_t)(b * HEADS + h)) * S1SPLIT + split) * AGENT;
#pragma unroll
    for (int i = 0; i < 13; i++)
        if (i < cnt) g_pacc[(pb_ + base + i) * HD + d] = acc[i];
    if (t < AGENT) { g_pm[pb_ + t] = mrow[t]; g_ps[pb_ + t] = srow[t]; }
}

__global__ __launch_bounds__(256) void k_s1merge() {
    int bh = blockIdx.x;
    int t = threadIdx.x;
    for (int idx = t; idx < AGENT * HD; idx += 256) {
        int a = idx >> 6, d = idx & 63;
        size_t p0 = ((size_t)bh * S1SPLIT) * AGENT + a;
        float nm = -1e30f;
        for (int s = 0; s < S1SPLIT; s++) nm = fmaxf(nm, g_pm[p0 + s * AGENT]);
        float S = 0.f, A = 0.f;
        for (int s = 0; s < S1SPLIT; s++) {
            float w = __expf(g_pm[p0 + s * AGENT] - nm);
            S += g_ps[p0 + s * AGENT] * w;
            A += g_pacc[(p0 + s * AGENT) * HD + d] * w;
        }
        g_agentv[((size_t)bh * AGENT + a) * HD + d] = A / S;
    }
}

// ---------------- stage 2: q->agent attention (2 threads/token, f32x2) ----------------
// smem layout (floats): ah0 @0 (49*32), ah1 @1576, av0 @3152, av1 @4728,
//                       qs @6296 (128*65), bsm @14616 (128*49)  -> total 20888
#define S2_AH0 0
#define S2_AH1 1576
#define S2_AV0 3152
#define S2_AV1 4728
#define S2_QS  6296
#define S2_BSM 14616
#define S2_SMEM_FLOATS 20888
__global__ __launch_bounds__(256) void k_s2() {
    extern __shared__ float sm[];
    float* qs  = sm + S2_QS;
    float* bsm = sm + S2_BSM;
    int chunk = blockIdx.x, h = blockIdx.y, b = blockIdx.z;
    int t = threadIdx.x;
    int tok = t >> 1, half = t & 1;
    int n0 = chunk * 128;

    // load agent q/v into split planes (dims 0-31 -> plane0, 32-63 -> plane1)
    for (int idx = t; idx < AGENT * HD; idx += 256) {
        int a = idx >> 6, d = idx & 63;
        int off = (d < 32) ? (a * 32 + d) : (1576 + a * 32 + (d - 32));
        sm[S2_AH0 + off] = g_agent[((size_t)b * AGENT + a) * DIM + h * HD + d] * 0.125f;
        sm[S2_AV0 + off] = g_agentv[((size_t)(b * HEADS + h)) * AGENT * HD + idx];
    }
    for (int idx = t; idx < 128 * 64; idx += 256) {
        int r = idx >> 6, d = idx & 63;
        int n = n0 + r;
        qs[r * 65 + d] = (n < NTOK)
            ? g_qkv[((size_t)b * NTOK + n) * 1536 + h * HD + d] : 0.f;
    }
    for (int idx = t; idx < 128 * AGENT; idx += 256) {
        if (n0 * AGENT + idx < NTOK * AGENT)
            bsm[idx] = g_bias2[(size_t)h * NTOK * AGENT + (size_t)n0 * AGENT + idx];
    }
    __syncthreads();

    int n = n0 + tok;
    u32 vmask = __ballot_sync(0xffffffffu, n < NTOK);   // uniform per warp (64-token tail)
    if (n < NTOK) {
        // pack own 32-dim half of q
        const float* qrow = qs + tok * 65 + half * 32;
        u64 q2[16];
#pragma unroll
        for (int d2 = 0; d2 < 16; d2++)
            PACK2F(q2[d2], qrow[2 * d2], qrow[2 * d2 + 1]);

        const float* ahp = sm + (half ? S2_AH1 : S2_AH0);
        const int a0 = half ? 25 : 0, a1 = half ? 49 : 25;   // owned agents
        float m_loc = -1e30f;
#pragma unroll 1
        for (int a = 0; a < AGENT; a++) {
            u64 acc2 = 0;
            const u64* ah2 = (const u64*)(ahp + a * 32);
#pragma unroll
            for (int d2 = 0; d2 < 16; d2++) FMA2(acc2, q2[d2], ah2[d2]);
            float lo, hi; UNPACK2F(lo, hi, acc2);
            float part = lo + hi;
            float full = part + __shfl_xor_sync(vmask, part, 1);
            if (a >= a0 && a < a1) {
                float s = full + bsm[tok * AGENT + a];
                bsm[tok * AGENT + a] = s;
                m_loc = fmaxf(m_loc, s);
            }
        }
        float m = fmaxf(m_loc, __shfl_xor_sync(vmask, m_loc, 1));
        float sum_loc = 0.f;
        for (int a = a0; a < a1; a++) {
            float p = __expf(bsm[tok * AGENT + a] - m);
            bsm[tok * AGENT + a] = p;
            sum_loc += p;
        }
        float sum = sum_loc + __shfl_xor_sync(vmask, sum_loc, 1);
        float inv = 1.f / sum;
        __syncwarp(vmask);   // partner's prob writes visible

        const float* avp = sm + (half ? S2_AV1 : S2_AV0);
        u64 o2[16];
#pragma unroll
        for (int d2 = 0; d2 < 16; d2++) o2[d2] = 0;
#pragma unroll 1
        for (int a = 0; a < AGENT; a++) {
            float p = bsm[tok * AGENT + a];
            u64 p2; PACK2F(p2, p, p);
            const u64* av2 = (const u64*)(avp + a * 32);
#pragma unroll
            for (int d2 = 0; d2 < 16; d2++) FMA2(o2[d2], p2, av2[d2]);
        }
        float* orow = qs + tok * 65 + half * 32;
#pragma unroll
        for (int d2 = 0; d2 < 16; d2++) {
            float lo, hi; UNPACK2F(lo, hi, o2[d2]);
            orow[2 * d2] = lo * inv;
            orow[2 * d2 + 1] = hi * inv;
        }
    }
    __syncthreads();
    for (int idx = t; idx < 128 * 64; idx += 256) {
        int r = idx >> 6, dd = idx & 63;
        int nn = n0 + r;
        if (nn < NTOK)
            g_attnout[((size_t)b * NTOK + nn) * DIM + h * HD + dd] = qs[r * 65 + dd];
    }
}

// ---------------- depthwise 3x3 conv on v + attn residual -> bf16 hi/lo ----------------
__global__ __launch_bounds__(256) void k_dwc(const float* __restrict__ w_dwc,
                                             const float* __restrict__ b_dwc) {
    int y = blockIdx.x, b = blockIdx.y, t = threadIdx.x;
    int c = (t & 127) * 4;
    int xh = t >> 7;
    float wreg[4][9], bd[4];
#pragma unroll
    for (int j = 0; j < 4; j++) {
        bd[j] = b_dwc[c + j];
#pragma unroll
        for (int kk = 0; kk < 9; kk++) wreg[j][kk] = w_dwc[(c + j) * 9 + kk];
    }
    for (int x = xh; x < WWID; x += 2) {
        float a0 = bd[0], a1 = bd[1], a2 = bd[2], a3 = bd[3];
#pragma unroll
        for (int ky = 0; ky < 3; ky++) {
            int yy = y + ky - 1;
            if ((unsigned)yy >= HH) continue;
#pragma unroll
            for (int kx = 0; kx < 3; kx++) {
                int xx = x + kx - 1;
                if ((unsigned)xx >= WWID) continue;
                const float4 v = *(const float4*)&g_qkv[
                    (((size_t)b * NTOK) + yy * WWID + xx) * 1536 + 1024 + c];
                int kk = ky * 3 + kx;
                a0 += v.x * wreg[0][kk];
                a1 += v.y * wreg[1][kk];
                a2 += v.z * wreg[2][kk];
                a3 += v.w * wreg[3][kk];
            }
        }
        size_t m = ((size_t)b * NTOK) + y * WWID + x;
        const float4 cur = *(const float4*)&g_attnout[m * DIM + c];
        a0 += cur.x; a1 += cur.y; a2 += cur.z; a3 += cur.w;
        u32 h0 = f2bf(a0), h1 = f2bf(a1), h2 = f2bf(a2), h3 = f2bf(a3);
        u32* dh = (u32*)&g_aohl[m * 1024 + c];
        dh[0] = h0 | (h1 << 16);
        dh[1] = h2 | (h3 << 16);
        u32* dl = (u32*)&g_aohl[m * 1024 + 512 + c];
        dl[0] = pack2(a0 - bf2f(h0), a1 - bf2f(h1));
        dl[1] = pack2(a2 - bf2f(h2), a3 - bf2f(h3));
    }
}

// ---------------- launcher ----------------
extern "C" void kernel_launch(void* const* d_in, const int* in_sizes, int n_in,
                              void* d_out, int out_size) {
    const float* x      = (const float*)d_in[0];
    const float* w_qkv  = (const float*)d_in[1];
    const float* w_proj = (const float*)d_in[2];
    const float* b_proj = (const float*)d_in[3];
    const float* w_dwc  = (const float*)d_in[4];
    const float* b_dwc  = (const float*)d_in[5];
    const float* an     = (const float*)d_in[6];
    const float* na     = (const float*)d_in[7];
    const float* ahb    = (const float*)d_in[8];
    const float* awb    = (const float*)d_in[9];
    const float* hab    = (const float*)d_in[10];
    const float* wab    = (const float*)d_in[11];
    const float* cab    = (const float*)d_in[12];
    float* out = (float*)d_out;

    void *p_qkv = 0, *p_xhl = 0, *p_aohl = 0, *p_wq = 0, *p_wp = 0;
    cudaGetSymbolAddress(&p_qkv, g_qkv);
    cudaGetSymbolAddress(&p_xhl, g_xhl);
    cudaGetSymbolAddress(&p_aohl, g_aohl);
    cudaGetSymbolAddress(&p_wq, g_wqkvhl);
    cudaGetSymbolAddress(&p_wp, g_wprojhl);
    float* qkv = (float*)p_qkv;
    unsigned short* xhl = (unsigned short*)p_xhl;
    unsigned short* aohl = (unsigned short*)p_aohl;
    unsigned short* wqhl = (unsigned short*)p_wq;
    unsigned short* wphl = (unsigned short*)p_wp;

    cudaFuncSetAttribute(k_gemm, cudaFuncAttributeMaxDynamicSharedMemorySize, GSMEM_TOTAL);
    cudaFuncSetAttribute(k_s1, cudaFuncAttributeMaxDynamicSharedMemorySize,
                         S1_SMEM_FLOATS * (int)sizeof(float));
    cudaFuncSetAttribute(k_s2, cudaFuncAttributeMaxDynamicSharedMemorySize,
                         S2_SMEM_FLOATS * (int)sizeof(float));

    const int M = BB * NTOK;   // 50176

    // bf16 hi/lo conversions
    k_cvt<<<(M * 128 + 255) / 256, 256>>>(x, xhl, M * 128);
    k_cvt<<<(1536 * 128 + 255) / 256, 256>>>(w_qkv, wqhl, 1536 * 128);
    k_cvt<<<(512 * 128 + 255) / 256, 256>>>(w_proj, wphl, 512 * 128);

    // QKV GEMM: (50176,512)x(1536,512)^T -> (50176,1536) via HMMA bf16x3
    k_gemm<<<dim3(1536 / 128, M / 128), 256, GSMEM_TOTAL>>>(xhl, wqhl, 0, qkv, 1536);

    // bias tables (b-independent)
    k_pb<<<HEADS * AGENT, WW2>>>(an, ahb, awb);
    k_ab<<<(HEADS * 197 * AGENT + 255) / 256, 256>>>(na, hab, wab, cab);
    k_bias1<<<(HEADS * AGENT * NTOK + 255) / 256, 256>>>();
    k_bias2<<<(HEADS * NTOK * AGENT + 255) / 256, 256>>>();

    // agent pooling
    k_agent<<<BB * AGENT, DIM>>>();

    // stage 1: fused flash attention, split-KV + merge
    k_s1<<<dim3(S1SPLIT, HEADS, BB), 256, S1_SMEM_FLOATS * (int)sizeof(float)>>>();
    k_s1merge<<<BB * HEADS, 256>>>();

    // stage 2 (writes g_attnout)
    k_s2<<<dim3(25, HEADS, BB), 256, S2_SMEM_FLOATS * (int)sizeof(float)>>>();

    // depthwise conv residual, fused fp32->bf16 split (writes g_aohl)
    k_dwc<<<dim3(HH, BB), 256>>>(w_dwc, b_dwc);

    // projection GEMM with bias -> final fp32 output
    k_gemm<<<dim3(512 / 128, M / 128), 256, GSMEM_TOTAL>>>(aohl, wphl, b_proj, out, 512);
}

// round 17
// speedup vs baseline: 2.0294x; 1.0384x over previous
#include <cuda_runtime.h>
#include <math.h>

typedef unsigned int u32;
typedef unsigned long long u64;

// ---------------- problem constants ----------------
#define BB    16
#define NTOK  3136
#define DIM   512
#define HH    56
#define WWID  56
#define HEADS 8
#define HD    64
#define AGENT 49
#define WIN   14
#define WW2   196   // 14*14
#define S1SPLIT 5

// ---------------- packed f32x2 helpers (B300 FFMA2) ----------------
#define FMA2(c, a, b) asm("fma.rn.f32x2 %0, %1, %2, %0;" : "+l"(c) : "l"(a), "l"(b))
#define MUL2(c, a) asm("mul.rn.f32x2 %0, %0, %1;" : "+l"(c) : "l"(a))
#define PACK2F(out, lo, hi) asm("mov.b64 %0, {%1, %2};" : "=l"(out) : "f"(lo), "f"(hi))
#define UNPACK2F(lo, hi, in) asm("mov.b64 {%0, %1}, %2;" : "=f"(lo), "=f"(hi) : "l"(in))

// ---------------- scratch (device globals; no allocation allowed) ----------------
__device__ float g_qkv[(size_t)BB * NTOK * 3 * DIM];            // fp32 qkv
__device__ float g_attnout[(size_t)BB * NTOK * DIM];            // attention only
__device__ unsigned short g_xhl[(size_t)BB * NTOK * 2 * DIM];   // x hi/lo bf16 bits
__device__ unsigned short g_aohl[(size_t)BB * NTOK * 2 * DIM];  // attn+dwc hi/lo bf16 bits
__device__ unsigned short g_wqkvhl[3 * DIM * 2 * DIM];
__device__ unsigned short g_wprojhl[DIM * 2 * DIM];
__device__ float g_agent[BB * AGENT * DIM];
__device__ float g_agentv[BB * HEADS * AGENT * HD];
__device__ float g_pacc[(size_t)BB * HEADS * S1SPLIT * AGENT * HD];
__device__ float g_pm[BB * HEADS * S1SPLIT * AGENT];
__device__ float g_ps[BB * HEADS * S1SPLIT * AGENT];
__device__ float g_pb[HEADS * AGENT * WW2];
__device__ float g_ab[HEADS * 197 * AGENT];
__device__ float g_bias1[HEADS * AGENT * NTOK];
__device__ float g_bias2[HEADS * NTOK * AGENT];

// ---------------- manual bf16 helpers (no cuda_bf16 types) ----------------
__device__ __forceinline__ u32 f2bf(float f) {           // round-to-nearest-even
    u32 u = __float_as_uint(f);
    return (u + 0x7fffu + ((u >> 16) & 1u)) >> 16;
}
__device__ __forceinline__ float bf2f(u32 b) { return __uint_as_float(b << 16); }
__device__ __forceinline__ u32 pack2(float lo, float hi) {
    return f2bf(lo) | (f2bf(hi) << 16);
}

// ---------------- bilinear helpers (jax half-pixel + clamp semantics) ----------------
__device__ __forceinline__ float bil7(const float* __restrict__ A, int wy, int wx) {
    float sy = (wy + 0.5f) * 0.5f - 0.5f;
    float sx = (wx + 0.5f) * 0.5f - 0.5f;
    sy = fminf(fmaxf(sy, 0.f), 6.f);
    sx = fminf(fmaxf(sx, 0.f), 6.f);
    int y0 = (int)sy; float fy = sy - y0; int y1 = min(y0 + 1, 6);
    int x0 = (int)sx; float fx = sx - x0; int x1 = min(x0 + 1, 6);
    float v00 = A[y0 * 7 + x0], v01 = A[y0 * 7 + x1];
    float v10 = A[y1 * 7 + x0], v11 = A[y1 * 7 + x1];
    return (1.f - fy) * ((1.f - fx) * v00 + fx * v01) +
           fy * ((1.f - fx) * v10 + fx * v11);
}

__global__ void k_pb(const float* __restrict__ an, const float* __restrict__ ahb,
                     const float* __restrict__ awb) {
    int ha = blockIdx.x;
    int t = threadIdx.x;
    if (t >= WW2) return;
    int wy = t / WIN, wx = t % WIN;
    float v = bil7(an + ha * 49, wy, wx);
    g_pb[ha * WW2 + t] = v + ahb[ha * WIN + wy] + awb[ha * WIN + wx];
}

__global__ void k_ab(const float* __restrict__ na, const float* __restrict__ hab,
                     const float* __restrict__ wab, const float* __restrict__ cab) {
    int tid = blockIdx.x * blockDim.x + threadIdx.x;
    int total = HEADS * 197 * AGENT;
    if (tid >= total) return;
    int h = tid / (197 * AGENT);
    int r = (tid / AGENT) % 197;
    int a = tid % AGENT;
    float v;
    if (r == 0) {
        v = cab[h * AGENT + a];
    } else {
        int t = r - 1;
        int wy = t / WIN, wx = t % WIN;
        v = bil7(na + (h * AGENT + a) * 49, wy, wx)
          + hab[(h * WIN + wy) * AGENT + a]
          + wab[(h * WIN + wx) * AGENT + a];
    }
    g_ab[(h * 197 + r) * AGENT + a] = v;
}

__global__ void k_bias1() {
    int tid = blockIdx.x * blockDim.x + threadIdx.x;
    int total = HEADS * AGENT * NTOK;
    if (tid >= total) return;
    int ha = tid / NTOK;
    int n = tid % NTOK;
    float s = (n + 0.5f) * 0.0625f - 0.5f;
    s = fminf(fmaxf(s, 0.f), 195.f);
    int t0 = (int)s; float f = s - t0; int t1 = min(t0 + 1, 195);
    g_bias1[tid] = g_pb[ha * WW2 + t0] * (1.f - f) + g_pb[ha * WW2 + t1] * f;
}

__global__ void k_bias2() {
    int tid = blockIdx.x * blockDim.x + threadIdx.x;
    int total = HEADS * NTOK * AGENT;
    if (tid >= total) return;
    int h = tid / (NTOK * AGENT);
    int rem = tid % (NTOK * AGENT);
    int n = rem / AGENT;
    int a = rem % AGENT;
    float s = (n + 0.5f) * (197.0f / 3136.0f) - 0.5f;
    s = fminf(fmaxf(s, 0.f), 196.f);
    int r0 = (int)s; float f = s - r0; int r1 = min(r0 + 1, 196);
    g_bias2[tid] = g_ab[(h * 197 + r0) * AGENT + a] * (1.f - f)
                 + g_ab[(h * 197 + r1) * AGENT + a] * f;
}

// ---------------- fp32 -> bf16 hi/lo split conversion ----------------
// src: [M, 512] fp32 row-major. dst: [M, 1024] bf16-bits, row = [hi(512) | lo(512)]
__global__ void k_cvt(const float* __restrict__ src, unsigned short* __restrict__ dst,
                      int total4) {
    int idx = blockIdx.x * 256 + threadIdx.x;
    if (idx >= total4) return;
    int m = idx >> 7;            // /128  (512/4 groups per row)
    int k4 = (idx & 127) << 2;
    float4 v = *(const float4*)(src + (size_t)m * 512 + k4);
    u32 h0 = f2bf(v.x), h1 = f2bf(v.y), h2 = f2bf(v.z), h3 = f2bf(v.w);
    float r0 = v.x - bf2f(h0), r1 = v.y - bf2f(h1);
    float r2 = v.z - bf2f(h2), r3 = v.w - bf2f(h3);
    u32* dh = (u32*)(dst + (size_t)m * 1024 + k4);
    dh[0] = h0 | (h1 << 16);
    dh[1] = h2 | (h3 << 16);
    u32* dl = (u32*)(dst + (size_t)m * 1024 + 512 + k4);
    dl[0] = pack2(r0, r1);
    dl[1] = pack2(r2, r3);
}

// ================= bf16x3 GEMM via mma.sync (HMMA, base sm_103-safe) =================
// C[M,N] = A[M,512]*B[N,512]^T (+bias). A/B rows: 1024 bf16 = [hi(512)|lo(512)].
// CTA tile 128x128, 256 thr (8 warps 4x2, warp tile 32x64), BK=32,
// 2-stage cp.async double buffer (80KB) -> 2 CTAs/SM.  (R12 inner-loop ordering.)

#define G_PLANE 10240                       // 128 * 80 bytes
#define G_STAGE (4 * G_PLANE)               // 40960
#define G_NSTG  2
#define GSMEM_TOTAL (G_NSTG * G_STAGE)      // 81920

static __device__ __forceinline__ u32 smem_u32(const void* p) {
    u32 a;
    asm("{ .reg .u64 t; cvta.to.shared.u64 t, %1; cvt.u32.u64 %0, t; }" : "=r"(a) : "l"(p));
    return a;
}
static __device__ __forceinline__ void cpa16(u32 s, const void* g) {
    asm volatile("cp.async.cg.shared.global [%0], [%1], 16;" :: "r"(s), "l"(g) : "memory");
}
static __device__ __forceinline__ void ldsm4(u32* r, u32 addr) {
    asm volatile("ldmatrix.sync.aligned.m8n8.x4.shared.b16 {%0,%1,%2,%3}, [%4];"
        : "=r"(r[0]), "=r"(r[1]), "=r"(r[2]), "=r"(r[3]) : "r"(addr));
}
static __device__ __forceinline__ void mma16816(float* c, const u32* a, const u32* b) {
    asm volatile("mma.sync.aligned.m16n8k16.row.col.f32.bf16.bf16.f32 "
        "{%0,%1,%2,%3}, {%4,%5,%6,%7}, {%8,%9}, {%0,%1,%2,%3};"
        : "+f"(c[0]), "+f"(c[1]), "+f"(c[2]), "+f"(c[3])
        : "r"(a[0]), "r"(a[1]), "r"(a[2]), "r"(a[3]), "r"(b[0]), "r"(b[1]));
}

// load K-chunk c (32 halves per plane) for A rows m0..+128 and B rows n0..+128
static __device__ __forceinline__ void load_chunk(
    u32 buf, const unsigned short* __restrict__ A, const unsigned short* __restrict__ B,
    int m0, int n0, int c, int tid)
{
    for (int idx = tid; idx < 512; idx += 256) {
        int r = idx >> 2, seg = idx & 3;
        const unsigned short* g = A + (size_t)(m0 + r) * 1024 + c * 32 + seg * 8;
        u32 d = buf + r * 80 + seg * 16;
        cpa16(d, g);                 // A hi
        cpa16(d + G_PLANE, g + 512); // A lo
    }
    for (int idx = tid; idx < 512; idx += 256) {
        int r = idx >> 2, seg = idx & 3;
        const unsigned short* g = B + (size_t)(n0 + r) * 1024 + c * 32 + seg * 8;
        u32 d = buf + 2 * G_PLANE + r * 80 + seg * 16;
        cpa16(d, g);                 // B hi
        cpa16(d + G_PLANE, g + 512); // B lo
    }
    asm volatile("cp.async.commit_group;" ::: "memory");
}

__global__ __launch_bounds__(256, 2)
void k_gemm(const unsigned short* __restrict__ Ahl, const unsigned short* __restrict__ Bhl,
            const float* __restrict__ bias, float* __restrict__ C, int ldc)
{
    extern __shared__ char smem[];
    const u32 sb = smem_u32(smem);
    const int tid = threadIdx.x;
    const int wid = tid >> 5, lane = tid & 31;
    const int wm = wid >> 1, wn = wid & 1;       // 4 x 2 warp grid
    const int m0 = blockIdx.y * 128;
    const int n0 = blockIdx.x * 128;
    const int row_a = lane & 15;                 // ldmatrix row within 16
    const int kseg = lane >> 4;                  // 0/1 -> k halves 0-7 / 8-15

    float acc[2][8][4];
#pragma unroll
    for (int mt = 0; mt < 2; mt++)
#pragma unroll
        for (int j = 0; j < 8; j++)
#pragma unroll
            for (int q = 0; q < 4; q++) acc[mt][j][q] = 0.f;

    // prologue: fill both buffers
    load_chunk(sb + 0 * G_STAGE, Ahl, Bhl, m0, n0, 0, tid);
    load_chunk(sb + 1 * G_STAGE, Ahl, Bhl, m0, n0, 1, tid);

    // per-warp fragment offsets within a stage (buf-independent)
    const u32 aoff0 = (u32)((wm * 32 + row_a) * 80) + (u32)(kseg * 16);
    const u32 boff0 = 2 * G_PLANE + (u32)((wn * 64 + row_a) * 80) + (u32)(kseg * 16);

    for (int c = 0; c < 16; c++) {
        if (c < 15) asm volatile("cp.async.wait_group 1;" ::: "memory");
        else        asm volatile("cp.async.wait_group 0;" ::: "memory");
        __syncthreads();

        const u32 buf = sb + (c & 1) * G_STAGE;
#pragma unroll
        for (int ks = 0; ks < 2; ks++) {
            const u32 kb = ks * 32;
            u32 ah[2][4], al[2][4], bh[8][2], bl[8][2];
#pragma unroll
            for (int mt = 0; mt < 2; mt++) {
                u32 ad = buf + aoff0 + mt * (16 * 80) + kb;
                ldsm4(ah[mt], ad);
                ldsm4(al[mt], ad + G_PLANE);
            }
#pragma unroll
            for (int nt = 0; nt < 4; nt++) {
                u32 bd = buf + boff0 + nt * (16 * 80) + kb;
                u32 r[4];
                ldsm4(r, bd);
                bh[2 * nt][0] = r[0]; bh[2 * nt + 1][0] = r[1];
                bh[2 * nt][1] = r[2]; bh[2 * nt + 1][1] = r[3];
                ldsm4(r, bd + G_PLANE);
                bl[2 * nt][0] = r[0]; bl[2 * nt + 1][0] = r[1];
                bl[2 * nt][1] = r[2]; bl[2 * nt + 1][1] = r[3];
            }
#pragma unroll
            for (int mt = 0; mt < 2; mt++)
#pragma unroll
                for (int j = 0; j < 8; j++) {
                    mma16816(acc[mt][j], ah[mt], bh[j]);
                    mma16816(acc[mt][j], ah[mt], bl[j]);
                    mma16816(acc[mt][j], al[mt], bh[j]);
                }
        }
        __syncthreads();
        if (c + 2 < 16)
            load_chunk(buf, Ahl, Bhl, m0, n0, c + 2, tid);
    }

    // epilogue: direct float2 stores (+bias)
    const int gq = lane >> 2, tg = lane & 3;
#pragma unroll
    for (int mt = 0; mt < 2; mt++) {
        int row = m0 + wm * 32 + mt * 16 + gq;
#pragma unroll
        for (int j = 0; j < 8; j++) {
            int col = n0 + wn * 64 + j * 8 + tg * 2;
            float b0 = 0.f, b1 = 0.f;
            if (bias) { b0 = bias[col]; b1 = bias[col + 1]; }
            float2 v0 = make_float2(acc[mt][j][0] + b0, acc[mt][j][1] + b1);
            float2 v1 = make_float2(acc[mt][j][2] + b0, acc[mt][j][3] + b1);
            *(float2*)&C[(size_t)row * ldc + col] = v0;
            *(float2*)&C[(size_t)(row + 8) * ldc + col] = v1;
        }
    }
}

// ---------------- agent pooling: exact 8x8 block mean of q ----------------
__global__ void k_agent() {
    int b = blockIdx.x / AGENT;
    int a = blockIdx.x % AGENT;
    int py = a / 7, px = a % 7;
    int c = threadIdx.x;
    float s = 0.f;
#pragma unroll 4
    for (int dy = 0; dy < 8; dy++)
        for (int dx = 0; dx < 8; dx++) {
            int n = (py * 8 + dy) * WWID + px * 8 + dx;
            s += g_qkv[((size_t)b * NTOK + n) * 1536 + c];
        }
    g_agent[((size_t)b * AGENT + a) * DIM + c] = s * (1.f / 64.f);
}

// ---------------- stage 1 (fused flash, split-KV) ----------------
#define S1_SMEM_FLOATS (3136 + 128 * 65 + 49 * 128 + 192)
__global__ __launch_bounds__(256) void k_s1() {
    extern __shared__ float sm[];
    float* ah_s = sm;
    float* ks   = sm + 3136;          // k tile during scores; reused as v tile after
    float* sc   = sm + 3136 + 8320;
    float* mrow = sc + 6272;
    float* srow = mrow + 64;
    float* frow = srow + 64;
    int split = blockIdx.x, h = blockIdx.y, b = blockIdx.z;
    int t = threadIdx.x, warp = t >> 5, lane = t & 31;
    int g = t >> 6, d = t & 63;
    const int base = (g == 0) ? 0 : (13 + 12 * (g - 1));
    const int cnt = (g == 0) ? 13 : 12;
    // f32x2 scores ownership: thread owns k-row nl_own, half the agent range
    const int nl_own = t & 127;
    const int a_beg = (t >> 7) ? 25 : 0;
    const int a_end = (t >> 7) ? 49 : 25;

    for (int idx = t; idx < AGENT * HD; idx += 256) {
        int a = idx >> 6, dd = idx & 63;
        ah_s[idx] = g_agent[((size_t)b * AGENT + a) * DIM + h * HD + dd] * 0.125f;
    }
    if (t < AGENT) { mrow[t] = -1e30f; srow[t] = 0.f; }
    u64 acc2[13];
#pragma unroll
    for (int i = 0; i < 13; i++) acc2[i] = 0;
    __syncthreads();

    for (int c = 0; c < 5; c++) {
        int n0 = (split * 5 + c) * 128;
        int nc = min(128, NTOK - n0);

        // k tile load: LDG.128 + 4 scalar STS into pitch-65 (conflict-free reads)
        for (int idx = t; idx < 2048; idx += 256) {
            int r = idx >> 4, f4 = (idx & 15) << 2;
            if (r < nc) {
                const float4 kv4 = *(const float4*)&g_qkv[
                    ((size_t)b * NTOK + n0 + r) * 1536 + DIM + h * HD + f4];
                ks[r * 65 + f4 + 0] = kv4.x;
                ks[r * 65 + f4 + 1] = kv4.y;
                ks[r * 65 + f4 + 2] = kv4.z;
                ks[r * 65 + f4 + 3] = kv4.w;
            } else {
                ks[r * 65 + f4 + 0] = 0.f;
                ks[r * 65 + f4 + 1] = 0.f;
                ks[r * 65 + f4 + 2] = 0.f;
                ks[r * 65 + f4 + 3] = 0.f;
            }
        }
        __syncthreads();

        // scores + bias via packed f32x2: own k-row in 32 u64 regs, 2 indep chains
        {
            u64 k2[32];
#pragma unroll
            for (int d2 = 0; d2 < 32; d2++)
                PACK2F(k2[d2], ks[nl_own * 65 + 2 * d2], ks[nl_own * 65 + 2 * d2 + 1]);
            bool valid = nl_own < nc;
#pragma unroll 1
            for (int a = a_beg; a < a_end; a++) {
                u64 accA = 0, accB = 0;
                const u64* ah2 = (const u64*)(ah_s + a * 64);
#pragma unroll
                for (int d2 = 0; d2 < 16; d2++) {
                    FMA2(accA, k2[2 * d2], ah2[2 * d2]);
                    FMA2(accB, k2[2 * d2 + 1], ah2[2 * d2 + 1]);
                }
                float loA, hiA, loB, hiB;
                UNPACK2F(loA, hiA, accA);
                UNPACK2F(loB, hiB, accB);
                sc[a * 128 + nl_own] = valid
                    ? ((loA + hiA) + (loB + hiB)
                       + g_bias1[(h * AGENT + a) * NTOK + n0 + nl_own]) : -1e30f;
            }
        }
        __syncthreads();

        // stage v chunk into ks (k tile is dead now; stride 64, 16B-aligned)
        for (int idx = t; idx < 2048; idx += 256) {
            int r = idx >> 4, f4 = (idx & 15) << 2;
            if (r < nc) {
                const float4 vv4 = *(const float4*)&g_qkv[
                    ((size_t)b * NTOK + n0 + r) * 1536 + 1024 + h * HD + f4];
                *(float4*)&ks[r * 64 + f4] = vv4;
            }
        }
        // per-row online stats (8 warps cover 49 rows) — concurrent with v staging
        for (int a = warp; a < AGENT; a += 8) {
            float cm = -1e30f;
            for (int i = lane; i < 128; i += 32) cm = fmaxf(cm, sc[a * 128 + i]);
            for (int off = 16; off; off >>= 1)
                cm = fmaxf(cm, __shfl_xor_sync(0xffffffffu, cm, off));
            float mo = mrow[a];
            float nm = fmaxf(mo, cm);
            float f = __expf(mo - nm);
            float rs = 0.f;
            for (int i = lane; i < 128; i += 32) {
                float p = __expf(sc[a * 128 + i] - nm);
                sc[a * 128 + i] = p;
                rs += p;
            }
            for (int off = 16; off; off >>= 1)
                rs += __shfl_xor_sync(0xffffffffu, rs, off);
            if (lane == 0) { mrow[a] = nm; srow[a] = srow[a] * f + rs; frow[a] = f; }
        }
        __syncthreads();

        // rescale accumulators by frow (both lanes)
#pragma unroll
        for (int i = 0; i < 13; i++)
            if (i < cnt) {
                float f = frow[base + i];
                u64 f2; PACK2F(f2, f, f);
                MUL2(acc2[i], f2);
            }
        // V accumulation over nl-pairs: prob pairs via broadcast LDS.64,
        // v pair packed from two scalar LDS (lo lane = even nl, hi = odd nl)
        {
            int nh = nc >> 1;            // nc is 128 or 64 -> always even
#pragma unroll 1
            for (int j = 0; j < nh; j++) {
                u64 v2;
                PACK2F(v2, ks[(2 * j) * 64 + d], ks[(2 * j + 1) * 64 + d]);
#pragma unroll
                for (int i = 0; i < 13; i++)
                    if (i < cnt) {
                        u64 p2 = *(const u64*)&sc[(base + i) * 128 + 2 * j];
                        FMA2(acc2[i], p2, v2);
                    }
            }
        }
        __syncthreads();
    }

    size_t pb_ = (((size_t)(b * HEADS + h)) * S1SPLIT + split) * AGENT;
#pragma unroll
    for (int i = 0; i < 13; i++)
        if (i < cnt) {
            float lo, hi; UNPACK2F(lo, hi, acc2[i]);
            g_pacc[(pb_ + base + i) * HD + d] = lo + hi;
        }
    if (t < AGENT) { g_pm[pb_ + t] = mrow[t]; g_ps[pb_ + t] = srow[t]; }
}

__global__ __launch_bounds__(256) void k_s1merge() {
    int bh = blockIdx.x;
    int t = threadIdx.x;
    for (int idx = t; idx < AGENT * HD; idx += 256) {
        int a = idx >> 6, d = idx & 63;
        size_t p0 = ((size_t)bh * S1SPLIT) * AGENT + a;
        float nm = -1e30f;
        for (int s = 0; s < S1SPLIT; s++) nm = fmaxf(nm, g_pm[p0 + s * AGENT]);
        float S = 0.f, A = 0.f;
        for (int s = 0; s < S1SPLIT; s++) {
            float w = __expf(g_pm[p0 + s * AGENT] - nm);
            S += g_ps[p0 + s * AGENT] * w;
            A += g_pacc[(p0 + s * AGENT) * HD + d] * w;
        }
        g_agentv[((size_t)bh * AGENT + a) * HD + d] = A / S;
    }
}

// ---------------- stage 2: q->agent attention (2 threads/token, f32x2) ----------------
// smem layout (floats): ah0 @0 (49*32), ah1 @1576, av0 @3152, av1 @4728,
//                       qs @6296 (128*65), bsm @14616 (128*49)  -> total 20888
#define S2_AH0 0
#define S2_AH1 1576
#define S2_AV0 3152
#define S2_AV1 4728
#define S2_QS  6296
#define S2_BSM 14616
#define S2_SMEM_FLOATS 20888
__global__ __launch_bounds__(256) void k_s2() {
    extern __shared__ float sm[];
    float* qs  = sm + S2_QS;
    float* bsm = sm + S2_BSM;
    int chunk = blockIdx.x, h = blockIdx.y, b = blockIdx.z;
    int t = threadIdx.x;
    int tok = t >> 1, half = t & 1;
    int n0 = chunk * 128;

    // load agent q/v into split planes (dims 0-31 -> plane0, 32-63 -> plane1)
    for (int idx = t; idx < AGENT * HD; idx += 256) {
        int a = idx >> 6, d = idx & 63;
        int off = (d < 32) ? (a * 32 + d) : (1576 + a * 32 + (d - 32));
        sm[S2_AH0 + off] = g_agent[((size_t)b * AGENT + a) * DIM + h * HD + d] * 0.125f;
        sm[S2_AV0 + off] = g_agentv[((size_t)(b * HEADS + h)) * AGENT * HD + idx];
    }
    for (int idx = t; idx < 128 * 64; idx += 256) {
        int r = idx >> 6, d = idx & 63;
        int n = n0 + r;
        qs[r * 65 + d] = (n < NTOK)
            ? g_qkv[((size_t)b * NTOK + n) * 1536 + h * HD + d] : 0.f;
    }
    for (int idx = t; idx < 128 * AGENT; idx += 256) {
        if (n0 * AGENT + idx < NTOK * AGENT)
            bsm[idx] = g_bias2[(size_t)h * NTOK * AGENT + (size_t)n0 * AGENT + idx];
    }
    __syncthreads();

    int n = n0 + tok;
    u32 vmask = __ballot_sync(0xffffffffu, n < NTOK);   // uniform per warp (64-token tail)
    if (n < NTOK) {
        // pack own 32-dim half of q
        const float* qrow = qs + tok * 65 + half * 32;
        u64 q2[16];
#pragma unroll
        for (int d2 = 0; d2 < 16; d2++)
            PACK2F(q2[d2], qrow[2 * d2], qrow[2 * d2 + 1]);

        const float* ahp = sm + (half ? S2_AH1 : S2_AH0);
        const int a0 = half ? 25 : 0, a1 = half ? 49 : 25;   // owned agents
        float m_loc = -1e30f;
#pragma unroll 1
        for (int a = 0; a < AGENT; a++) {
            u64 acc2 = 0;
            const u64* ah2 = (const u64*)(ahp + a * 32);
#pragma unroll
            for (int d2 = 0; d2 < 16; d2++) FMA2(acc2, q2[d2], ah2[d2]);
            float lo, hi; UNPACK2F(lo, hi, acc2);
            float part = lo + hi;
            float full = part + __shfl_xor_sync(vmask, part, 1);
            if (a >= a0 && a < a1) {
                float s = full + bsm[tok * AGENT + a];
                bsm[tok * AGENT + a] = s;
                m_loc = fmaxf(m_loc, s);
            }
        }
        float m = fmaxf(m_loc, __shfl_xor_sync(vmask, m_loc, 1));
        float sum_loc = 0.f;
        for (int a = a0; a < a1; a++) {
            float p = __expf(bsm[tok * AGENT + a] - m);
            bsm[tok * AGENT + a] = p;
            sum_loc += p;
        }
        float sum = sum_loc + __shfl_xor_sync(vmask, sum_loc, 1);
        float inv = 1.f / sum;
        __syncwarp(vmask);   // partner's prob writes visible

        const float* avp = sm + (half ? S2_AV1 : S2_AV0);
        u64 o2[16];
#pragma unroll
        for (int d2 = 0; d2 < 16; d2++) o2[d2] = 0;
#pragma unroll 1
        for (int a = 0; a < AGENT; a++) {
            float p = bsm[tok * AGENT + a];
            u64 p2; PACK2F(p2, p, p);
            const u64* av2 = (const u64*)(avp + a * 32);
#pragma unroll
            for (int d2 = 0; d2 < 16; d2++) FMA2(o2[d2], p2, av2[d2]);
        }
        float* orow = qs + tok * 65 + half * 32;
#pragma unroll
        for (int d2 = 0; d2 < 16; d2++) {
            float lo, hi; UNPACK2F(lo, hi, o2[d2]);
            orow[2 * d2] = lo * inv;
            orow[2 * d2 + 1] = hi * inv;
        }
    }
    __syncthreads();
    for (int idx = t; idx < 128 * 64; idx += 256) {
        int r = idx >> 6, dd = idx & 63;
        int nn = n0 + r;
        if (nn < NTOK)
            g_attnout[((size_t)b * NTOK + nn) * DIM + h * HD + dd] = qs[r * 65 + dd];
    }
}

// ---------------- depthwise 3x3 conv on v + attn residual -> bf16 hi/lo ----------------
__global__ __launch_bounds__(256) void k_dwc(const float* __restrict__ w_dwc,
                                             const float* __restrict__ b_dwc) {
    int y = blockIdx.x, b = blockIdx.y, t = threadIdx.x;
    int c = (t & 127) * 4;
    int xh = t >> 7;
    float wreg[4][9], bd[4];
#pragma unroll
    for (int j = 0; j < 4; j++) {
        bd[j] = b_dwc[c + j];
#pragma unroll
        for (int kk = 0; kk < 9; kk++) wreg[j][kk] = w_dwc[(c + j) * 9 + kk];
    }
    for (int x = xh; x < WWID; x += 2) {
        float a0 = bd[0], a1 = bd[1], a2 = bd[2], a3 = bd[3];
#pragma unroll
        for (int ky = 0; ky < 3; ky++) {
            int yy = y + ky - 1;
            if ((unsigned)yy >= HH) continue;
#pragma unroll
            for (int kx = 0; kx < 3; kx++) {
                int xx = x + kx - 1;
                if ((unsigned)xx >= WWID) continue;
                const float4 v = *(const float4*)&g_qkv[
                    (((size_t)b * NTOK) + yy * WWID + xx) * 1536 + 1024 + c];
                int kk = ky * 3 + kx;
                a0 += v.x * wreg[0][kk];
                a1 += v.y * wreg[1][kk];
                a2 += v.z * wreg[2][kk];
                a3 += v.w * wreg[3][kk];
            }
        }
        size_t m = ((size_t)b * NTOK) + y * WWID + x;
        const float4 cur = *(const float4*)&g_attnout[m * DIM + c];
        a0 += cur.x; a1 += cur.y; a2 += cur.z; a3 += cur.w;
        u32 h0 = f2bf(a0), h1 = f2bf(a1), h2 = f2bf(a2), h3 = f2bf(a3);
        u32* dh = (u32*)&g_aohl[m * 1024 + c];
        dh[0] = h0 | (h1 << 16);
        dh[1] = h2 | (h3 << 16);
        u32* dl = (u32*)&g_aohl[m * 1024 + 512 + c];
        dl[0] = pack2(a0 - bf2f(h0), a1 - bf2f(h1));
        dl[1] = pack2(a2 - bf2f(h2), a3 - bf2f(h3));
    }
}

// ---------------- launcher ----------------
extern "C" void kernel_launch(void* const* d_in, const int* in_sizes, int n_in,
                              void* d_out, int out_size) {
    const float* x      = (const float*)d_in[0];
    const float* w_qkv  = (const float*)d_in[1];
    const float* w_proj = (const float*)d_in[2];
    const float* b_proj = (const float*)d_in[3];
    const float* w_dwc  = (const float*)d_in[4];
    const float* b_dwc  = (const float*)d_in[5];
    const float* an     = (const float*)d_in[6];
    const float* na     = (const float*)d_in[7];
    const float* ahb    = (const float*)d_in[8];
    const float* awb    = (const float*)d_in[9];
    const float* hab    = (const float*)d_in[10];
    const float* wab    = (const float*)d_in[11];
    const float* cab    = (const float*)d_in[12];
    float* out = (float*)d_out;

    void *p_qkv = 0, *p_xhl = 0, *p_aohl = 0, *p_wq = 0, *p_wp = 0;
    cudaGetSymbolAddress(&p_qkv, g_qkv);
    cudaGetSymbolAddress(&p_xhl, g_xhl);
    cudaGetSymbolAddress(&p_aohl, g_aohl);
    cudaGetSymbolAddress(&p_wq, g_wqkvhl);
    cudaGetSymbolAddress(&p_wp, g_wprojhl);
    float* qkv = (float*)p_qkv;
    unsigned short* xhl = (unsigned short*)p_xhl;
    unsigned short* aohl = (unsigned short*)p_aohl;
    unsigned short* wqhl = (unsigned short*)p_wq;
    unsigned short* wphl = (unsigned short*)p_wp;

    cudaFuncSetAttribute(k_gemm, cudaFuncAttributeMaxDynamicSharedMemorySize, GSMEM_TOTAL);
    cudaFuncSetAttribute(k_s1, cudaFuncAttributeMaxDynamicSharedMemorySize,
                         S1_SMEM_FLOATS * (int)sizeof(float));
    cudaFuncSetAttribute(k_s2, cudaFuncAttributeMaxDynamicSharedMemorySize,
                         S2_SMEM_FLOATS * (int)sizeof(float));

    const int M = BB * NTOK;   // 50176

    // bf16 hi/lo conversions
    k_cvt<<<(M * 128 + 255) / 256, 256>>>(x, xhl, M * 128);
    k_cvt<<<(1536 * 128 + 255) / 256, 256>>>(w_qkv, wqhl, 1536 * 128);
    k_cvt<<<(512 * 128 + 255) / 256, 256>>>(w_proj, wphl, 512 * 128);

    // QKV GEMM: (50176,512)x(1536,512)^T -> (50176,1536) via HMMA bf16x3
    k_gemm<<<dim3(1536 / 128, M / 128), 256, GSMEM_TOTAL>>>(xhl, wqhl, 0, qkv, 1536);

    // bias tables (b-independent)
    k_pb<<<HEADS * AGENT, WW2>>>(an, ahb, awb);
    k_ab<<<(HEADS * 197 * AGENT + 255) / 256, 256>>>(na, hab, wab, cab);
    k_bias1<<<(HEADS * AGENT * NTOK + 255) / 256, 256>>>();
    k_bias2<<<(HEADS * NTOK * AGENT + 255) / 256, 256>>>();

    // agent pooling
    k_agent<<<BB * AGENT, DIM>>>();

    // stage 1: fused flash attention, split-KV + merge
    k_s1<<<dim3(S1SPLIT, HEADS, BB), 256, S1_SMEM_FLOATS * (int)sizeof(float)>>>();
    k_s1merge<<<BB * HEADS, 256>>>();

    // stage 2 (writes g_attnout)
    k_s2<<<dim3(25, HEADS, BB), 256, S2_SMEM_FLOATS * (int)sizeof(float)>>>();

    // depthwise conv residual, fused fp32->bf16 split (writes g_aohl)
    k_dwc<<<dim3(HH, BB), 256>>>(w_dwc, b_dwc);

    // projection GEMM with bias -> final fp32 output
    k_gemm<<<dim3(512 / 128, M / 128), 256, GSMEM_TOTAL>>>(aohl, wphl, b_proj, out, 512);
}